// round 3
// baseline (speedup 1.0000x reference)
#include <cuda_runtime.h>
#include <math.h>

// Problem dims
#define BB      8
#define SS      512
#define DDIM    1024
#define HDIM    4096
#define NHEADS  16
#define DHEAD   64
#define MROWS   (BB*SS)        // 4096
#define LN_EPS  1e-5f

// GEMM tiling
#define BM 128
#define BN 64
#define BK 16
#define TM 8
#define TN 4
#define NTHR 256

// ---------------- scratch (device globals; no allocation) ----------------
__device__ float2 g_Q [MROWS*DDIM];
__device__ float2 g_K [MROWS*DDIM];
__device__ float2 g_V [MROWS*DDIM];
__device__ float2 g_O [MROWS*DDIM];
__device__ float2 g_X2[MROWS*DDIM];
__device__ float2 g_Mp[MROWS*DDIM];
__device__ float2 g_Hm[MROWS*HDIM];
__device__ float2 g_Sc[(size_t)BB*NHEADS*SS*SS];

// ---------------- complex GEMM ----------------
// C[m,n] = sum_k A[m,k] * B'[k,n]   (complex product, no conjugate)
// TRANSB=true : B' = B^T with B stored [N,K] row-major (K contiguous)  -> X @ W^T
// TRANSB=false: B' = B   with B stored [K,N] row-major (N contiguous)  -> A @ V
// Batched via blockIdx.z: base offset = (z/zdiv)*s?1 + (z%zdiv)*s?2 for A,B,C.
template<bool TRANSB>
__global__ __launch_bounds__(NTHR)
void cgemm(const float2* __restrict__ A, int lda,
           const float2* __restrict__ B, int ldb,
           float2* __restrict__ C, int ldc,
           int Kdim,
           long sA1, long sA2, long sB1, long sB2, long sC1, long sC2, int zdiv,
           const float2* __restrict__ bias, float scale, int act)
{
    __shared__ float2 As[BK][BM + 2];
    __shared__ float2 Bs[BK][BN + 2];

    const int tid = threadIdx.x;
    const int tx  = tid & 15;   // n group (16 groups of TN=4)
    const int ty  = tid >> 4;   // m group (16 groups of TM=8)

    const int z = blockIdx.z;
    const long offA = (long)(z / zdiv) * sA1 + (long)(z % zdiv) * sA2;
    const long offB = (long)(z / zdiv) * sB1 + (long)(z % zdiv) * sB2;
    const long offC = (long)(z / zdiv) * sC1 + (long)(z % zdiv) * sC2;

    const float2* Ab = A + offA + (long)blockIdx.y * BM * lda;
    const float2* Bb;
    if (TRANSB) Bb = B + offB + (long)blockIdx.x * BN * ldb;
    else        Bb = B + offB + blockIdx.x * BN;

    float accr[TM][TN], acci[TM][TN];
    #pragma unroll
    for (int i = 0; i < TM; i++)
        #pragma unroll
        for (int j = 0; j < TN; j++) { accr[i][j] = 0.f; acci[i][j] = 0.f; }

    for (int k0 = 0; k0 < Kdim; k0 += BK) {
        // load A tile [BM x BK], store transposed As[k][m]
        #pragma unroll
        for (int t = 0; t < (BM*BK)/NTHR; t++) {
            int idx = tid + t*NTHR;
            int m = idx >> 4, k = idx & 15;
            As[k][m] = Ab[(long)m * lda + k0 + k];
        }
        if (TRANSB) {
            #pragma unroll
            for (int t = 0; t < (BN*BK)/NTHR; t++) {
                int idx = tid + t*NTHR;
                int n = idx >> 4, k = idx & 15;
                Bs[k][n] = Bb[(long)n * ldb + k0 + k];
            }
        } else {
            #pragma unroll
            for (int t = 0; t < (BN*BK)/NTHR; t++) {
                int idx = tid + t*NTHR;
                int k = idx / BN, n = idx % BN;
                Bs[k][n] = Bb[(long)(k0 + k) * ldb + n];
            }
        }
        __syncthreads();

        #pragma unroll
        for (int k = 0; k < BK; k++) {
            float2 a[TM], b[TN];
            #pragma unroll
            for (int i = 0; i < TM; i++) a[i] = As[k][ty*TM + i];
            #pragma unroll
            for (int j = 0; j < TN; j++) b[j] = Bs[k][tx*TN + j];
            #pragma unroll
            for (int i = 0; i < TM; i++)
                #pragma unroll
                for (int j = 0; j < TN; j++) {
                    accr[i][j] = fmaf(a[i].x,  b[j].x, accr[i][j]);
                    accr[i][j] = fmaf(-a[i].y, b[j].y, accr[i][j]);
                    acci[i][j] = fmaf(a[i].x,  b[j].y, acci[i][j]);
                    acci[i][j] = fmaf(a[i].y,  b[j].x, acci[i][j]);
                }
        }
        __syncthreads();
    }

    float2* Cb = C + offC + (long)blockIdx.y * BM * ldc + blockIdx.x * BN;
    #pragma unroll
    for (int i = 0; i < TM; i++) {
        int m = ty*TM + i;
        #pragma unroll
        for (int j = 0; j < TN; j++) {
            int n = tx*TN + j;
            float cr = accr[i][j] * scale;
            float ci = acci[i][j] * scale;
            if (bias) { float2 bb = bias[blockIdx.x*BN + n]; cr += bb.x; ci += bb.y; }
            if (act)  { float mag = sqrtf(cr*cr + ci*ci); cr = 0.5f*(cr + mag); ci = 0.5f*ci; }
            Cb[(long)m * ldc + n] = make_float2(cr, ci);
        }
    }
}

// ---------------- softmax over key axis, real & imag independently ----------------
// one warp per row of 512 complex scores
__global__ __launch_bounds__(256)
void softmax_kernel(float2* __restrict__ Sc)
{
    int row  = blockIdx.x * 8 + (threadIdx.x >> 5);
    int lane = threadIdx.x & 31;
    float2* r = Sc + (long)row * SS;

    float2 v[16];
    float mx = -1e30f, my = -1e30f;
    #pragma unroll
    for (int i = 0; i < 16; i++) {
        v[i] = r[lane + 32*i];
        mx = fmaxf(mx, v[i].x); my = fmaxf(my, v[i].y);
    }
    #pragma unroll
    for (int o = 16; o > 0; o >>= 1) {
        mx = fmaxf(mx, __shfl_xor_sync(0xffffffffu, mx, o));
        my = fmaxf(my, __shfl_xor_sync(0xffffffffu, my, o));
    }
    float sx = 0.f, sy = 0.f;
    #pragma unroll
    for (int i = 0; i < 16; i++) {
        v[i].x = __expf(v[i].x - mx);
        v[i].y = __expf(v[i].y - my);
        sx += v[i].x; sy += v[i].y;
    }
    #pragma unroll
    for (int o = 16; o > 0; o >>= 1) {
        sx += __shfl_xor_sync(0xffffffffu, sx, o);
        sy += __shfl_xor_sync(0xffffffffu, sy, o);
    }
    float ix = 1.f / sx, iy = 1.f / sy;
    #pragma unroll
    for (int i = 0; i < 16; i++)
        r[lane + 32*i] = make_float2(v[i].x * ix, v[i].y * iy);
}

// ---------------- block reduction of 4 values (256 threads) ----------------
__device__ __forceinline__
void reduce4(float& a, float& b, float& c, float& d, float* sh)
{
    #pragma unroll
    for (int o = 16; o > 0; o >>= 1) {
        a += __shfl_xor_sync(0xffffffffu, a, o);
        b += __shfl_xor_sync(0xffffffffu, b, o);
        c += __shfl_xor_sync(0xffffffffu, c, o);
        d += __shfl_xor_sync(0xffffffffu, d, o);
    }
    int w = threadIdx.x >> 5;
    __syncthreads();
    if ((threadIdx.x & 31) == 0) {
        sh[w] = a; sh[8+w] = b; sh[16+w] = c; sh[24+w] = d;
    }
    __syncthreads();
    float ra = 0.f, rb = 0.f, rc = 0.f, rd = 0.f;
    #pragma unroll
    for (int i = 0; i < 8; i++) { ra += sh[i]; rb += sh[8+i]; rc += sh[16+i]; rd += sh[24+i]; }
    a = ra; b = rb; c = rc; d = rd;
}

// ---------------- fused double layernorm after attention ----------------
// t = LN0(O + query); X2 = LN1(x + t). real & imag normalized independently.
__global__ __launch_bounds__(256)
void ln_attn_kernel(const float2* __restrict__ O, const float2* __restrict__ query,
                    const float2* __restrict__ x,
                    const float* __restrict__ ln_g, const float* __restrict__ ln_b,
                    float2* __restrict__ X2)
{
    __shared__ float sh[32];
    const long base = (long)blockIdx.x * DDIM;
    const float inv = 1.f / DDIM;

    float2 v[4];
    float sr = 0.f, sqr = 0.f, si = 0.f, sqi = 0.f;
    #pragma unroll
    for (int i = 0; i < 4; i++) {
        int d = threadIdx.x + i*256;
        float2 o = O[base + d], q = query[base + d];
        v[i] = make_float2(o.x + q.x, o.y + q.y);
        sr += v[i].x; sqr += v[i].x * v[i].x;
        si += v[i].y; sqi += v[i].y * v[i].y;
    }
    reduce4(sr, sqr, si, sqi, sh);
    float mr = sr*inv, mi = si*inv;
    float rr = rsqrtf(sqr*inv - mr*mr + LN_EPS);
    float ri = rsqrtf(sqi*inv - mi*mi + LN_EPS);

    float2 u[4];
    float s2r = 0.f, q2r = 0.f, s2i = 0.f, q2i = 0.f;
    #pragma unroll
    for (int i = 0; i < 4; i++) {
        int d = threadIdx.x + i*256;
        float tr = (v[i].x - mr)*rr * ln_g[d]          + ln_b[d];
        float ti = (v[i].y - mi)*ri * ln_g[DDIM + d]   + ln_b[DDIM + d];
        float2 xx = x[base + d];
        u[i] = make_float2(xx.x + tr, xx.y + ti);
        s2r += u[i].x; q2r += u[i].x * u[i].x;
        s2i += u[i].y; q2i += u[i].y * u[i].y;
    }
    reduce4(s2r, q2r, s2i, q2i, sh);
    float m2r = s2r*inv, m2i = s2i*inv;
    float r2r = rsqrtf(q2r*inv - m2r*m2r + LN_EPS);
    float r2i = rsqrtf(q2i*inv - m2i*m2i + LN_EPS);

    const float* g1 = ln_g + 2*DDIM;   // stage 1
    const float* b1 = ln_b + 2*DDIM;
    #pragma unroll
    for (int i = 0; i < 4; i++) {
        int d = threadIdx.x + i*256;
        float yr = (u[i].x - m2r)*r2r * g1[d]        + b1[d];
        float yi = (u[i].y - m2i)*r2i * g1[DDIM + d] + b1[DDIM + d];
        X2[base + d] = make_float2(yr, yi);
    }
}

// ---------------- final layernorm: out = LN2(X2 + Mp) ----------------
__global__ __launch_bounds__(256)
void ln_final_kernel(const float2* __restrict__ X2, const float2* __restrict__ Mp,
                     const float* __restrict__ ln_g, const float* __restrict__ ln_b,
                     float2* __restrict__ out)
{
    __shared__ float sh[32];
    const long base = (long)blockIdx.x * DDIM;
    const float inv = 1.f / DDIM;

    float2 v[4];
    float sr = 0.f, sqr = 0.f, si = 0.f, sqi = 0.f;
    #pragma unroll
    for (int i = 0; i < 4; i++) {
        int d = threadIdx.x + i*256;
        float2 a = X2[base + d], m = Mp[base + d];
        v[i] = make_float2(a.x + m.x, a.y + m.y);
        sr += v[i].x; sqr += v[i].x * v[i].x;
        si += v[i].y; sqi += v[i].y * v[i].y;
    }
    reduce4(sr, sqr, si, sqi, sh);
    float mr = sr*inv, mi = si*inv;
    float rr = rsqrtf(sqr*inv - mr*mr + LN_EPS);
    float ri = rsqrtf(sqi*inv - mi*mi + LN_EPS);

    const float* g2 = ln_g + 4*DDIM;   // stage 2
    const float* b2 = ln_b + 4*DDIM;
    #pragma unroll
    for (int i = 0; i < 4; i++) {
        int d = threadIdx.x + i*256;
        float yr = (v[i].x - mr)*rr * g2[d]        + b2[d];
        float yi = (v[i].y - mi)*ri * g2[DDIM + d] + b2[DDIM + d];
        out[base + d] = make_float2(yr, yi);
    }
}

// ---------------- host launch ----------------
extern "C" void kernel_launch(void* const* d_in, const int* in_sizes, int n_in,
                              void* d_out, int out_size)
{
    const float2* x     = (const float2*)d_in[0];
    const float2* query = (const float2*)d_in[1];
    const float2* wq    = (const float2*)d_in[2];
    const float2* bq    = (const float2*)d_in[3];
    const float2* wk    = (const float2*)d_in[4];
    const float2* bk    = (const float2*)d_in[5];
    const float2* wv    = (const float2*)d_in[6];
    const float2* bv    = (const float2*)d_in[7];
    const float2* wfc   = (const float2*)d_in[8];
    const float2* bfc   = (const float2*)d_in[9];
    const float2* wpr   = (const float2*)d_in[10];
    const float2* bpr   = (const float2*)d_in[11];
    const float*  lng   = (const float*)d_in[12];
    const float*  lnb   = (const float*)d_in[13];

    float2 *Q, *K, *V, *O, *X2, *Mp, *Hm, *Sc;
    cudaGetSymbolAddress((void**)&Q,  g_Q);
    cudaGetSymbolAddress((void**)&K,  g_K);
    cudaGetSymbolAddress((void**)&V,  g_V);
    cudaGetSymbolAddress((void**)&O,  g_O);
    cudaGetSymbolAddress((void**)&X2, g_X2);
    cudaGetSymbolAddress((void**)&Mp, g_Mp);
    cudaGetSymbolAddress((void**)&Hm, g_Hm);
    cudaGetSymbolAddress((void**)&Sc, g_Sc);

    const dim3 blk(NTHR);
    const float rscale = 0.125f;  // 1/sqrt(64)

    // QKV projections: [4096 x 1024] = in @ W^T + b
    {
        dim3 grd(DDIM/BN, MROWS/BM, 1);
        cgemm<true><<<grd, blk>>>(query, DDIM, wq, DDIM, Q, DDIM, DDIM,
                                  0,0,0,0,0,0, 1, bq, 1.f, 0);
        cgemm<true><<<grd, blk>>>(x,     DDIM, wk, DDIM, K, DDIM, DDIM,
                                  0,0,0,0,0,0, 1, bk, 1.f, 0);
        cgemm<true><<<grd, blk>>>(x,     DDIM, wv, DDIM, V, DDIM, DDIM,
                                  0,0,0,0,0,0, 1, bv, 1.f, 0);
    }

    // Scores: S[z, q, k] = scale * Q_z @ K_z^T   (z = b*NH + h)
    {
        dim3 grd(SS/BN, SS/BM, BB*NHEADS);
        cgemm<true><<<grd, blk>>>(Q, DDIM, K, DDIM, Sc, SS, DHEAD,
                                  (long)SS*DDIM, DHEAD,
                                  (long)SS*DDIM, DHEAD,
                                  (long)NHEADS*SS*SS, (long)SS*SS,
                                  NHEADS, (const float2*)nullptr, rscale, 0);
    }

    // Softmax over keys (real & imag independently)
    softmax_kernel<<<(BB*NHEADS*SS)/8, 256>>>(Sc);

    // O = A @ V   (NN form)
    {
        dim3 grd(DHEAD/BN, SS/BM, BB*NHEADS);
        cgemm<false><<<grd, blk>>>(Sc, SS, V, DDIM, O, DDIM, SS,
                                   (long)NHEADS*SS*SS, (long)SS*SS,
                                   (long)SS*DDIM, DHEAD,
                                   (long)SS*DDIM, DHEAD,
                                   NHEADS, (const float2*)nullptr, 1.f, 0);
    }

    // X2 = LN1(x + LN0(O + query))
    ln_attn_kernel<<<MROWS, 256>>>(O, query, x, lng, lnb, X2);

    // fc: Hm = modReLU( X2 @ Wfc^T + bfc )   [4096 x 4096]
    {
        dim3 grd(HDIM/BN, MROWS/BM, 1);
        cgemm<true><<<grd, blk>>>(X2, DDIM, wfc, DDIM, Hm, HDIM, DDIM,
                                  0,0,0,0,0,0, 1, bfc, 1.f, 1);
    }

    // proj: Mp = Hm @ Wproj^T + bproj   [4096 x 1024], K = 4096
    {
        dim3 grd(DDIM/BN, MROWS/BM, 1);
        cgemm<true><<<grd, blk>>>(Hm, HDIM, wpr, HDIM, Mp, DDIM, HDIM,
                                  0,0,0,0,0,0, 1, bpr, 1.f, 0);
    }

    // out = LN2(X2 + Mp)
    ln_final_kernel<<<MROWS, 256>>>(X2, Mp, lng, lnb, (float2*)d_out);
}

// round 5
// speedup vs baseline: 2.2396x; 2.2396x over previous
#include <cuda_runtime.h>
#include <cuda_bf16.h>
#include <cstdint>
#include <math.h>

typedef __nv_bfloat16 bf16;
typedef __nv_bfloat162 bf162;

#define DD 1024
#define MR 4096
#define LN_EPS 1e-5f

// ---------------- scratch (device globals; no allocation) ----------------
__device__ __align__(256) bf16 g_Qe [(size_t)MR*6144];
__device__ __align__(256) bf16 g_Xe [(size_t)MR*6144];
__device__ __align__(256) bf16 g_X2e[(size_t)MR*6144];
__device__ __align__(256) bf16 g_Hme[(size_t)MR*24576];
__device__ __align__(256) bf16 g_Wqe[(size_t)2048*6144];
__device__ __align__(256) bf16 g_Wke[(size_t)2048*6144];
__device__ __align__(256) bf16 g_Wve[(size_t)2048*6144];
__device__ __align__(256) bf16 g_Wfe[(size_t)8192*6144];
__device__ __align__(256) bf16 g_Wpe[(size_t)2048*24576];
__device__ __align__(256) bf16 g_Qa [(size_t)128*512*384];
__device__ __align__(256) bf16 g_Kb [(size_t)128*1024*384];
__device__ __align__(256) bf16 g_Vb [(size_t)128*128*3072];
__device__ __align__(256) bf16 g_Pa [(size_t)128*512*3072];
__device__ float2 g_Q [(size_t)MR*DD];
__device__ float2 g_K [(size_t)MR*DD];
__device__ float2 g_V [(size_t)MR*DD];
__device__ float2 g_O [(size_t)MR*DD];
__device__ float2 g_X2[(size_t)MR*DD];
__device__ float2 g_Mp[(size_t)MR*DD];
__device__ float2 g_Hm[(size_t)MR*4096];
__device__ float2 g_Sc[(size_t)128*512*512];

// ---------------- helpers ----------------
__device__ __forceinline__ uint32_t s2u(const void* p){
    uint32_t a;
    asm("{ .reg .u64 t; cvta.to.shared.u64 t, %1; cvt.u32.u64 %0, t; }":"=r"(a):"l"(p));
    return a;
}
__device__ __forceinline__ void cpa16(uint32_t d, const void* g){
    asm volatile("cp.async.cg.shared.global [%0], [%1], 16;"::"r"(d),"l"(g));
}
__device__ __forceinline__ void split2(float vr, float vi, bf162& h, bf162& l){
    bf16 hr=__float2bfloat16_rn(vr), hi=__float2bfloat16_rn(vi);
    h.x=hr; h.y=hi;
    l.x=__float2bfloat16_rn(vr-__bfloat162float(hr));
    l.y=__float2bfloat16_rn(vi-__bfloat162float(hi));
}
__device__ __forceinline__ void ldm4(uint32_t* r, uint32_t a){
    asm volatile("ldmatrix.sync.aligned.m8n8.x4.shared.b16 {%0,%1,%2,%3}, [%4];"
        :"=r"(r[0]),"=r"(r[1]),"=r"(r[2]),"=r"(r[3]):"r"(a));
}
__device__ __forceinline__ void mma16816(float* d, const uint32_t* a, uint32_t b0, uint32_t b1){
    asm volatile("mma.sync.aligned.m16n8k16.row.col.f32.bf16.bf16.f32 "
        "{%0,%1,%2,%3}, {%4,%5,%6,%7}, {%8,%9}, {%0,%1,%2,%3};"
        :"+f"(d[0]),"+f"(d[1]),"+f"(d[2]),"+f"(d[3])
        :"r"(a[0]),"r"(a[1]),"r"(a[2]),"r"(a[3]),"r"(b0),"r"(b1));
}

// ---------------- GEMM via mma.sync (base-ISA tensor cores) ----------------
// C[m,n'] = sum_k A[m,k]*B[n',k]; BM=128, BN=128, BK=64; 8 warps (4M x 2N)
struct GP {
    const bf16 *A, *B; long lda, ldb;
    long sA1, sA2, sB1, sB2;
    float2* C; long ldc, sC1, sC2;
    int zdiv, kC;
    const float2* bias; float scale; int act;
};
#define ROWB 144            // 64 bf16 = 128B data + 16B pad
#define ASZ  (128*ROWB)     // 18432
#define STB  (2*ASZ)        // A + B per stage

__global__ __launch_bounds__(256,1) void tgemm(GP p)
{
    extern __shared__ __align__(256) char sm[];
    uint32_t TILE = s2u(sm);
    const int tid = threadIdx.x, lane = tid & 31, wid = tid >> 5;
    const int warpM = wid & 3, warpN = wid >> 2;

    const int z = blockIdx.z;
    const bf16* Ag = p.A + (z/p.zdiv)*p.sA1 + (z%p.zdiv)*p.sA2 + (long)blockIdx.y*128*p.lda;
    const bf16* Bg = p.B + (z/p.zdiv)*p.sB1 + (z%p.zdiv)*p.sB2 + (long)blockIdx.x*128*p.ldb;

    auto loadStage = [&](int c){
        uint32_t st = TILE + (c%3)*STB;
        long kof = (long)c*64;
        #pragma unroll
        for (int i=0;i<4;i++){
            int idx = tid + i*256; int r = idx>>3, cc = idx&7;
            cpa16(st + r*ROWB + cc*16, Ag + (long)r*p.lda + kof + cc*8);
        }
        #pragma unroll
        for (int i=0;i<4;i++){
            int idx = tid + i*256; int r = idx>>3, cc = idx&7;
            cpa16(st + ASZ + r*ROWB + cc*16, Bg + (long)r*p.ldb + kof + cc*8);
        }
        asm volatile("cp.async.commit_group;":::"memory");
    };

    float acc[2][8][4];
    #pragma unroll
    for (int mf=0;mf<2;mf++)
        #pragma unroll
        for (int nf=0;nf<8;nf++)
            #pragma unroll
            for (int t=0;t<4;t++) acc[mf][nf][t] = 0.f;

    loadStage(0);
    if (p.kC > 1) loadStage(1);

    // per-lane ldmatrix base addresses (within a stage slot)
    const uint32_t aRel = (uint32_t)((warpM*32 + (lane&15))*ROWB + (lane>>4)*16);
    const uint32_t bRel = (uint32_t)(ASZ + (warpN*64 + (lane&7))*ROWB + ((lane>>3)&3)*16);

    for (int c = 0; c < p.kC; c++) {
        if (c+1 < p.kC) asm volatile("cp.async.wait_group 1;":::"memory");
        else            asm volatile("cp.async.wait_group 0;":::"memory");
        __syncthreads();
        if (c+2 < p.kC) loadStage(c+2);

        uint32_t st = TILE + (c%3)*STB;
        uint32_t aB = st + aRel, bB = st + bRel;
        #pragma unroll
        for (int kh=0; kh<2; kh++){
            uint32_t bf[8][4];
            #pragma unroll
            for (int nf=0; nf<8; nf++) ldm4(bf[nf], bB + nf*(8*ROWB) + kh*64);
            #pragma unroll
            for (int s=0; s<2; s++){
                int ks = kh*2 + s;
                uint32_t af[2][4];
                #pragma unroll
                for (int mf=0; mf<2; mf++) ldm4(af[mf], aB + mf*(16*ROWB) + ks*32);
                #pragma unroll
                for (int mf=0; mf<2; mf++)
                    #pragma unroll
                    for (int nf=0; nf<8; nf++)
                        mma16816(acc[mf][nf], af[mf], bf[nf][s*2], bf[nf][s*2+1]);
            }
        }
        __syncthreads();
    }

    // epilogue: d0,d1 = (cr,ci) at row r, d2,d3 at row r+8 (complex pair = adjacent cols)
    const long coff = (z/p.zdiv)*p.sC1 + (z%p.zdiv)*p.sC2;
    const int ncBase = blockIdx.x*64 + warpN*32 + (lane&3);
    #pragma unroll
    for (int mf=0; mf<2; mf++){
        long r0 = (long)blockIdx.y*128 + warpM*32 + mf*16 + (lane>>2);
        #pragma unroll
        for (int nf=0; nf<8; nf++){
            int nc = ncBase + nf*4;
            float2 bb = p.bias ? p.bias[nc] : make_float2(0.f,0.f);
            #pragma unroll
            for (int h=0; h<2; h++){
                float cr = acc[mf][nf][2*h]   * p.scale + bb.x;
                float ci = acc[mf][nf][2*h+1] * p.scale + bb.y;
                if (p.act){ float mg = sqrtf(cr*cr+ci*ci); cr = 0.5f*(cr+mg); ci = 0.5f*ci; }
                p.C[coff + (r0 + h*8)*p.ldc + nc] = make_float2(cr, ci);
            }
        }
    }
}

// ---------------- expansions ----------------
__global__ __launch_bounds__(256) void expandW(const float2* __restrict__ W, bf16* __restrict__ out, int K)
{
    long idx = (long)blockIdx.x*256 + threadIdx.x;
    long n = idx / K; int k = (int)(idx % K);
    float2 w = W[idx];
    bf162 h0,l0,h1,l1;
    split2(w.x, -w.y, h0, l0);
    split2(w.y,  w.x, h1, l1);
    long K2 = 2L*K;
    bf16* r0 = out + (2*n)*(3*K2) + 2*k;
    bf16* r1 = r0 + 3*K2;
    *(bf162*)(r0)=h0; *(bf162*)(r0+K2)=h0; *(bf162*)(r0+2*K2)=l0;
    *(bf162*)(r1)=h1; *(bf162*)(r1+K2)=h1; *(bf162*)(r1+2*K2)=l1;
}
__global__ __launch_bounds__(256) void expandA(const float2* __restrict__ X, bf16* __restrict__ out, int K)
{
    long idx = (long)blockIdx.x*256 + threadIdx.x;
    long m = idx / K; int k = (int)(idx % K);
    float2 v = X[idx];
    bf162 h,l; split2(v.x, v.y, h, l);
    long K2 = 2L*K;
    bf16* b = out + m*(3*K2) + 2*k;
    *(bf162*)(b)=h; *(bf162*)(b+K2)=l; *(bf162*)(b+2*K2)=h;
}
__global__ __launch_bounds__(256) void expandQh(const float2* __restrict__ Q, bf16* __restrict__ out)
{
    long idx = (long)blockIdx.x*256 + threadIdx.x;
    long m = idx >> 10; int n = (int)(idx & 1023);
    int b = (int)(m>>9), s = (int)(m&511), h = n>>6, d = n&63;
    float2 v = Q[idx];
    bf162 hh,ll; split2(v.x, v.y, hh, ll);
    bf16* base = out + ((long)(b*16+h)*512 + s)*384 + 2*d;
    *(bf162*)(base)=hh; *(bf162*)(base+128)=ll; *(bf162*)(base+256)=hh;
}
__global__ __launch_bounds__(256) void expandKV(const float2* __restrict__ K, const float2* __restrict__ V,
                                                bf16* __restrict__ Kb, bf16* __restrict__ Vb)
{
    long idx = (long)blockIdx.x*256 + threadIdx.x;
    long m = idx >> 10; int n = (int)(idx & 1023);
    int b = (int)(m>>9), s = (int)(m&511), h = n>>6, d = n&63;
    long z = b*16 + h;
    {
        float2 v = K[idx];
        bf162 h0,l0,h1,l1; split2(v.x,-v.y,h0,l0); split2(v.y,v.x,h1,l1);
        bf16* r0 = Kb + (z*1024 + 2*s)*384 + 2*d;
        bf16* r1 = r0 + 384;
        *(bf162*)(r0)=h0; *(bf162*)(r0+128)=h0; *(bf162*)(r0+256)=l0;
        *(bf162*)(r1)=h1; *(bf162*)(r1+128)=h1; *(bf162*)(r1+256)=l1;
    }
    {
        float2 v = V[idx];
        bf162 h0,l0,h1,l1; split2(v.x,-v.y,h0,l0); split2(v.y,v.x,h1,l1);
        bf16* r0 = Vb + (z*128 + 2*d)*3072 + 2*s;
        bf16* r1 = r0 + 3072;
        *(bf162*)(r0)=h0; *(bf162*)(r0+1024)=h0; *(bf162*)(r0+2048)=l0;
        *(bf162*)(r1)=h1; *(bf162*)(r1+1024)=h1; *(bf162*)(r1+2048)=l1;
    }
}

// ---------------- softmax + probs expansion ----------------
__global__ __launch_bounds__(256) void softmax_kernel(const float2* __restrict__ Sc, bf16* __restrict__ Pa)
{
    long rid = (long)blockIdx.x*8 + (threadIdx.x>>5);
    int lane = threadIdx.x & 31;
    const float2* r = Sc + rid*512;
    float2 v[16]; float mx=-1e30f, my=-1e30f;
    #pragma unroll
    for (int i=0;i<16;i++){ v[i]=r[lane+32*i]; mx=fmaxf(mx,v[i].x); my=fmaxf(my,v[i].y); }
    #pragma unroll
    for (int o=16;o>0;o>>=1){ mx=fmaxf(mx,__shfl_xor_sync(~0u,mx,o)); my=fmaxf(my,__shfl_xor_sync(~0u,my,o)); }
    float sx=0.f, sy=0.f;
    #pragma unroll
    for (int i=0;i<16;i++){ v[i].x=__expf(v[i].x-mx); v[i].y=__expf(v[i].y-my); sx+=v[i].x; sy+=v[i].y; }
    #pragma unroll
    for (int o=16;o>0;o>>=1){ sx+=__shfl_xor_sync(~0u,sx,o); sy+=__shfl_xor_sync(~0u,sy,o); }
    float ix=1.f/sx, iy=1.f/sy;
    bf16* base = Pa + rid*3072;
    #pragma unroll
    for (int i=0;i<16;i++){
        int k = lane + 32*i;
        bf162 h,l; split2(v[i].x*ix, v[i].y*iy, h, l);
        *(bf162*)(base+2*k)=h; *(bf162*)(base+1024+2*k)=l; *(bf162*)(base+2048+2*k)=h;
    }
}

// ---------------- layernorms ----------------
__device__ __forceinline__ void reduce4(float& a, float& b, float& c, float& d, float* sh)
{
    #pragma unroll
    for (int o=16;o>0;o>>=1){
        a+=__shfl_xor_sync(~0u,a,o); b+=__shfl_xor_sync(~0u,b,o);
        c+=__shfl_xor_sync(~0u,c,o); d+=__shfl_xor_sync(~0u,d,o);
    }
    int w = threadIdx.x>>5;
    __syncthreads();
    if ((threadIdx.x&31)==0){ sh[w]=a; sh[8+w]=b; sh[16+w]=c; sh[24+w]=d; }
    __syncthreads();
    float ra=0,rb=0,rc=0,rd=0;
    #pragma unroll
    for (int i=0;i<8;i++){ ra+=sh[i]; rb+=sh[8+i]; rc+=sh[16+i]; rd+=sh[24+i]; }
    a=ra; b=rb; c=rc; d=rd;
}

__global__ __launch_bounds__(256)
void ln_attn_kernel(const float2* __restrict__ O, const float2* __restrict__ query,
                    const float2* __restrict__ x,
                    const float* __restrict__ g, const float* __restrict__ bta,
                    float2* __restrict__ X2)
{
    __shared__ float sh[32];
    const long base = (long)blockIdx.x*DD;
    const float inv = 1.f/DD;
    float2 v[4]; float sr=0,sq=0,si=0,qi=0;
    #pragma unroll
    for (int i=0;i<4;i++){
        int d = threadIdx.x + i*256;
        float2 o=O[base+d], q=query[base+d];
        v[i]=make_float2(o.x+q.x, o.y+q.y);
        sr+=v[i].x; sq+=v[i].x*v[i].x; si+=v[i].y; qi+=v[i].y*v[i].y;
    }
    reduce4(sr,sq,si,qi,sh);
    float mr=sr*inv, mi=si*inv;
    float rr=rsqrtf(sq*inv-mr*mr+LN_EPS), ri=rsqrtf(qi*inv-mi*mi+LN_EPS);
    float2 u[4]; float s2=0,q2=0,s3=0,q3=0;
    #pragma unroll
    for (int i=0;i<4;i++){
        int d = threadIdx.x + i*256;
        float tr=(v[i].x-mr)*rr*g[d]+bta[d];
        float ti=(v[i].y-mi)*ri*g[DD+d]+bta[DD+d];
        float2 xx=x[base+d];
        u[i]=make_float2(xx.x+tr, xx.y+ti);
        s2+=u[i].x; q2+=u[i].x*u[i].x; s3+=u[i].y; q3+=u[i].y*u[i].y;
    }
    reduce4(s2,q2,s3,q3,sh);
    float m2=s2*inv, m3=s3*inv;
    float r2=rsqrtf(q2*inv-m2*m2+LN_EPS), r3=rsqrtf(q3*inv-m3*m3+LN_EPS);
    const float *g1=g+2*DD, *b1=bta+2*DD;
    #pragma unroll
    for (int i=0;i<4;i++){
        int d = threadIdx.x + i*256;
        X2[base+d]=make_float2((u[i].x-m2)*r2*g1[d]+b1[d], (u[i].y-m3)*r3*g1[DD+d]+b1[DD+d]);
    }
}

__global__ __launch_bounds__(256)
void ln_final_kernel(const float2* __restrict__ X2, const float2* __restrict__ Mp,
                     const float* __restrict__ g, const float* __restrict__ bta,
                     float2* __restrict__ out)
{
    __shared__ float sh[32];
    const long base = (long)blockIdx.x*DD;
    const float inv = 1.f/DD;
    float2 v[4]; float sr=0,sq=0,si=0,qi=0;
    #pragma unroll
    for (int i=0;i<4;i++){
        int d = threadIdx.x + i*256;
        float2 a=X2[base+d], m=Mp[base+d];
        v[i]=make_float2(a.x+m.x, a.y+m.y);
        sr+=v[i].x; sq+=v[i].x*v[i].x; si+=v[i].y; qi+=v[i].y*v[i].y;
    }
    reduce4(sr,sq,si,qi,sh);
    float mr=sr*inv, mi=si*inv;
    float rr=rsqrtf(sq*inv-mr*mr+LN_EPS), ri=rsqrtf(qi*inv-mi*mi+LN_EPS);
    const float *g2=g+4*DD, *b2=bta+4*DD;
    #pragma unroll
    for (int i=0;i<4;i++){
        int d = threadIdx.x + i*256;
        out[base+d]=make_float2((v[i].x-mr)*rr*g2[d]+b2[d], (v[i].y-mi)*ri*g2[DD+d]+b2[DD+d]);
    }
}

// ---------------- host ----------------
static GP mkgp(const bf16* A, long lda, const bf16* B, long ldb,
               float2* C, long ldc, int kC,
               const float2* bias, float scale, int act,
               int zdiv=1, long sA1=0,long sA2=0,long sB1=0,long sB2=0,long sC1=0,long sC2=0)
{
    GP p; p.A=A; p.B=B; p.lda=lda; p.ldb=ldb; p.C=C; p.ldc=ldc; p.kC=kC;
    p.bias=bias; p.scale=scale; p.act=act; p.zdiv=zdiv;
    p.sA1=sA1; p.sA2=sA2; p.sB1=sB1; p.sB2=sB2; p.sC1=sC1; p.sC2=sC2;
    return p;
}

extern "C" void kernel_launch(void* const* d_in, const int* in_sizes, int n_in,
                              void* d_out, int out_size)
{
    const float2* x     = (const float2*)d_in[0];
    const float2* query = (const float2*)d_in[1];
    const float2* wq    = (const float2*)d_in[2];
    const float2* bq    = (const float2*)d_in[3];
    const float2* wk    = (const float2*)d_in[4];
    const float2* bk    = (const float2*)d_in[5];
    const float2* wv    = (const float2*)d_in[6];
    const float2* bv    = (const float2*)d_in[7];
    const float2* wfc   = (const float2*)d_in[8];
    const float2* bfc   = (const float2*)d_in[9];
    const float2* wpr   = (const float2*)d_in[10];
    const float2* bpr   = (const float2*)d_in[11];
    const float*  lng   = (const float*)d_in[12];
    const float*  lnb   = (const float*)d_in[13];

    bf16 *Qe,*Xe,*X2e,*Hme,*Wqe,*Wke,*Wve,*Wfe,*Wpe,*Qa,*Kb,*Vb,*Pa;
    float2 *Q,*K,*V,*O,*X2,*Mp,*Hm,*Sc;
    cudaGetSymbolAddress((void**)&Qe,g_Qe);   cudaGetSymbolAddress((void**)&Xe,g_Xe);
    cudaGetSymbolAddress((void**)&X2e,g_X2e); cudaGetSymbolAddress((void**)&Hme,g_Hme);
    cudaGetSymbolAddress((void**)&Wqe,g_Wqe); cudaGetSymbolAddress((void**)&Wke,g_Wke);
    cudaGetSymbolAddress((void**)&Wve,g_Wve); cudaGetSymbolAddress((void**)&Wfe,g_Wfe);
    cudaGetSymbolAddress((void**)&Wpe,g_Wpe); cudaGetSymbolAddress((void**)&Qa,g_Qa);
    cudaGetSymbolAddress((void**)&Kb,g_Kb);   cudaGetSymbolAddress((void**)&Vb,g_Vb);
    cudaGetSymbolAddress((void**)&Pa,g_Pa);
    cudaGetSymbolAddress((void**)&Q,g_Q);   cudaGetSymbolAddress((void**)&K,g_K);
    cudaGetSymbolAddress((void**)&V,g_V);   cudaGetSymbolAddress((void**)&O,g_O);
    cudaGetSymbolAddress((void**)&X2,g_X2); cudaGetSymbolAddress((void**)&Mp,g_Mp);
    cudaGetSymbolAddress((void**)&Hm,g_Hm); cudaGetSymbolAddress((void**)&Sc,g_Sc);

    const int SMB = 3*STB;   // 110592
    cudaFuncSetAttribute(tgemm, cudaFuncAttributeMaxDynamicSharedMemorySize, SMB);

    // expansions of inputs/weights
    expandA<<<MR*DD/256,256>>>(query, Qe, DD);
    expandA<<<MR*DD/256,256>>>(x,     Xe, DD);
    expandW<<<1024*1024/256,256>>>(wq, Wqe, DD);
    expandW<<<1024*1024/256,256>>>(wk, Wke, DD);
    expandW<<<1024*1024/256,256>>>(wv, Wve, DD);
    expandW<<<4096*1024/256,256>>>(wfc, Wfe, DD);
    expandW<<<1024*4096/256,256>>>(wpr, Wpe, 4096);

    // QKV projections: [4096 x 2048'], K_eff=6144 (kC=96)
    {
        dim3 grd(16, 32, 1);
        tgemm<<<grd,256,SMB>>>(mkgp(Qe,6144, Wqe,6144, Q,1024, 96, bq,1.f,0));
        tgemm<<<grd,256,SMB>>>(mkgp(Xe,6144, Wke,6144, K,1024, 96, bk,1.f,0));
        tgemm<<<grd,256,SMB>>>(mkgp(Xe,6144, Wve,6144, V,1024, 96, bv,1.f,0));
    }
    expandQh<<<MR*DD/256,256>>>(Q, Qa);
    expandKV<<<MR*DD/256,256>>>(K, V, Kb, Vb);

    // scores: per z=(b,h): [512 x 1024'], K_eff=384 (kC=6)
    {
        dim3 grd(8, 4, 128);
        tgemm<<<grd,256,SMB>>>(mkgp(Qa,384, Kb,384, Sc,512, 6, nullptr,0.125f,0,
            1, 512L*384,0, 1024L*384,0, 512L*512,0));
    }
    softmax_kernel<<<128*512/8,256>>>(Sc, Pa);

    // AV: per z: [512 x 128'], K_eff=3072 (kC=48)
    {
        dim3 grd(1, 4, 128);
        tgemm<<<grd,256,SMB>>>(mkgp(Pa,3072, Vb,3072, O,1024, 48, nullptr,1.f,0,
            16, 16L*512*3072, 512L*3072, 16L*128*3072, 128L*3072, 512L*1024, 64));
    }
    ln_attn_kernel<<<MR,256>>>(O, query, x, lng, lnb, X2);
    expandA<<<MR*DD/256,256>>>(X2, X2e, DD);

    // fc: [4096 x 8192'], K_eff=6144 (kC=96), bias+modReLU
    tgemm<<<dim3(64,32,1),256,SMB>>>(mkgp(X2e,6144, Wfe,6144, Hm,4096, 96, bfc,1.f,1));
    expandA<<<MR*4096/256,256>>>(Hm, Hme, 4096);

    // proj: [4096 x 2048'], K_eff=24576 (kC=384)
    tgemm<<<dim3(16,32,1),256,SMB>>>(mkgp(Hme,24576, Wpe,24576, Mp,1024, 384, bpr,1.f,0));

    ln_final_kernel<<<MR,256>>>(X2, Mp, lng, lnb, (float2*)d_out);
}

// round 6
// speedup vs baseline: 2.3077x; 1.0304x over previous
#include <cuda_runtime.h>
#include <cuda_bf16.h>
#include <cstdint>
#include <math.h>

typedef __nv_bfloat16 bf16;
typedef __nv_bfloat162 bf162;

#define DD 1024
#define MR 4096
#define LN_EPS 1e-5f

// ---------------- scratch (device globals; no allocation) ----------------
__device__ __align__(256) bf16 g_Qe [(size_t)MR*6144];
__device__ __align__(256) bf16 g_Xe [(size_t)MR*6144];
__device__ __align__(256) bf16 g_X2e[(size_t)MR*6144];
__device__ __align__(256) bf16 g_Hme[(size_t)MR*24576];
__device__ __align__(256) bf16 g_Wqe[(size_t)2048*6144];
__device__ __align__(256) bf16 g_Wke[(size_t)2048*6144];
__device__ __align__(256) bf16 g_Wve[(size_t)2048*6144];
__device__ __align__(256) bf16 g_Wfe[(size_t)8192*6144];
__device__ __align__(256) bf16 g_Wpe[(size_t)2048*24576];
__device__ __align__(256) bf16 g_Qa [(size_t)128*512*384];
__device__ __align__(256) bf16 g_Kb [(size_t)128*1024*384];
__device__ __align__(256) bf16 g_Vb [(size_t)128*128*3072];
__device__ __align__(256) bf16 g_Pa [(size_t)128*512*3072];
__device__ float2 g_O [(size_t)MR*DD];
__device__ float2 g_X2[(size_t)MR*DD];
__device__ float2 g_Mp[(size_t)MR*DD];
__device__ float2 g_Sc[(size_t)128*512*512];

// ---------------- helpers ----------------
__device__ __forceinline__ uint32_t s2u(const void* p){
    uint32_t a;
    asm("{ .reg .u64 t; cvta.to.shared.u64 t, %1; cvt.u32.u64 %0, t; }":"=r"(a):"l"(p));
    return a;
}
__device__ __forceinline__ void cpa16(uint32_t d, const void* g){
    asm volatile("cp.async.cg.shared.global [%0], [%1], 16;"::"r"(d),"l"(g));
}
__device__ __forceinline__ void split2(float vr, float vi, bf162& h, bf162& l){
    bf16 hr=__float2bfloat16_rn(vr), hi=__float2bfloat16_rn(vi);
    h.x=hr; h.y=hi;
    l.x=__float2bfloat16_rn(vr-__bfloat162float(hr));
    l.y=__float2bfloat16_rn(vi-__bfloat162float(hi));
}
__device__ __forceinline__ void ldm4(uint32_t* r, uint32_t a){
    asm volatile("ldmatrix.sync.aligned.m8n8.x4.shared.b16 {%0,%1,%2,%3}, [%4];"
        :"=r"(r[0]),"=r"(r[1]),"=r"(r[2]),"=r"(r[3]):"r"(a));
}
__device__ __forceinline__ void mma16816(float* d, const uint32_t* a, uint32_t b0, uint32_t b1){
    asm volatile("mma.sync.aligned.m16n8k16.row.col.f32.bf16.bf16.f32 "
        "{%0,%1,%2,%3}, {%4,%5,%6,%7}, {%8,%9}, {%0,%1,%2,%3};"
        :"+f"(d[0]),"+f"(d[1]),"+f"(d[2]),"+f"(d[3])
        :"r"(a[0]),"r"(a[1]),"r"(a[2]),"r"(a[3]),"r"(b0),"r"(b1));
}

// ---------------- GEMM via mma.sync ----------------
// BM=128, BN=128, BK=128; 8 warps (4M x 2N); 3-stage cp.async; 1 sync/chunk.
// epilogue modes: 0=float2 C; 1=Qa split-A per-head; 2=Kb split-B; 3=Vb split-B; 4=Hme split-A
struct GP {
    const bf16 *A, *B; long lda, ldb;
    long sA1, sA2, sB1, sB2;
    float2* C; long ldc, sC1, sC2;
    bf16* Ob;
    int zdiv, kC, mode, act;
    const float2* bias; float scale;
};
#define ROWB 272            // 128 bf16 = 256B data + 16B pad
#define ASZ  (128*ROWB)     // 34816
#define STB  (2*ASZ)        // 69632
#define SMB  (3*STB)        // 208896

__global__ __launch_bounds__(256,1) void tgemm(GP p)
{
    extern __shared__ __align__(256) char sm[];
    uint32_t TILE = s2u(sm);
    const int tid = threadIdx.x, lane = tid & 31, wid = tid >> 5;
    const int warpM = wid & 3, warpN = wid >> 2;

    const int z = blockIdx.z;
    const bf16* Ag = p.A + (z/p.zdiv)*p.sA1 + (z%p.zdiv)*p.sA2 + (long)blockIdx.y*128*p.lda;
    const bf16* Bg = p.B + (z/p.zdiv)*p.sB1 + (z%p.zdiv)*p.sB2 + (long)blockIdx.x*128*p.ldb;

    auto loadStage = [&](int c){
        uint32_t st = TILE + (c%3)*STB;
        long kof = (long)c*128;
        #pragma unroll
        for (int i=0;i<8;i++){
            int idx = tid + i*256; int r = idx>>4, cc = idx&15;
            cpa16(st + r*ROWB + cc*16, Ag + (long)r*p.lda + kof + cc*8);
        }
        #pragma unroll
        for (int i=0;i<8;i++){
            int idx = tid + i*256; int r = idx>>4, cc = idx&15;
            cpa16(st + ASZ + r*ROWB + cc*16, Bg + (long)r*p.ldb + kof + cc*8);
        }
        asm volatile("cp.async.commit_group;":::"memory");
    };

    float acc[2][8][4];
    #pragma unroll
    for (int mf=0;mf<2;mf++)
        #pragma unroll
        for (int nf=0;nf<8;nf++)
            #pragma unroll
            for (int t=0;t<4;t++) acc[mf][nf][t] = 0.f;

    loadStage(0);
    if (p.kC > 1) loadStage(1);

    const uint32_t aRel = (uint32_t)((warpM*32 + (lane&15))*ROWB + (lane>>4)*16);
    const uint32_t bRel = (uint32_t)(ASZ + (warpN*64 + (lane&7))*ROWB + ((lane>>3)&3)*16);

    for (int c = 0; c < p.kC; c++) {
        if (c+1 < p.kC) asm volatile("cp.async.wait_group 1;":::"memory");
        else            asm volatile("cp.async.wait_group 0;":::"memory");
        __syncthreads();
        if (c+2 < p.kC) loadStage(c+2);

        uint32_t st = TILE + (c%3)*STB;
        uint32_t aB = st + aRel, bB = st + bRel;
        #pragma unroll
        for (int kh=0; kh<4; kh++){
            uint32_t bfr[8][4];
            #pragma unroll
            for (int nf=0; nf<8; nf++) ldm4(bfr[nf], bB + nf*(8*ROWB) + kh*64);
            #pragma unroll
            for (int s=0; s<2; s++){
                int ks = kh*2 + s;
                uint32_t af[2][4];
                #pragma unroll
                for (int mf=0; mf<2; mf++) ldm4(af[mf], aB + mf*(16*ROWB) + ks*32);
                #pragma unroll
                for (int mf=0; mf<2; mf++)
                    #pragma unroll
                    for (int nf=0; nf<8; nf++)
                        mma16816(acc[mf][nf], af[mf], bfr[nf][s*2], bfr[nf][s*2+1]);
            }
        }
        // no trailing sync: next iteration's leading sync orders stage reuse
    }

    // epilogue: (d0,d1)=(cr,ci)@row r ; (d2,d3)@row r+8 ; complex pair = adjacent cols
    const long coff = (z/p.zdiv)*p.sC1 + (z%p.zdiv)*p.sC2;
    const int ncBase = blockIdx.x*64 + warpN*32 + (lane&3);
    #pragma unroll
    for (int mf=0; mf<2; mf++){
        long r0 = (long)blockIdx.y*128 + warpM*32 + mf*16 + (lane>>2);
        #pragma unroll
        for (int nf=0; nf<8; nf++){
            int nc = ncBase + nf*4;
            float2 bb = p.bias ? p.bias[nc] : make_float2(0.f,0.f);
            #pragma unroll
            for (int h2=0; h2<2; h2++){
                long m = r0 + h2*8;
                float cr = acc[mf][nf][2*h2]   * p.scale + bb.x;
                float ci = acc[mf][nf][2*h2+1] * p.scale + bb.y;
                if (p.act){ float mg = sqrtf(cr*cr+ci*ci); cr = 0.5f*(cr+mg); ci = 0.5f*ci; }
                if (p.mode == 0) {
                    p.C[coff + m*p.ldc + nc] = make_float2(cr, ci);
                } else if (p.mode == 1) {          // Qa: per-head split-A [z][512][384]
                    int b=(int)(m>>9), s=(int)(m&511), hh=nc>>6, d=nc&63;
                    bf162 h,l; split2(cr, ci, h, l);
                    bf16* base = p.Ob + ((long)(b*16+hh)*512 + s)*384 + 2*d;
                    *(bf162*)(base)=h; *(bf162*)(base+128)=l; *(bf162*)(base+256)=h;
                } else if (p.mode == 4) {          // Hme: split-A [m][24576]
                    bf162 h,l; split2(cr, ci, h, l);
                    bf16* base = p.Ob + m*24576 + 2*nc;
                    *(bf162*)(base)=h; *(bf162*)(base+8192)=l; *(bf162*)(base+16384)=h;
                } else {                           // 2: Kb, 3: Vb (split-B layouts)
                    int b=(int)(m>>9), s=(int)(m&511), hh=nc>>6, d=nc&63;
                    long zz = b*16 + hh;
                    bf162 h0,l0,h1,l1; split2(cr,-ci,h0,l0); split2(ci,cr,h1,l1);
                    if (p.mode == 2) {
                        bf16* r0p = p.Ob + (zz*1024 + 2*s)*384 + 2*d;
                        bf16* r1p = r0p + 384;
                        *(bf162*)(r0p)=h0; *(bf162*)(r0p+128)=h0; *(bf162*)(r0p+256)=l0;
                        *(bf162*)(r1p)=h1; *(bf162*)(r1p+128)=h1; *(bf162*)(r1p+256)=l1;
                    } else {
                        bf16* r0p = p.Ob + (zz*128 + 2*d)*3072 + 2*s;
                        bf16* r1p = r0p + 3072;
                        *(bf162*)(r0p)=h0; *(bf162*)(r0p+1024)=h0; *(bf162*)(r0p+2048)=l0;
                        *(bf162*)(r1p)=h1; *(bf162*)(r1p+1024)=h1; *(bf162*)(r1p+2048)=l1;
                    }
                }
            }
        }
    }
}

// ---------------- expansions (inputs/weights only) ----------------
__global__ __launch_bounds__(256) void expandW(const float2* __restrict__ W, bf16* __restrict__ out, int K)
{
    long idx = (long)blockIdx.x*256 + threadIdx.x;
    long n = idx / K; int k = (int)(idx % K);
    float2 w = W[idx];
    bf162 h0,l0,h1,l1;
    split2(w.x, -w.y, h0, l0);
    split2(w.y,  w.x, h1, l1);
    long K2 = 2L*K;
    bf16* r0 = out + (2*n)*(3*K2) + 2*k;
    bf16* r1 = r0 + 3*K2;
    *(bf162*)(r0)=h0; *(bf162*)(r0+K2)=h0; *(bf162*)(r0+2*K2)=l0;
    *(bf162*)(r1)=h1; *(bf162*)(r1+K2)=h1; *(bf162*)(r1+2*K2)=l1;
}
__global__ __launch_bounds__(256) void expandA(const float2* __restrict__ X, bf16* __restrict__ out, int K)
{
    long idx = (long)blockIdx.x*256 + threadIdx.x;
    long m = idx / K; int k = (int)(idx % K);
    float2 v = X[idx];
    bf162 h,l; split2(v.x, v.y, h, l);
    long K2 = 2L*K;
    bf16* b = out + m*(3*K2) + 2*k;
    *(bf162*)(b)=h; *(bf162*)(b+K2)=l; *(bf162*)(b+2*K2)=h;
}

// ---------------- softmax + probs expansion ----------------
__global__ __launch_bounds__(256) void softmax_kernel(const float2* __restrict__ Sc, bf16* __restrict__ Pa)
{
    long rid = (long)blockIdx.x*8 + (threadIdx.x>>5);
    int lane = threadIdx.x & 31;
    const float2* r = Sc + rid*512;
    float2 v[16]; float mx=-1e30f, my=-1e30f;
    #pragma unroll
    for (int i=0;i<16;i++){ v[i]=r[lane+32*i]; mx=fmaxf(mx,v[i].x); my=fmaxf(my,v[i].y); }
    #pragma unroll
    for (int o=16;o>0;o>>=1){ mx=fmaxf(mx,__shfl_xor_sync(~0u,mx,o)); my=fmaxf(my,__shfl_xor_sync(~0u,my,o)); }
    float sx=0.f, sy=0.f;
    #pragma unroll
    for (int i=0;i<16;i++){ v[i].x=__expf(v[i].x-mx); v[i].y=__expf(v[i].y-my); sx+=v[i].x; sy+=v[i].y; }
    #pragma unroll
    for (int o=16;o>0;o>>=1){ sx+=__shfl_xor_sync(~0u,sx,o); sy+=__shfl_xor_sync(~0u,sy,o); }
    float ix=1.f/sx, iy=1.f/sy;
    bf16* base = Pa + rid*3072;
    #pragma unroll
    for (int i=0;i<16;i++){
        int k = lane + 32*i;
        bf162 h,l; split2(v[i].x*ix, v[i].y*iy, h, l);
        *(bf162*)(base+2*k)=h; *(bf162*)(base+1024+2*k)=l; *(bf162*)(base+2048+2*k)=h;
    }
}

// ---------------- layernorms ----------------
__device__ __forceinline__ void reduce4(float& a, float& b, float& c, float& d, float* sh)
{
    #pragma unroll
    for (int o=16;o>0;o>>=1){
        a+=__shfl_xor_sync(~0u,a,o); b+=__shfl_xor_sync(~0u,b,o);
        c+=__shfl_xor_sync(~0u,c,o); d+=__shfl_xor_sync(~0u,d,o);
    }
    int w = threadIdx.x>>5;
    __syncthreads();
    if ((threadIdx.x&31)==0){ sh[w]=a; sh[8+w]=b; sh[16+w]=c; sh[24+w]=d; }
    __syncthreads();
    float ra=0,rb=0,rc=0,rd=0;
    #pragma unroll
    for (int i=0;i<8;i++){ ra+=sh[i]; rb+=sh[8+i]; rc+=sh[16+i]; rd+=sh[24+i]; }
    a=ra; b=rb; c=rc; d=rd;
}

__global__ __launch_bounds__(256)
void ln_attn_kernel(const float2* __restrict__ O, const float2* __restrict__ query,
                    const float2* __restrict__ x,
                    const float* __restrict__ g, const float* __restrict__ bta,
                    float2* __restrict__ X2, bf16* __restrict__ X2e)
{
    __shared__ float sh[32];
    const long base = (long)blockIdx.x*DD;
    const float inv = 1.f/DD;
    float2 v[4]; float sr=0,sq=0,si=0,qi=0;
    #pragma unroll
    for (int i=0;i<4;i++){
        int d = threadIdx.x + i*256;
        float2 o=O[base+d], q=query[base+d];
        v[i]=make_float2(o.x+q.x, o.y+q.y);
        sr+=v[i].x; sq+=v[i].x*v[i].x; si+=v[i].y; qi+=v[i].y*v[i].y;
    }
    reduce4(sr,sq,si,qi,sh);
    float mr=sr*inv, mi=si*inv;
    float rr=rsqrtf(sq*inv-mr*mr+LN_EPS), ri=rsqrtf(qi*inv-mi*mi+LN_EPS);
    float2 u[4]; float s2=0,q2=0,s3=0,q3=0;
    #pragma unroll
    for (int i=0;i<4;i++){
        int d = threadIdx.x + i*256;
        float tr=(v[i].x-mr)*rr*g[d]+bta[d];
        float ti=(v[i].y-mi)*ri*g[DD+d]+bta[DD+d];
        float2 xx=x[base+d];
        u[i]=make_float2(xx.x+tr, xx.y+ti);
        s2+=u[i].x; q2+=u[i].x*u[i].x; s3+=u[i].y; q3+=u[i].y*u[i].y;
    }
    reduce4(s2,q2,s3,q3,sh);
    float m2=s2*inv, m3=s3*inv;
    float r2=rsqrtf(q2*inv-m2*m2+LN_EPS), r3=rsqrtf(q3*inv-m3*m3+LN_EPS);
    const float *g1=g+2*DD, *b1=bta+2*DD;
    #pragma unroll
    for (int i=0;i<4;i++){
        int d = threadIdx.x + i*256;
        float yr=(u[i].x-m2)*r2*g1[d]+b1[d];
        float yi=(u[i].y-m3)*r3*g1[DD+d]+b1[DD+d];
        X2[base+d]=make_float2(yr, yi);
        bf162 h,l; split2(yr, yi, h, l);
        bf16* eb = X2e + (long)blockIdx.x*6144 + 2*d;
        *(bf162*)(eb)=h; *(bf162*)(eb+2048)=l; *(bf162*)(eb+4096)=h;
    }
}

__global__ __launch_bounds__(256)
void ln_final_kernel(const float2* __restrict__ X2, const float2* __restrict__ Mp,
                     const float* __restrict__ g, const float* __restrict__ bta,
                     float2* __restrict__ out)
{
    __shared__ float sh[32];
    const long base = (long)blockIdx.x*DD;
    const float inv = 1.f/DD;
    float2 v[4]; float sr=0,sq=0,si=0,qi=0;
    #pragma unroll
    for (int i=0;i<4;i++){
        int d = threadIdx.x + i*256;
        float2 a=X2[base+d], m=Mp[base+d];
        v[i]=make_float2(a.x+m.x, a.y+m.y);
        sr+=v[i].x; sq+=v[i].x*v[i].x; si+=v[i].y; qi+=v[i].y*v[i].y;
    }
    reduce4(sr,sq,si,qi,sh);
    float mr=sr*inv, mi=si*inv;
    float rr=rsqrtf(sq*inv-mr*mr+LN_EPS), ri=rsqrtf(qi*inv-mi*mi+LN_EPS);
    const float *g2=g+4*DD, *b2=bta+4*DD;
    #pragma unroll
    for (int i=0;i<4;i++){
        int d = threadIdx.x + i*256;
        out[base+d]=make_float2((v[i].x-mr)*rr*g2[d]+b2[d], (v[i].y-mi)*ri*g2[DD+d]+b2[DD+d]);
    }
}

// ---------------- host ----------------
static GP mkgp(const bf16* A, long lda, const bf16* B, long ldb, int kC,
               int mode, float2* C, long ldc, bf16* Ob,
               const float2* bias, float scale, int act,
               int zdiv=1, long sA1=0,long sA2=0,long sB1=0,long sB2=0,long sC1=0,long sC2=0)
{
    GP p; p.A=A; p.B=B; p.lda=lda; p.ldb=ldb; p.kC=kC; p.mode=mode;
    p.C=C; p.ldc=ldc; p.Ob=Ob; p.bias=bias; p.scale=scale; p.act=act; p.zdiv=zdiv;
    p.sA1=sA1; p.sA2=sA2; p.sB1=sB1; p.sB2=sB2; p.sC1=sC1; p.sC2=sC2;
    return p;
}

extern "C" void kernel_launch(void* const* d_in, const int* in_sizes, int n_in,
                              void* d_out, int out_size)
{
    const float2* x     = (const float2*)d_in[0];
    const float2* query = (const float2*)d_in[1];
    const float2* wq    = (const float2*)d_in[2];
    const float2* bq    = (const float2*)d_in[3];
    const float2* wk    = (const float2*)d_in[4];
    const float2* bk    = (const float2*)d_in[5];
    const float2* wv    = (const float2*)d_in[6];
    const float2* bv    = (const float2*)d_in[7];
    const float2* wfc   = (const float2*)d_in[8];
    const float2* bfc   = (const float2*)d_in[9];
    const float2* wpr   = (const float2*)d_in[10];
    const float2* bpr   = (const float2*)d_in[11];
    const float*  lng   = (const float*)d_in[12];
    const float*  lnb   = (const float*)d_in[13];

    bf16 *Qe,*Xe,*X2e,*Hme,*Wqe,*Wke,*Wve,*Wfe,*Wpe,*Qa,*Kb,*Vb,*Pa;
    float2 *O,*X2,*Mp,*Sc;
    cudaGetSymbolAddress((void**)&Qe,g_Qe);   cudaGetSymbolAddress((void**)&Xe,g_Xe);
    cudaGetSymbolAddress((void**)&X2e,g_X2e); cudaGetSymbolAddress((void**)&Hme,g_Hme);
    cudaGetSymbolAddress((void**)&Wqe,g_Wqe); cudaGetSymbolAddress((void**)&Wke,g_Wke);
    cudaGetSymbolAddress((void**)&Wve,g_Wve); cudaGetSymbolAddress((void**)&Wfe,g_Wfe);
    cudaGetSymbolAddress((void**)&Wpe,g_Wpe); cudaGetSymbolAddress((void**)&Qa,g_Qa);
    cudaGetSymbolAddress((void**)&Kb,g_Kb);   cudaGetSymbolAddress((void**)&Vb,g_Vb);
    cudaGetSymbolAddress((void**)&Pa,g_Pa);
    cudaGetSymbolAddress((void**)&O,g_O);   cudaGetSymbolAddress((void**)&X2,g_X2);
    cudaGetSymbolAddress((void**)&Mp,g_Mp); cudaGetSymbolAddress((void**)&Sc,g_Sc);

    cudaFuncSetAttribute(tgemm, cudaFuncAttributeMaxDynamicSharedMemorySize, SMB);

    // expansions of inputs/weights
    expandA<<<MR*DD/256,256>>>(query, Qe, DD);
    expandA<<<MR*DD/256,256>>>(x,     Xe, DD);
    expandW<<<1024*1024/256,256>>>(wq, Wqe, DD);
    expandW<<<1024*1024/256,256>>>(wk, Wke, DD);
    expandW<<<1024*1024/256,256>>>(wv, Wve, DD);
    expandW<<<4096*1024/256,256>>>(wfc, Wfe, DD);
    expandW<<<1024*4096/256,256>>>(wpr, Wpe, 4096);

    // QKV projections: K_eff=6144 (kC=48), epilogues write attention layouts directly
    {
        dim3 grd(16, 32, 1);
        tgemm<<<grd,256,SMB>>>(mkgp(Qe,6144, Wqe,6144, 48, 1, nullptr,0, Qa, bq,1.f,0));
        tgemm<<<grd,256,SMB>>>(mkgp(Xe,6144, Wke,6144, 48, 2, nullptr,0, Kb, bk,1.f,0));
        tgemm<<<grd,256,SMB>>>(mkgp(Xe,6144, Wve,6144, 48, 3, nullptr,0, Vb, bv,1.f,0));
    }

    // scores: per z=(b,h): [512 x 1024'], K_eff=384 (kC=3)
    {
        dim3 grd(8, 4, 128);
        tgemm<<<grd,256,SMB>>>(mkgp(Qa,384, Kb,384, 3, 0, Sc,512, nullptr, nullptr,0.125f,0,
            1, 512L*384,0, 1024L*384,0, 512L*512,0));
    }
    softmax_kernel<<<128*512/8,256>>>(Sc, Pa);

    // AV: per z: [512 x 128'], K_eff=3072 (kC=24)
    {
        dim3 grd(1, 4, 128);
        tgemm<<<grd,256,SMB>>>(mkgp(Pa,3072, Vb,3072, 24, 0, O,1024, nullptr, nullptr,1.f,0,
            16, 16L*512*3072, 512L*3072, 16L*128*3072, 128L*3072, 512L*1024, 64));
    }
    ln_attn_kernel<<<MR,256>>>(O, query, x, lng, lnb, X2, X2e);

    // fc: [4096 x 8192'], K_eff=6144 (kC=48), bias+modReLU, writes Hme split-A directly
    tgemm<<<dim3(64,32,1),256,SMB>>>(mkgp(X2e,6144, Wfe,6144, 48, 4, nullptr,0, Hme, bfc,1.f,1));

    // proj: [4096 x 2048'], K_eff=24576 (kC=192)
    tgemm<<<dim3(16,32,1),256,SMB>>>(mkgp(Hme,24576, Wpe,24576, 192, 0, Mp,1024, nullptr, bpr,1.f,0));

    ln_final_kernel<<<MR,256>>>(X2, Mp, lng, lnb, (float2*)d_out);
}

// round 7
// speedup vs baseline: 2.7937x; 1.2106x over previous
#include <cuda_runtime.h>
#include <cuda_bf16.h>
#include <cstdint>
#include <math.h>

typedef __nv_bfloat16 bf16;
typedef __nv_bfloat162 bf162;

#define DD 1024
#define MR 4096
#define LN_EPS 1e-5f

// ---------------- scratch (device globals; no allocation) ----------------
__device__ __align__(256) bf16 g_Qe [(size_t)MR*6144];
__device__ __align__(256) bf16 g_Xe [(size_t)MR*6144];
__device__ __align__(256) bf16 g_X2e[(size_t)MR*6144];
__device__ __align__(256) bf16 g_Hme[(size_t)MR*24576];
__device__ __align__(256) bf16 g_Wqe[(size_t)2048*6144];
__device__ __align__(256) bf16 g_Wke[(size_t)2048*6144];
__device__ __align__(256) bf16 g_Wve[(size_t)2048*6144];
__device__ __align__(256) bf16 g_Wfe[(size_t)8192*6144];
__device__ __align__(256) bf16 g_Wpe[(size_t)2048*24576];
__device__ __align__(256) bf16 g_Qa [(size_t)128*512*384];
__device__ __align__(256) bf16 g_Kb [(size_t)128*1024*384];
__device__ __align__(256) bf16 g_Vb [(size_t)128*128*3072];
__device__ __align__(256) bf16 g_Pa [(size_t)128*512*3072];
__device__ float2 g_O [(size_t)MR*DD];
__device__ float2 g_X2[(size_t)MR*DD];
__device__ float2 g_Mp[(size_t)MR*DD];
__device__ float2 g_Sc[(size_t)128*512*512];

// ---------------- helpers ----------------
__device__ __forceinline__ uint32_t s2u(const void* p){
    uint32_t a;
    asm("{ .reg .u64 t; cvta.to.shared.u64 t, %1; cvt.u32.u64 %0, t; }":"=r"(a):"l"(p));
    return a;
}
__device__ __forceinline__ void cpa16(uint32_t d, const void* g){
    asm volatile("cp.async.cg.shared.global [%0], [%1], 16;"::"r"(d),"l"(g));
}
__device__ __forceinline__ void split2(float vr, float vi, bf162& h, bf162& l){
    bf16 hr=__float2bfloat16_rn(vr), hi=__float2bfloat16_rn(vi);
    h.x=hr; h.y=hi;
    l.x=__float2bfloat16_rn(vr-__bfloat162float(hr));
    l.y=__float2bfloat16_rn(vi-__bfloat162float(hi));
}
__device__ __forceinline__ void ldm4(uint32_t* r, uint32_t a){
    asm volatile("ldmatrix.sync.aligned.m8n8.x4.shared.b16 {%0,%1,%2,%3}, [%4];"
        :"=r"(r[0]),"=r"(r[1]),"=r"(r[2]),"=r"(r[3]):"r"(a));
}
__device__ __forceinline__ void mma16816(float* d, const uint32_t* a, uint32_t b0, uint32_t b1){
    asm volatile("mma.sync.aligned.m16n8k16.row.col.f32.bf16.bf16.f32 "
        "{%0,%1,%2,%3}, {%4,%5,%6,%7}, {%8,%9}, {%0,%1,%2,%3};"
        :"+f"(d[0]),"+f"(d[1]),"+f"(d[2]),"+f"(d[3])
        :"r"(a[0]),"r"(a[1]),"r"(a[2]),"r"(a[3]),"r"(b0),"r"(b1));
}

// ---------------- GEMM via mma.sync ----------------
// BM=128, BN=128, BK=64; 8 warps (4M x 2N); 3-stage cp.async; 1 sync/chunk; 2 CTAs/SM.
// MODE: 0=float2 C; 1=Qa split-A per-head; 2=Kb split-B; 3=Vb split-B; 4=Hme split-A
struct GP {
    const bf16 *A, *B; long lda, ldb;
    long sA1, sA2, sB1, sB2;
    float2* C; long ldc, sC1, sC2;
    bf16* Ob;
    int zdiv, kC, act;
    const float2* bias; float scale;
};
#define ROWB 144            // 64 bf16 = 128B data + 16B pad
#define ASZ  (128*ROWB)     // 18432
#define STB  (2*ASZ)        // 36864
#define SMB  (3*STB)        // 110592

template<int MODE>
__global__ __launch_bounds__(256,2) void tgemm(GP p)
{
    extern __shared__ __align__(256) char sm[];
    uint32_t TILE = s2u(sm);
    const int tid = threadIdx.x, lane = tid & 31, wid = tid >> 5;
    const int warpM = wid & 3, warpN = wid >> 2;

    const int z = blockIdx.z;
    const bf16* Ag = p.A + (z/p.zdiv)*p.sA1 + (z%p.zdiv)*p.sA2 + (long)blockIdx.y*128*p.lda;
    const bf16* Bg = p.B + (z/p.zdiv)*p.sB1 + (z%p.zdiv)*p.sB2 + (long)blockIdx.x*128*p.ldb;

    auto loadStage = [&](int c){
        uint32_t st = TILE + (c%3)*STB;
        long kof = (long)c*64;
        #pragma unroll
        for (int i=0;i<4;i++){
            int idx = tid + i*256; int r = idx>>3, cc = idx&7;
            cpa16(st + r*ROWB + cc*16, Ag + (long)r*p.lda + kof + cc*8);
        }
        #pragma unroll
        for (int i=0;i<4;i++){
            int idx = tid + i*256; int r = idx>>3, cc = idx&7;
            cpa16(st + ASZ + r*ROWB + cc*16, Bg + (long)r*p.ldb + kof + cc*8);
        }
        asm volatile("cp.async.commit_group;":::"memory");
    };

    float acc[2][8][4];
    #pragma unroll
    for (int mf=0;mf<2;mf++)
        #pragma unroll
        for (int nf=0;nf<8;nf++)
            #pragma unroll
            for (int t=0;t<4;t++) acc[mf][nf][t] = 0.f;

    loadStage(0);
    if (p.kC > 1) loadStage(1);

    const uint32_t aRel = (uint32_t)((warpM*32 + (lane&15))*ROWB + (lane>>4)*16);
    const uint32_t bRel = (uint32_t)(ASZ + (warpN*64 + (lane&7))*ROWB + ((lane>>3)&3)*16);

    for (int c = 0; c < p.kC; c++) {
        if (c+1 < p.kC) asm volatile("cp.async.wait_group 1;":::"memory");
        else            asm volatile("cp.async.wait_group 0;":::"memory");
        __syncthreads();
        if (c+2 < p.kC) loadStage(c+2);

        uint32_t st = TILE + (c%3)*STB;
        uint32_t aB = st + aRel, bB = st + bRel;
        #pragma unroll
        for (int kh=0; kh<2; kh++){
            uint32_t bfr[8][4];
            #pragma unroll
            for (int nf=0; nf<8; nf++) ldm4(bfr[nf], bB + nf*(8*ROWB) + kh*64);
            #pragma unroll
            for (int s=0; s<2; s++){
                int ks = kh*2 + s;
                uint32_t af[2][4];
                #pragma unroll
                for (int mf=0; mf<2; mf++) ldm4(af[mf], aB + mf*(16*ROWB) + ks*32);
                #pragma unroll
                for (int mf=0; mf<2; mf++)
                    #pragma unroll
                    for (int nf=0; nf<8; nf++)
                        mma16816(acc[mf][nf], af[mf], bfr[nf][s*2], bfr[nf][s*2+1]);
            }
        }
        // no trailing sync: next iteration's leading sync orders stage reuse
    }

    // epilogue: (d0,d1)=(cr,ci)@row r ; (d2,d3)@row r+8 ; complex pair = adjacent cols
    const long coff = (z/p.zdiv)*p.sC1 + (z%p.zdiv)*p.sC2;
    const int ncBase = blockIdx.x*64 + warpN*32 + (lane&3);
    #pragma unroll
    for (int mf=0; mf<2; mf++){
        long r0 = (long)blockIdx.y*128 + warpM*32 + mf*16 + (lane>>2);
        #pragma unroll
        for (int nf=0; nf<8; nf++){
            int nc = ncBase + nf*4;
            float2 bb = p.bias ? p.bias[nc] : make_float2(0.f,0.f);
            #pragma unroll
            for (int h2=0; h2<2; h2++){
                long m = r0 + h2*8;
                float cr = acc[mf][nf][2*h2]   * p.scale + bb.x;
                float ci = acc[mf][nf][2*h2+1] * p.scale + bb.y;
                if (p.act){ float mg = sqrtf(cr*cr+ci*ci); cr = 0.5f*(cr+mg); ci = 0.5f*ci; }
                if (MODE == 0) {
                    p.C[coff + m*p.ldc + nc] = make_float2(cr, ci);
                } else if (MODE == 1) {          // Qa: per-head split-A [z][512][384]
                    int b=(int)(m>>9), s=(int)(m&511), hh=nc>>6, d=nc&63;
                    bf162 h,l; split2(cr, ci, h, l);
                    bf16* base = p.Ob + ((long)(b*16+hh)*512 + s)*384 + 2*d;
                    *(bf162*)(base)=h; *(bf162*)(base+128)=l; *(bf162*)(base+256)=h;
                } else if (MODE == 4) {          // Hme: split-A [m][24576]
                    bf162 h,l; split2(cr, ci, h, l);
                    bf16* base = p.Ob + m*24576 + 2*nc;
                    *(bf162*)(base)=h; *(bf162*)(base+8192)=l; *(bf162*)(base+16384)=h;
                } else {                         // 2: Kb, 3: Vb (split-B layouts)
                    int b=(int)(m>>9), s=(int)(m&511), hh=nc>>6, d=nc&63;
                    long zz = b*16 + hh;
                    bf162 h0,l0,h1,l1; split2(cr,-ci,h0,l0); split2(ci,cr,h1,l1);
                    if (MODE == 2) {
                        bf16* r0p = p.Ob + (zz*1024 + 2*s)*384 + 2*d;
                        bf16* r1p = r0p + 384;
                        *(bf162*)(r0p)=h0; *(bf162*)(r0p+128)=h0; *(bf162*)(r0p+256)=l0;
                        *(bf162*)(r1p)=h1; *(bf162*)(r1p+128)=h1; *(bf162*)(r1p+256)=l1;
                    } else {
                        bf16* r0p = p.Ob + (zz*128 + 2*d)*3072 + 2*s;
                        bf16* r1p = r0p + 3072;
                        *(bf162*)(r0p)=h0; *(bf162*)(r0p+1024)=h0; *(bf162*)(r0p+2048)=l0;
                        *(bf162*)(r1p)=h1; *(bf162*)(r1p+1024)=h1; *(bf162*)(r1p+2048)=l1;
                    }
                }
            }
        }
    }
}

// ---------------- expansions (inputs/weights only) ----------------
__global__ __launch_bounds__(256) void expandW(const float2* __restrict__ W, bf16* __restrict__ out, int K)
{
    long idx = (long)blockIdx.x*256 + threadIdx.x;
    long n = idx / K; int k = (int)(idx % K);
    float2 w = W[idx];
    bf162 h0,l0,h1,l1;
    split2(w.x, -w.y, h0, l0);
    split2(w.y,  w.x, h1, l1);
    long K2 = 2L*K;
    bf16* r0 = out + (2*n)*(3*K2) + 2*k;
    bf16* r1 = r0 + 3*K2;
    *(bf162*)(r0)=h0; *(bf162*)(r0+K2)=h0; *(bf162*)(r0+2*K2)=l0;
    *(bf162*)(r1)=h1; *(bf162*)(r1+K2)=h1; *(bf162*)(r1+2*K2)=l1;
}
__global__ __launch_bounds__(256) void expandA(const float2* __restrict__ X, bf16* __restrict__ out, int K)
{
    long idx = (long)blockIdx.x*256 + threadIdx.x;
    long m = idx / K; int k = (int)(idx % K);
    float2 v = X[idx];
    bf162 h,l; split2(v.x, v.y, h, l);
    long K2 = 2L*K;
    bf16* b = out + m*(3*K2) + 2*k;
    *(bf162*)(b)=h; *(bf162*)(b+K2)=l; *(bf162*)(b+2*K2)=h;
}

// ---------------- softmax + probs expansion ----------------
__global__ __launch_bounds__(256) void softmax_kernel(const float2* __restrict__ Sc, bf16* __restrict__ Pa)
{
    long rid = (long)blockIdx.x*8 + (threadIdx.x>>5);
    int lane = threadIdx.x & 31;
    const float2* r = Sc + rid*512;
    float2 v[16]; float mx=-1e30f, my=-1e30f;
    #pragma unroll
    for (int i=0;i<16;i++){ v[i]=r[lane+32*i]; mx=fmaxf(mx,v[i].x); my=fmaxf(my,v[i].y); }
    #pragma unroll
    for (int o=16;o>0;o>>=1){ mx=fmaxf(mx,__shfl_xor_sync(~0u,mx,o)); my=fmaxf(my,__shfl_xor_sync(~0u,my,o)); }
    float sx=0.f, sy=0.f;
    #pragma unroll
    for (int i=0;i<16;i++){ v[i].x=__expf(v[i].x-mx); v[i].y=__expf(v[i].y-my); sx+=v[i].x; sy+=v[i].y; }
    #pragma unroll
    for (int o=16;o>0;o>>=1){ sx+=__shfl_xor_sync(~0u,sx,o); sy+=__shfl_xor_sync(~0u,sy,o); }
    float ix=1.f/sx, iy=1.f/sy;
    bf16* base = Pa + rid*3072;
    #pragma unroll
    for (int i=0;i<16;i++){
        int k = lane + 32*i;
        bf162 h,l; split2(v[i].x*ix, v[i].y*iy, h, l);
        *(bf162*)(base+2*k)=h; *(bf162*)(base+1024+2*k)=l; *(bf162*)(base+2048+2*k)=h;
    }
}

// ---------------- layernorms ----------------
__device__ __forceinline__ void reduce4(float& a, float& b, float& c, float& d, float* sh)
{
    #pragma unroll
    for (int o=16;o>0;o>>=1){
        a+=__shfl_xor_sync(~0u,a,o); b+=__shfl_xor_sync(~0u,b,o);
        c+=__shfl_xor_sync(~0u,c,o); d+=__shfl_xor_sync(~0u,d,o);
    }
    int w = threadIdx.x>>5;
    __syncthreads();
    if ((threadIdx.x&31)==0){ sh[w]=a; sh[8+w]=b; sh[16+w]=c; sh[24+w]=d; }
    __syncthreads();
    float ra=0,rb=0,rc=0,rd=0;
    #pragma unroll
    for (int i=0;i<8;i++){ ra+=sh[i]; rb+=sh[8+i]; rc+=sh[16+i]; rd+=sh[24+i]; }
    a=ra; b=rb; c=rc; d=rd;
}

__global__ __launch_bounds__(256)
void ln_attn_kernel(const float2* __restrict__ O, const float2* __restrict__ query,
                    const float2* __restrict__ x,
                    const float* __restrict__ g, const float* __restrict__ bta,
                    float2* __restrict__ X2, bf16* __restrict__ X2e)
{
    __shared__ float sh[32];
    const long base = (long)blockIdx.x*DD;
    const float inv = 1.f/DD;
    float2 v[4]; float sr=0,sq=0,si=0,qi=0;
    #pragma unroll
    for (int i=0;i<4;i++){
        int d = threadIdx.x + i*256;
        float2 o=O[base+d], q=query[base+d];
        v[i]=make_float2(o.x+q.x, o.y+q.y);
        sr+=v[i].x; sq+=v[i].x*v[i].x; si+=v[i].y; qi+=v[i].y*v[i].y;
    }
    reduce4(sr,sq,si,qi,sh);
    float mr=sr*inv, mi=si*inv;
    float rr=rsqrtf(sq*inv-mr*mr+LN_EPS), ri=rsqrtf(qi*inv-mi*mi+LN_EPS);
    float2 u[4]; float s2=0,q2=0,s3=0,q3=0;
    #pragma unroll
    for (int i=0;i<4;i++){
        int d = threadIdx.x + i*256;
        float tr=(v[i].x-mr)*rr*g[d]+bta[d];
        float ti=(v[i].y-mi)*ri*g[DD+d]+bta[DD+d];
        float2 xx=x[base+d];
        u[i]=make_float2(xx.x+tr, xx.y+ti);
        s2+=u[i].x; q2+=u[i].x*u[i].x; s3+=u[i].y; q3+=u[i].y*u[i].y;
    }
    reduce4(s2,q2,s3,q3,sh);
    float m2=s2*inv, m3=s3*inv;
    float r2=rsqrtf(q2*inv-m2*m2+LN_EPS), r3=rsqrtf(q3*inv-m3*m3+LN_EPS);
    const float *g1=g+2*DD, *b1=bta+2*DD;
    #pragma unroll
    for (int i=0;i<4;i++){
        int d = threadIdx.x + i*256;
        float yr=(u[i].x-m2)*r2*g1[d]+b1[d];
        float yi=(u[i].y-m3)*r3*g1[DD+d]+b1[DD+d];
        X2[base+d]=make_float2(yr, yi);
        bf162 h,l; split2(yr, yi, h, l);
        bf16* eb = X2e + (long)blockIdx.x*6144 + 2*d;
        *(bf162*)(eb)=h; *(bf162*)(eb+2048)=l; *(bf162*)(eb+4096)=h;
    }
}

__global__ __launch_bounds__(256)
void ln_final_kernel(const float2* __restrict__ X2, const float2* __restrict__ Mp,
                     const float* __restrict__ g, const float* __restrict__ bta,
                     float2* __restrict__ out)
{
    __shared__ float sh[32];
    const long base = (long)blockIdx.x*DD;
    const float inv = 1.f/DD;
    float2 v[4]; float sr=0,sq=0,si=0,qi=0;
    #pragma unroll
    for (int i=0;i<4;i++){
        int d = threadIdx.x + i*256;
        float2 a=X2[base+d], m=Mp[base+d];
        v[i]=make_float2(a.x+m.x, a.y+m.y);
        sr+=v[i].x; sq+=v[i].x*v[i].x; si+=v[i].y; qi+=v[i].y*v[i].y;
    }
    reduce4(sr,sq,si,qi,sh);
    float mr=sr*inv, mi=si*inv;
    float rr=rsqrtf(sq*inv-mr*mr+LN_EPS), ri=rsqrtf(qi*inv-mi*mi+LN_EPS);
    const float *g2=g+4*DD, *b2=bta+4*DD;
    #pragma unroll
    for (int i=0;i<4;i++){
        int d = threadIdx.x + i*256;
        out[base+d]=make_float2((v[i].x-mr)*rr*g2[d]+b2[d], (v[i].y-mi)*ri*g2[DD+d]+b2[DD+d]);
    }
}

// ---------------- host ----------------
static GP mkgp(const bf16* A, long lda, const bf16* B, long ldb, int kC,
               float2* C, long ldc, bf16* Ob,
               const float2* bias, float scale, int act,
               int zdiv=1, long sA1=0,long sA2=0,long sB1=0,long sB2=0,long sC1=0,long sC2=0)
{
    GP p; p.A=A; p.B=B; p.lda=lda; p.ldb=ldb; p.kC=kC;
    p.C=C; p.ldc=ldc; p.Ob=Ob; p.bias=bias; p.scale=scale; p.act=act; p.zdiv=zdiv;
    p.sA1=sA1; p.sA2=sA2; p.sB1=sB1; p.sB2=sB2; p.sC1=sC1; p.sC2=sC2;
    return p;
}

extern "C" void kernel_launch(void* const* d_in, const int* in_sizes, int n_in,
                              void* d_out, int out_size)
{
    const float2* x     = (const float2*)d_in[0];
    const float2* query = (const float2*)d_in[1];
    const float2* wq    = (const float2*)d_in[2];
    const float2* bq    = (const float2*)d_in[3];
    const float2* wk    = (const float2*)d_in[4];
    const float2* bk    = (const float2*)d_in[5];
    const float2* wv    = (const float2*)d_in[6];
    const float2* bv    = (const float2*)d_in[7];
    const float2* wfc   = (const float2*)d_in[8];
    const float2* bfc   = (const float2*)d_in[9];
    const float2* wpr   = (const float2*)d_in[10];
    const float2* bpr   = (const float2*)d_in[11];
    const float*  lng   = (const float*)d_in[12];
    const float*  lnb   = (const float*)d_in[13];

    bf16 *Qe,*Xe,*X2e,*Hme,*Wqe,*Wke,*Wve,*Wfe,*Wpe,*Qa,*Kb,*Vb,*Pa;
    float2 *O,*X2,*Mp,*Sc;
    cudaGetSymbolAddress((void**)&Qe,g_Qe);   cudaGetSymbolAddress((void**)&Xe,g_Xe);
    cudaGetSymbolAddress((void**)&X2e,g_X2e); cudaGetSymbolAddress((void**)&Hme,g_Hme);
    cudaGetSymbolAddress((void**)&Wqe,g_Wqe); cudaGetSymbolAddress((void**)&Wke,g_Wke);
    cudaGetSymbolAddress((void**)&Wve,g_Wve); cudaGetSymbolAddress((void**)&Wfe,g_Wfe);
    cudaGetSymbolAddress((void**)&Wpe,g_Wpe); cudaGetSymbolAddress((void**)&Qa,g_Qa);
    cudaGetSymbolAddress((void**)&Kb,g_Kb);   cudaGetSymbolAddress((void**)&Vb,g_Vb);
    cudaGetSymbolAddress((void**)&Pa,g_Pa);
    cudaGetSymbolAddress((void**)&O,g_O);   cudaGetSymbolAddress((void**)&X2,g_X2);
    cudaGetSymbolAddress((void**)&Mp,g_Mp); cudaGetSymbolAddress((void**)&Sc,g_Sc);

    cudaFuncSetAttribute(tgemm<0>, cudaFuncAttributeMaxDynamicSharedMemorySize, SMB);
    cudaFuncSetAttribute(tgemm<1>, cudaFuncAttributeMaxDynamicSharedMemorySize, SMB);
    cudaFuncSetAttribute(tgemm<2>, cudaFuncAttributeMaxDynamicSharedMemorySize, SMB);
    cudaFuncSetAttribute(tgemm<3>, cudaFuncAttributeMaxDynamicSharedMemorySize, SMB);
    cudaFuncSetAttribute(tgemm<4>, cudaFuncAttributeMaxDynamicSharedMemorySize, SMB);

    // expansions of inputs/weights
    expandA<<<MR*DD/256,256>>>(query, Qe, DD);
    expandA<<<MR*DD/256,256>>>(x,     Xe, DD);
    expandW<<<1024*1024/256,256>>>(wq, Wqe, DD);
    expandW<<<1024*1024/256,256>>>(wk, Wke, DD);
    expandW<<<1024*1024/256,256>>>(wv, Wve, DD);
    expandW<<<4096*1024/256,256>>>(wfc, Wfe, DD);
    expandW<<<1024*4096/256,256>>>(wpr, Wpe, 4096);

    // QKV projections: K_eff=6144 (kC=96), epilogues write attention layouts directly
    {
        dim3 grd(16, 32, 1);
        tgemm<1><<<grd,256,SMB>>>(mkgp(Qe,6144, Wqe,6144, 96, nullptr,0, Qa, bq,1.f,0));
        tgemm<2><<<grd,256,SMB>>>(mkgp(Xe,6144, Wke,6144, 96, nullptr,0, Kb, bk,1.f,0));
        tgemm<3><<<grd,256,SMB>>>(mkgp(Xe,6144, Wve,6144, 96, nullptr,0, Vb, bv,1.f,0));
    }

    // scores: per z=(b,h): [512 x 1024'], K_eff=384 (kC=6)
    {
        dim3 grd(8, 4, 128);
        tgemm<0><<<grd,256,SMB>>>(mkgp(Qa,384, Kb,384, 6, Sc,512, nullptr, nullptr,0.125f,0,
            1, 512L*384,0, 1024L*384,0, 512L*512,0));
    }
    softmax_kernel<<<128*512/8,256>>>(Sc, Pa);

    // AV: per z: [512 x 128'], K_eff=3072 (kC=48)
    {
        dim3 grd(1, 4, 128);
        tgemm<0><<<grd,256,SMB>>>(mkgp(Pa,3072, Vb,3072, 48, O,1024, nullptr, nullptr,1.f,0,
            16, 16L*512*3072, 512L*3072, 16L*128*3072, 128L*3072, 512L*1024, 64));
    }
    ln_attn_kernel<<<MR,256>>>(O, query, x, lng, lnb, X2, X2e);

    // fc: [4096 x 8192'], K_eff=6144 (kC=96), bias+modReLU, writes Hme split-A directly
    tgemm<4><<<dim3(64,32,1),256,SMB>>>(mkgp(X2e,6144, Wfe,6144, 96, nullptr,0, Hme, bfc,1.f,1));

    // proj: [4096 x 2048'], K_eff=24576 (kC=384)
    tgemm<0><<<dim3(16,32,1),256,SMB>>>(mkgp(Hme,24576, Wpe,24576, 384, Mp,1024, nullptr, bpr,1.f,0));

    ln_final_kernel<<<MR,256>>>(X2, Mp, lng, lnb, (float2*)d_out);
}

// round 8
// speedup vs baseline: 2.9920x; 1.0710x over previous
#include <cuda_runtime.h>
#include <cuda_bf16.h>
#include <cstdint>
#include <math.h>

typedef __nv_bfloat16 bf16;
typedef __nv_bfloat162 bf162;

#define DD 1024
#define MR 4096
#define LN_EPS 1e-5f

// ---------------- scratch (device globals; no allocation) ----------------
__device__ __align__(256) bf16 g_Qe [(size_t)MR*6144];
__device__ __align__(256) bf16 g_Xe [(size_t)MR*6144];
__device__ __align__(256) bf16 g_X2e[(size_t)MR*6144];
__device__ __align__(256) bf16 g_Hme[(size_t)MR*24576];
__device__ __align__(256) bf16 g_Wqe[(size_t)2048*6144];
__device__ __align__(256) bf16 g_Wke[(size_t)2048*6144];
__device__ __align__(256) bf16 g_Wve[(size_t)2048*6144];
__device__ __align__(256) bf16 g_Wfe[(size_t)8192*6144];
__device__ __align__(256) bf16 g_Wpe[(size_t)2048*24576];
__device__ __align__(256) bf16 g_Qa [(size_t)128*512*384];
__device__ __align__(256) bf16 g_Kb [(size_t)128*1024*384];
__device__ __align__(256) bf16 g_Vb [(size_t)128*128*3072];
__device__ __align__(256) bf16 g_Pa [(size_t)128*512*3072];
__device__ float2 g_O [(size_t)MR*DD];
__device__ float2 g_X2[(size_t)MR*DD];
__device__ float2 g_Mp[(size_t)4*MR*DD];     // 4 split-K partials
__device__ float2 g_Sc[(size_t)128*512*512];

// ---------------- helpers ----------------
__device__ __forceinline__ uint32_t s2u(const void* p){
    uint32_t a;
    asm("{ .reg .u64 t; cvta.to.shared.u64 t, %1; cvt.u32.u64 %0, t; }":"=r"(a):"l"(p));
    return a;
}
__device__ __forceinline__ void cpa16(uint32_t d, const void* g){
    asm volatile("cp.async.cg.shared.global [%0], [%1], 16;"::"r"(d),"l"(g));
}
__device__ __forceinline__ void split2(float vr, float vi, bf162& h, bf162& l){
    bf16 hr=__float2bfloat16_rn(vr), hi=__float2bfloat16_rn(vi);
    h.x=hr; h.y=hi;
    l.x=__float2bfloat16_rn(vr-__bfloat162float(hr));
    l.y=__float2bfloat16_rn(vi-__bfloat162float(hi));
}
__device__ __forceinline__ void ldm4(uint32_t* r, uint32_t a){
    asm volatile("ldmatrix.sync.aligned.m8n8.x4.shared.b16 {%0,%1,%2,%3}, [%4];"
        :"=r"(r[0]),"=r"(r[1]),"=r"(r[2]),"=r"(r[3]):"r"(a));
}
__device__ __forceinline__ void mma16816(float* d, const uint32_t* a, uint32_t b0, uint32_t b1){
    asm volatile("mma.sync.aligned.m16n8k16.row.col.f32.bf16.bf16.f32 "
        "{%0,%1,%2,%3}, {%4,%5,%6,%7}, {%8,%9}, {%0,%1,%2,%3};"
        :"+f"(d[0]),"+f"(d[1]),"+f"(d[2]),"+f"(d[3])
        :"r"(a[0]),"r"(a[1]),"r"(a[2]),"r"(a[3]),"r"(b0),"r"(b1));
}

// ---------------- GEMM via mma.sync ----------------
// BM=128, BN=128, BK=64; 8 warps (4M x 2N); 3-stage cp.async; 1 sync/chunk; 2 CTAs/SM.
// MODE: 0=float2 C; 4=Hme split-A; 5=fused QKV (z selects Q/K/V path)
struct GP {
    const bf16 *A, *B, *A2, *B1, *B2;
    long lda, ldb;
    long sA1, sA2, sB1, sB2;
    float2* C; long ldc, sC1, sC2;
    bf16 *Ob, *Ob1, *Ob2;
    const float2 *bias, *bias1, *bias2;
    int zdiv, kC, act;
    float scale;
};
#define ROWB 144            // 64 bf16 = 128B data + 16B pad
#define ASZ  (128*ROWB)     // 18432
#define STB  (2*ASZ)        // 36864
#define SMB  (3*STB)        // 110592

template<int MODE>
__global__ __launch_bounds__(256,2) void tgemm(GP p)
{
    extern __shared__ __align__(256) char sm[];
    uint32_t TILE = s2u(sm);
    const int tid = threadIdx.x, lane = tid & 31, wid = tid >> 5;
    const int warpM = wid & 3, warpN = wid >> 2;

    const int z = blockIdx.z;
    const bf16 *Ap = p.A, *Bp = p.B;
    const float2* bi = p.bias;
    if (MODE == 5) {
        if (z == 1) { Ap = p.A2; Bp = p.B1; bi = p.bias1; }
        else if (z == 2) { Ap = p.A2; Bp = p.B2; bi = p.bias2; }
    }
    long offA = 0, offB = 0;
    if (MODE != 5) {
        offA = (z/p.zdiv)*p.sA1 + (z%p.zdiv)*p.sA2;
        offB = (z/p.zdiv)*p.sB1 + (z%p.zdiv)*p.sB2;
    }
    const bf16* Ag = Ap + offA + (long)blockIdx.y*128*p.lda;
    const bf16* Bg = Bp + offB + (long)blockIdx.x*128*p.ldb;

    auto loadStage = [&](int c){
        uint32_t st = TILE + (c%3)*STB;
        long kof = (long)c*64;
        #pragma unroll
        for (int i=0;i<4;i++){
            int idx = tid + i*256; int r = idx>>3, cc = idx&7;
            cpa16(st + r*ROWB + cc*16, Ag + (long)r*p.lda + kof + cc*8);
        }
        #pragma unroll
        for (int i=0;i<4;i++){
            int idx = tid + i*256; int r = idx>>3, cc = idx&7;
            cpa16(st + ASZ + r*ROWB + cc*16, Bg + (long)r*p.ldb + kof + cc*8);
        }
        asm volatile("cp.async.commit_group;":::"memory");
    };

    float acc[2][8][4];
    #pragma unroll
    for (int mf=0;mf<2;mf++)
        #pragma unroll
        for (int nf=0;nf<8;nf++)
            #pragma unroll
            for (int t=0;t<4;t++) acc[mf][nf][t] = 0.f;

    loadStage(0);
    if (p.kC > 1) loadStage(1);

    const uint32_t aRel = (uint32_t)((warpM*32 + (lane&15))*ROWB + (lane>>4)*16);
    const uint32_t bRel = (uint32_t)(ASZ + (warpN*64 + (lane&7))*ROWB + ((lane>>3)&3)*16);

    for (int c = 0; c < p.kC; c++) {
        if (c+1 < p.kC) asm volatile("cp.async.wait_group 1;":::"memory");
        else            asm volatile("cp.async.wait_group 0;":::"memory");
        __syncthreads();
        if (c+2 < p.kC) loadStage(c+2);

        uint32_t st = TILE + (c%3)*STB;
        uint32_t aB = st + aRel, bB = st + bRel;
        #pragma unroll
        for (int kh=0; kh<2; kh++){
            uint32_t bfr[8][4];
            #pragma unroll
            for (int nf=0; nf<8; nf++) ldm4(bfr[nf], bB + nf*(8*ROWB) + kh*64);
            #pragma unroll
            for (int s=0; s<2; s++){
                int ks = kh*2 + s;
                uint32_t af[2][4];
                #pragma unroll
                for (int mf=0; mf<2; mf++) ldm4(af[mf], aB + mf*(16*ROWB) + ks*32);
                #pragma unroll
                for (int mf=0; mf<2; mf++)
                    #pragma unroll
                    for (int nf=0; nf<8; nf++)
                        mma16816(acc[mf][nf], af[mf], bfr[nf][s*2], bfr[nf][s*2+1]);
            }
        }
        // no trailing sync: next iteration's leading sync orders stage reuse
    }

    // epilogue: (d0,d1)=(cr,ci)@row r ; (d2,d3)@row r+8 ; complex pair = adjacent cols
    const long coff = (MODE!=5) ? ((z/p.zdiv)*p.sC1 + (z%p.zdiv)*p.sC2) : 0;
    const int em = (MODE == 5) ? (z == 0 ? 1 : (z == 1 ? 2 : 3)) : MODE;
    bf16* ob = p.Ob;
    if (MODE == 5) { if (z == 1) ob = p.Ob1; else if (z == 2) ob = p.Ob2; }
    const int ncBase = blockIdx.x*64 + warpN*32 + (lane&3);
    #pragma unroll
    for (int mf=0; mf<2; mf++){
        long r0 = (long)blockIdx.y*128 + warpM*32 + mf*16 + (lane>>2);
        #pragma unroll
        for (int nf=0; nf<8; nf++){
            int nc = ncBase + nf*4;
            float2 bb = bi ? bi[nc] : make_float2(0.f,0.f);
            #pragma unroll
            for (int h2=0; h2<2; h2++){
                long m = r0 + h2*8;
                float cr = acc[mf][nf][2*h2]   * p.scale + bb.x;
                float ci = acc[mf][nf][2*h2+1] * p.scale + bb.y;
                if (p.act){ float mg = sqrtf(cr*cr+ci*ci); cr = 0.5f*(cr+mg); ci = 0.5f*ci; }
                if (em == 0) {
                    p.C[coff + m*p.ldc + nc] = make_float2(cr, ci);
                } else if (em == 1) {            // Qa: per-head split-A [z][512][384]
                    int b=(int)(m>>9), s=(int)(m&511), hh=nc>>6, d=nc&63;
                    bf162 h,l; split2(cr, ci, h, l);
                    bf16* base = ob + ((long)(b*16+hh)*512 + s)*384 + 2*d;
                    *(bf162*)(base)=h; *(bf162*)(base+128)=l; *(bf162*)(base+256)=h;
                } else if (em == 4) {            // Hme: split-A [m][24576]
                    bf162 h,l; split2(cr, ci, h, l);
                    bf16* base = ob + m*24576 + 2*nc;
                    *(bf162*)(base)=h; *(bf162*)(base+8192)=l; *(bf162*)(base+16384)=h;
                } else {                         // 2: Kb, 3: Vb (split-B layouts)
                    int b=(int)(m>>9), s=(int)(m&511), hh=nc>>6, d=nc&63;
                    long zz = b*16 + hh;
                    bf162 h0,l0,h1,l1; split2(cr,-ci,h0,l0); split2(ci,cr,h1,l1);
                    if (em == 2) {
                        bf16* r0p = ob + (zz*1024 + 2*s)*384 + 2*d;
                        bf16* r1p = r0p + 384;
                        *(bf162*)(r0p)=h0; *(bf162*)(r0p+128)=h0; *(bf162*)(r0p+256)=l0;
                        *(bf162*)(r1p)=h1; *(bf162*)(r1p+128)=h1; *(bf162*)(r1p+256)=l1;
                    } else {
                        bf16* r0p = ob + (zz*128 + 2*d)*3072 + 2*s;
                        bf16* r1p = r0p + 3072;
                        *(bf162*)(r0p)=h0; *(bf162*)(r0p+1024)=h0; *(bf162*)(r0p+2048)=l0;
                        *(bf162*)(r1p)=h1; *(bf162*)(r1p+1024)=h1; *(bf162*)(r1p+2048)=l1;
                    }
                }
            }
        }
    }
}

// ---------------- merged expansions ----------------
// blocks [0,16384): query->Qe ; [16384,32768): x->Xe
__global__ __launch_bounds__(256) void expandAall(const float2* __restrict__ q,
                                                  const float2* __restrict__ x,
                                                  bf16* __restrict__ Qe, bf16* __restrict__ Xe)
{
    long bid = blockIdx.x;
    const float2* src = q; bf16* dst = Qe;
    if (bid >= 16384) { bid -= 16384; src = x; dst = Xe; }
    long idx = bid*256 + threadIdx.x;
    long m = idx >> 10; int k = (int)(idx & 1023);
    float2 v = src[idx];
    bf162 h,l; split2(v.x, v.y, h, l);
    bf16* b = dst + m*6144 + 2*k;
    *(bf162*)(b)=h; *(bf162*)(b+2048)=l; *(bf162*)(b+4096)=h;
}
// weights merged: ranges wq,wk,wv (K=1024, 4096 blocks each), wfc (K=1024, 16384), wpr (K=4096, 16384)
__global__ __launch_bounds__(256) void expandWall(
    const float2* __restrict__ wq, const float2* __restrict__ wk, const float2* __restrict__ wv,
    const float2* __restrict__ wfc, const float2* __restrict__ wpr,
    bf16* __restrict__ Wqe, bf16* __restrict__ Wke, bf16* __restrict__ Wve,
    bf16* __restrict__ Wfe, bf16* __restrict__ Wpe)
{
    long bid = blockIdx.x;
    const float2* W; bf16* out; int K;
    if      (bid < 4096)  { W=wq;  out=Wqe; K=1024; }
    else if (bid < 8192)  { W=wk;  out=Wke; K=1024; bid-=4096; }
    else if (bid < 12288) { W=wv;  out=Wve; K=1024; bid-=8192; }
    else if (bid < 28672) { W=wfc; out=Wfe; K=1024; bid-=12288; }
    else                  { W=wpr; out=Wpe; K=4096; bid-=28672; }
    long idx = bid*256 + threadIdx.x;
    long n = idx / K; int k = (int)(idx % K);
    float2 w = W[idx];
    bf162 h0,l0,h1,l1;
    split2(w.x, -w.y, h0, l0);
    split2(w.y,  w.x, h1, l1);
    long K2 = 2L*K;
    bf16* r0 = out + (2*n)*(3*K2) + 2*k;
    bf16* r1 = r0 + 3*K2;
    *(bf162*)(r0)=h0; *(bf162*)(r0+K2)=h0; *(bf162*)(r0+2*K2)=l0;
    *(bf162*)(r1)=h1; *(bf162*)(r1+K2)=h1; *(bf162*)(r1+2*K2)=l1;
}

// ---------------- softmax + probs expansion ----------------
__global__ __launch_bounds__(256) void softmax_kernel(const float2* __restrict__ Sc, bf16* __restrict__ Pa)
{
    long rid = (long)blockIdx.x*8 + (threadIdx.x>>5);
    int lane = threadIdx.x & 31;
    const float2* r = Sc + rid*512;
    float2 v[16]; float mx=-1e30f, my=-1e30f;
    #pragma unroll
    for (int i=0;i<16;i++){ v[i]=r[lane+32*i]; mx=fmaxf(mx,v[i].x); my=fmaxf(my,v[i].y); }
    #pragma unroll
    for (int o=16;o>0;o>>=1){ mx=fmaxf(mx,__shfl_xor_sync(~0u,mx,o)); my=fmaxf(my,__shfl_xor_sync(~0u,my,o)); }
    float sx=0.f, sy=0.f;
    #pragma unroll
    for (int i=0;i<16;i++){ v[i].x=__expf(v[i].x-mx); v[i].y=__expf(v[i].y-my); sx+=v[i].x; sy+=v[i].y; }
    #pragma unroll
    for (int o=16;o>0;o>>=1){ sx+=__shfl_xor_sync(~0u,sx,o); sy+=__shfl_xor_sync(~0u,sy,o); }
    float ix=1.f/sx, iy=1.f/sy;
    bf16* base = Pa + rid*3072;
    #pragma unroll
    for (int i=0;i<16;i++){
        int k = lane + 32*i;
        bf162 h,l; split2(v[i].x*ix, v[i].y*iy, h, l);
        *(bf162*)(base+2*k)=h; *(bf162*)(base+1024+2*k)=l; *(bf162*)(base+2048+2*k)=h;
    }
}

// ---------------- layernorms ----------------
__device__ __forceinline__ void reduce4(float& a, float& b, float& c, float& d, float* sh)
{
    #pragma unroll
    for (int o=16;o>0;o>>=1){
        a+=__shfl_xor_sync(~0u,a,o); b+=__shfl_xor_sync(~0u,b,o);
        c+=__shfl_xor_sync(~0u,c,o); d+=__shfl_xor_sync(~0u,d,o);
    }
    int w = threadIdx.x>>5;
    __syncthreads();
    if ((threadIdx.x&31)==0){ sh[w]=a; sh[8+w]=b; sh[16+w]=c; sh[24+w]=d; }
    __syncthreads();
    float ra=0,rb=0,rc=0,rd=0;
    #pragma unroll
    for (int i=0;i<8;i++){ ra+=sh[i]; rb+=sh[8+i]; rc+=sh[16+i]; rd+=sh[24+i]; }
    a=ra; b=rb; c=rc; d=rd;
}

__global__ __launch_bounds__(256)
void ln_attn_kernel(const float2* __restrict__ O, const float2* __restrict__ query,
                    const float2* __restrict__ x,
                    const float* __restrict__ g, const float* __restrict__ bta,
                    float2* __restrict__ X2, bf16* __restrict__ X2e)
{
    __shared__ float sh[32];
    const long base = (long)blockIdx.x*DD;
    const float inv = 1.f/DD;
    float2 v[4]; float sr=0,sq=0,si=0,qi=0;
    #pragma unroll
    for (int i=0;i<4;i++){
        int d = threadIdx.x + i*256;
        float2 o=O[base+d], q=query[base+d];
        v[i]=make_float2(o.x+q.x, o.y+q.y);
        sr+=v[i].x; sq+=v[i].x*v[i].x; si+=v[i].y; qi+=v[i].y*v[i].y;
    }
    reduce4(sr,sq,si,qi,sh);
    float mr=sr*inv, mi=si*inv;
    float rr=rsqrtf(sq*inv-mr*mr+LN_EPS), ri=rsqrtf(qi*inv-mi*mi+LN_EPS);
    float2 u[4]; float s2=0,q2=0,s3=0,q3=0;
    #pragma unroll
    for (int i=0;i<4;i++){
        int d = threadIdx.x + i*256;
        float tr=(v[i].x-mr)*rr*g[d]+bta[d];
        float ti=(v[i].y-mi)*ri*g[DD+d]+bta[DD+d];
        float2 xx=x[base+d];
        u[i]=make_float2(xx.x+tr, xx.y+ti);
        s2+=u[i].x; q2+=u[i].x*u[i].x; s3+=u[i].y; q3+=u[i].y*u[i].y;
    }
    reduce4(s2,q2,s3,q3,sh);
    float m2=s2*inv, m3=s3*inv;
    float r2=rsqrtf(q2*inv-m2*m2+LN_EPS), r3=rsqrtf(q3*inv-m3*m3+LN_EPS);
    const float *g1=g+2*DD, *b1=bta+2*DD;
    #pragma unroll
    for (int i=0;i<4;i++){
        int d = threadIdx.x + i*256;
        float yr=(u[i].x-m2)*r2*g1[d]+b1[d];
        float yi=(u[i].y-m3)*r3*g1[DD+d]+b1[DD+d];
        X2[base+d]=make_float2(yr, yi);
        bf162 h,l; split2(yr, yi, h, l);
        bf16* eb = X2e + (long)blockIdx.x*6144 + 2*d;
        *(bf162*)(eb)=h; *(bf162*)(eb+2048)=l; *(bf162*)(eb+4096)=h;
    }
}

// out = LN2(X2 + Mp0+Mp1+Mp2+Mp3 + bproj)
__global__ __launch_bounds__(256)
void ln_final_kernel(const float2* __restrict__ X2, const float2* __restrict__ Mp,
                     const float2* __restrict__ bpr,
                     const float* __restrict__ g, const float* __restrict__ bta,
                     float2* __restrict__ out)
{
    __shared__ float sh[32];
    const long base = (long)blockIdx.x*DD;
    const long S = (long)MR*DD;
    const float inv = 1.f/DD;
    float2 v[4]; float sr=0,sq=0,si=0,qi=0;
    #pragma unroll
    for (int i=0;i<4;i++){
        int d = threadIdx.x + i*256;
        float2 a=X2[base+d];
        float2 m0=Mp[base+d], m1=Mp[S+base+d], m2v=Mp[2*S+base+d], m3v=Mp[3*S+base+d];
        float2 bb=bpr[d];
        v[i]=make_float2(a.x+m0.x+m1.x+m2v.x+m3v.x+bb.x,
                         a.y+m0.y+m1.y+m2v.y+m3v.y+bb.y);
        sr+=v[i].x; sq+=v[i].x*v[i].x; si+=v[i].y; qi+=v[i].y*v[i].y;
    }
    reduce4(sr,sq,si,qi,sh);
    float mr=sr*inv, mi=si*inv;
    float rr=rsqrtf(sq*inv-mr*mr+LN_EPS), ri=rsqrtf(qi*inv-mi*mi+LN_EPS);
    const float *g2=g+4*DD, *b2=bta+4*DD;
    #pragma unroll
    for (int i=0;i<4;i++){
        int d = threadIdx.x + i*256;
        out[base+d]=make_float2((v[i].x-mr)*rr*g2[d]+b2[d], (v[i].y-mi)*ri*g2[DD+d]+b2[DD+d]);
    }
}

// ---------------- host ----------------
static GP mkgp(const bf16* A, long lda, const bf16* B, long ldb, int kC,
               float2* C, long ldc, bf16* Ob,
               const float2* bias, float scale, int act,
               int zdiv=1, long sA1=0,long sA2=0,long sB1=0,long sB2=0,long sC1=0,long sC2=0)
{
    GP p = {};
    p.A=A; p.B=B; p.lda=lda; p.ldb=ldb; p.kC=kC;
    p.C=C; p.ldc=ldc; p.Ob=Ob; p.bias=bias; p.scale=scale; p.act=act; p.zdiv=zdiv;
    p.sA1=sA1; p.sA2=sA2; p.sB1=sB1; p.sB2=sB2; p.sC1=sC1; p.sC2=sC2;
    return p;
}

extern "C" void kernel_launch(void* const* d_in, const int* in_sizes, int n_in,
                              void* d_out, int out_size)
{
    const float2* x     = (const float2*)d_in[0];
    const float2* query = (const float2*)d_in[1];
    const float2* wq    = (const float2*)d_in[2];
    const float2* bq    = (const float2*)d_in[3];
    const float2* wk    = (const float2*)d_in[4];
    const float2* bk    = (const float2*)d_in[5];
    const float2* wv    = (const float2*)d_in[6];
    const float2* bv    = (const float2*)d_in[7];
    const float2* wfc   = (const float2*)d_in[8];
    const float2* bfc   = (const float2*)d_in[9];
    const float2* wpr   = (const float2*)d_in[10];
    const float2* bpr   = (const float2*)d_in[11];
    const float*  lng   = (const float*)d_in[12];
    const float*  lnb   = (const float*)d_in[13];

    bf16 *Qe,*Xe,*X2e,*Hme,*Wqe,*Wke,*Wve,*Wfe,*Wpe,*Qa,*Kb,*Vb,*Pa;
    float2 *O,*X2,*Mp,*Sc;
    cudaGetSymbolAddress((void**)&Qe,g_Qe);   cudaGetSymbolAddress((void**)&Xe,g_Xe);
    cudaGetSymbolAddress((void**)&X2e,g_X2e); cudaGetSymbolAddress((void**)&Hme,g_Hme);
    cudaGetSymbolAddress((void**)&Wqe,g_Wqe); cudaGetSymbolAddress((void**)&Wke,g_Wke);
    cudaGetSymbolAddress((void**)&Wve,g_Wve); cudaGetSymbolAddress((void**)&Wfe,g_Wfe);
    cudaGetSymbolAddress((void**)&Wpe,g_Wpe); cudaGetSymbolAddress((void**)&Qa,g_Qa);
    cudaGetSymbolAddress((void**)&Kb,g_Kb);   cudaGetSymbolAddress((void**)&Vb,g_Vb);
    cudaGetSymbolAddress((void**)&Pa,g_Pa);
    cudaGetSymbolAddress((void**)&O,g_O);   cudaGetSymbolAddress((void**)&X2,g_X2);
    cudaGetSymbolAddress((void**)&Mp,g_Mp); cudaGetSymbolAddress((void**)&Sc,g_Sc);

    cudaFuncSetAttribute(tgemm<0>, cudaFuncAttributeMaxDynamicSharedMemorySize, SMB);
    cudaFuncSetAttribute(tgemm<4>, cudaFuncAttributeMaxDynamicSharedMemorySize, SMB);
    cudaFuncSetAttribute(tgemm<5>, cudaFuncAttributeMaxDynamicSharedMemorySize, SMB);

    // expansions (2 launches)
    expandAall<<<32768,256>>>(query, x, Qe, Xe);
    expandWall<<<45056,256>>>(wq, wk, wv, wfc, wpr, Wqe, Wke, Wve, Wfe, Wpe);

    // QKV fused: grid (16,32,3); z=0:Q→Qa, z=1:K→Kb, z=2:V→Vb; K_eff=6144 (kC=96)
    {
        GP p = mkgp(Qe,6144, Wqe,6144, 96, nullptr,0, Qa, bq,1.f,0);
        p.A2 = Xe; p.B1 = Wke; p.B2 = Wve;
        p.Ob1 = Kb; p.Ob2 = Vb;
        p.bias1 = bk; p.bias2 = bv;
        tgemm<5><<<dim3(16,32,3),256,SMB>>>(p);
    }

    // scores: per z=(b,h): [512 x 1024'], K_eff=384 (kC=6)
    {
        dim3 grd(8, 4, 128);
        tgemm<0><<<grd,256,SMB>>>(mkgp(Qa,384, Kb,384, 6, Sc,512, nullptr, nullptr,0.125f,0,
            1, 512L*384,0, 1024L*384,0, 512L*512,0));
    }
    softmax_kernel<<<128*512/8,256>>>(Sc, Pa);

    // AV: per z: [512 x 128'], K_eff=3072 (kC=48)   <-- ncu -s 5 lands here
    {
        dim3 grd(1, 4, 128);
        tgemm<0><<<grd,256,SMB>>>(mkgp(Pa,3072, Vb,3072, 48, O,1024, nullptr, nullptr,1.f,0,
            16, 16L*512*3072, 512L*3072, 16L*128*3072, 128L*3072, 512L*1024, 64));
    }
    ln_attn_kernel<<<MR,256>>>(O, query, x, lng, lnb, X2, X2e);

    // fc: [4096 x 8192'], K_eff=6144 (kC=96), bias+modReLU, writes Hme split-A directly
    tgemm<4><<<dim3(64,32,1),256,SMB>>>(mkgp(X2e,6144, Wfe,6144, 96, nullptr,0, Hme, bfc,1.f,1));

    // proj split-K x4: grid (16,32,4); z = K-quarter -> partial Mp[z]; bias folded into ln_final
    tgemm<0><<<dim3(16,32,4),256,SMB>>>(mkgp(Hme,24576, Wpe,24576, 96, Mp,1024, nullptr, nullptr,1.f,0,
        4, 0, 6144, 0, 6144, 0, (long)MR*DD));

    ln_final_kernel<<<MR,256>>>(X2, Mp, bpr, lng, lnb, (float2*)d_out);
}

// round 10
// speedup vs baseline: 3.5577x; 1.1890x over previous
#include <cuda_runtime.h>
#include <cuda_bf16.h>
#include <cstdint>
#include <math.h>

typedef __nv_bfloat16 bf16;
typedef __nv_bfloat162 bf162;

#define DD 1024
#define MR 4096
#define LN_EPS 1e-5f

// ---------------- pooled scratch (single symbol, lifetime-aliased) ----------------
// Gauss operand layouts (bf16):
//  A-side: per comp c in {r,i,s=r+i}, width 3K: [h(K)|l(K)|h(K)]
//  B-side: per comp, width 3K: [h(K)|h(K)|l(K)]
constexpr size_t O_QG   = 0;
constexpr size_t O_XG   = O_QG  + (size_t)MR*9216*2;
constexpr size_t O_X2G  = O_XG  + (size_t)MR*9216*2;
constexpr size_t O_WQKV = O_X2G + (size_t)MR*9216*2;
constexpr size_t O_WFCG = O_WQKV + (size_t)3*1024*9216*2;
constexpr size_t O_WPG  = O_WFCG + (size_t)4096*9216*2;
constexpr size_t O_QA   = O_WPG  + (size_t)1024*36864*2;
constexpr size_t O_KB   = O_QA   + (size_t)128*512*384*2;
constexpr size_t O_VB   = O_KB   + (size_t)128*1024*384*2;
constexpr size_t O_PA   = O_VB   + (size_t)128*128*3072*2;
constexpr size_t O_OO   = O_PA   + (size_t)128*512*3072*2;
constexpr size_t O_X2   = O_OO   + (size_t)MR*DD*8;
constexpr size_t O_HMG  = O_X2   + (size_t)MR*DD*8;
constexpr size_t O_SC   = O_HMG  + (size_t)MR*36864*2;
constexpr size_t POOLSZ = O_SC   + (size_t)128*512*512*8;   // 1,725,956,096 B
// aliases (disjoint lifetimes in launch order):
constexpr size_t O_PQ  = O_HMG;  // Pq  (144MB) dead after cqkv;   Hmg written at cfc
constexpr size_t O_PFC = O_SC;   // Pfc (192MB) written at fc;     Sc dead after softmax
constexpr size_t O_PP  = O_PA;   // Pp  ( 96MB) written at proj;   Pa dead after AV

__device__ __align__(256) char g_pool[POOLSZ];

// ---------------- helpers ----------------
__device__ __forceinline__ uint32_t s2u(const void* p){
    uint32_t a;
    asm("{ .reg .u64 t; cvta.to.shared.u64 t, %1; cvt.u32.u64 %0, t; }":"=r"(a):"l"(p));
    return a;
}
__device__ __forceinline__ void cpa16(uint32_t d, const void* g){
    asm volatile("cp.async.cg.shared.global [%0], [%1], 16;"::"r"(d),"l"(g));
}
__device__ __forceinline__ void split1(float v, bf16& h, bf16& l){
    h = __float2bfloat16_rn(v);
    l = __float2bfloat16_rn(v - __bfloat162float(h));
}
__device__ __forceinline__ void split2(float vr, float vi, bf162& h, bf162& l){
    split1(vr, h.x, l.x); split1(vi, h.y, l.y);
}
__device__ __forceinline__ void ldm4(uint32_t* r, uint32_t a){
    asm volatile("ldmatrix.sync.aligned.m8n8.x4.shared.b16 {%0,%1,%2,%3}, [%4];"
        :"=r"(r[0]),"=r"(r[1]),"=r"(r[2]),"=r"(r[3]):"r"(a));
}
__device__ __forceinline__ void mma16816(float* d, const uint32_t* a, uint32_t b0, uint32_t b1){
    asm volatile("mma.sync.aligned.m16n8k16.row.col.f32.bf16.bf16.f32 "
        "{%0,%1,%2,%3}, {%4,%5,%6,%7}, {%8,%9}, {%0,%1,%2,%3};"
        :"+f"(d[0]),"+f"(d[1]),"+f"(d[2]),"+f"(d[3])
        :"r"(a[0]),"r"(a[1]),"r"(a[2]),"r"(a[3]),"r"(b0),"r"(b1));
}

// ---------------- GEMM via mma.sync ----------------
// BM=128, BN=128, BK=64; 8 warps (4M x 2N); 3-stage cp.async; 1 sync/chunk; 2 CTAs/SM.
// MODE 0: attention GEMM, float2 C (complex pairs), optional bias/scale.
// MODE 6: Gauss product GEMM, fp32 real C via float2 pair stores; A = (z<3 ? A : A2).
struct GP {
    const bf16 *A, *A2, *B;
    long lda, ldb;
    long sA1, sA2, sB1, sB2;
    float2* C; long ldc, sC1, sC2;
    const float2* bias;
    int zdiv, kC;
    float scale;
};
#define ROWB 144            // 64 bf16 = 128B data + 16B pad
#define ASZ  (128*ROWB)
#define STB  (2*ASZ)
#define SMB  (3*STB)        // 110592

template<int MODE>
__global__ __launch_bounds__(256,2) void tgemm(GP p)
{
    extern __shared__ __align__(256) char sm[];
    uint32_t TILE = s2u(sm);
    const int tid = threadIdx.x, lane = tid & 31, wid = tid >> 5;
    const int warpM = wid & 3, warpN = wid >> 2;

    const int z = blockIdx.z;
    const bf16* Ap = (MODE == 6 && z >= 3) ? p.A2 : p.A;
    const long offA = (z/p.zdiv)*p.sA1 + (z%p.zdiv)*p.sA2;
    const long offB = (z/p.zdiv)*p.sB1 + (z%p.zdiv)*p.sB2;
    const bf16* Ag = Ap + offA + (long)blockIdx.y*128*p.lda;
    const bf16* Bg = p.B + offB + (long)blockIdx.x*128*p.ldb;

    auto loadStage = [&](int c){
        uint32_t st = TILE + (c%3)*STB;
        long kof = (long)c*64;
        #pragma unroll
        for (int i=0;i<4;i++){
            int idx = tid + i*256; int r = idx>>3, cc = idx&7;
            cpa16(st + r*ROWB + cc*16, Ag + (long)r*p.lda + kof + cc*8);
        }
        #pragma unroll
        for (int i=0;i<4;i++){
            int idx = tid + i*256; int r = idx>>3, cc = idx&7;
            cpa16(st + ASZ + r*ROWB + cc*16, Bg + (long)r*p.ldb + kof + cc*8);
        }
        asm volatile("cp.async.commit_group;":::"memory");
    };

    float acc[2][8][4];
    #pragma unroll
    for (int mf=0;mf<2;mf++)
        #pragma unroll
        for (int nf=0;nf<8;nf++)
            #pragma unroll
            for (int t=0;t<4;t++) acc[mf][nf][t] = 0.f;

    loadStage(0);
    if (p.kC > 1) loadStage(1);

    const uint32_t aRel = (uint32_t)((warpM*32 + (lane&15))*ROWB + (lane>>4)*16);
    const uint32_t bRel = (uint32_t)(ASZ + (warpN*64 + (lane&7))*ROWB + ((lane>>3)&3)*16);

    for (int c = 0; c < p.kC; c++) {
        if (c+1 < p.kC) asm volatile("cp.async.wait_group 1;":::"memory");
        else            asm volatile("cp.async.wait_group 0;":::"memory");
        __syncthreads();
        if (c+2 < p.kC) loadStage(c+2);

        uint32_t st = TILE + (c%3)*STB;
        uint32_t aB = st + aRel, bB = st + bRel;
        #pragma unroll
        for (int kh=0; kh<2; kh++){
            uint32_t bfr[8][4];
            #pragma unroll
            for (int nf=0; nf<8; nf++) ldm4(bfr[nf], bB + nf*(8*ROWB) + kh*64);
            #pragma unroll
            for (int s=0; s<2; s++){
                int ks = kh*2 + s;
                uint32_t af[2][4];
                #pragma unroll
                for (int mf=0; mf<2; mf++) ldm4(af[mf], aB + mf*(16*ROWB) + ks*32);
                #pragma unroll
                for (int mf=0; mf<2; mf++)
                    #pragma unroll
                    for (int nf=0; nf<8; nf++)
                        mma16816(acc[mf][nf], af[mf], bfr[nf][s*2], bfr[nf][s*2+1]);
            }
        }
    }

    // epilogue: d0,d1 = adjacent cols @ row r; d2,d3 @ row r+8.
    const long coff = (z/p.zdiv)*p.sC1 + (z%p.zdiv)*p.sC2;
    const int ncBase = blockIdx.x*64 + warpN*32 + (lane&3);
    #pragma unroll
    for (int mf=0; mf<2; mf++){
        long r0 = (long)blockIdx.y*128 + warpM*32 + mf*16 + (lane>>2);
        #pragma unroll
        for (int nf=0; nf<8; nf++){
            int nc = ncBase + nf*4;
            float2 bb = (MODE==0 && p.bias) ? p.bias[nc] : make_float2(0.f,0.f);
            #pragma unroll
            for (int h2=0; h2<2; h2++){
                long m = r0 + h2*8;
                float cr = acc[mf][nf][2*h2]   * p.scale + bb.x;
                float ci = acc[mf][nf][2*h2+1] * p.scale + bb.y;
                p.C[coff + m*p.ldc + nc] = make_float2(cr, ci);
            }
        }
    }
}

// ---------------- expansions (Gauss layouts) ----------------
__global__ __launch_bounds__(256) void expandAG(const float2* __restrict__ q,
                                                const float2* __restrict__ x,
                                                bf16* __restrict__ Qg, bf16* __restrict__ Xg)
{
    long bid = blockIdx.x;
    const float2* src = q; bf16* dst = Qg;
    if (bid >= 16384) { bid -= 16384; src = x; dst = Xg; }
    long idx = bid*256 + threadIdx.x;
    long m = idx >> 10; int k = (int)(idx & 1023);
    float2 v = src[idx];
    float comp[3] = { v.x, v.y, v.x + v.y };
    bf16* base = dst + m*9216 + k;
    #pragma unroll
    for (int c=0;c<3;c++){
        bf16 h,l; split1(comp[c], h, l);
        bf16* b = base + c*3072;
        b[0]=h; b[1024]=l; b[2048]=h;
    }
}
__global__ __launch_bounds__(256) void expandWG(
    const float2* __restrict__ wq, const float2* __restrict__ wk, const float2* __restrict__ wv,
    const float2* __restrict__ wfc, const float2* __restrict__ wpr,
    bf16* __restrict__ Wqkv, bf16* __restrict__ Wfcg, bf16* __restrict__ Wpg)
{
    long bid = blockIdx.x;
    const float2* W; bf16* out; int K; long rstride;
    if      (bid < 4096)  { W=wq;  out=Wqkv;                    K=1024; rstride=9216; }
    else if (bid < 8192)  { W=wk;  out=Wqkv+(size_t)1024*9216;  K=1024; rstride=9216; bid-=4096; }
    else if (bid < 12288) { W=wv;  out=Wqkv+(size_t)2048*9216;  K=1024; rstride=9216; bid-=8192; }
    else if (bid < 28672) { W=wfc; out=Wfcg;                    K=1024; rstride=9216; bid-=12288; }
    else                  { W=wpr; out=Wpg;                     K=4096; rstride=36864; bid-=28672; }
    long idx = bid*256 + threadIdx.x;
    long n = idx / K; int k = (int)(idx % K);
    float2 w = W[idx];
    float comp[3] = { w.x, w.y, w.x + w.y };
    bf16* base = out + n*rstride + k;
    #pragma unroll
    for (int c=0;c<3;c++){
        bf16 h,l; split1(comp[c], h, l);
        bf16* b = base + (long)c*3*K;
        b[0]=h; b[K]=h; b[2*K]=l;
    }
}

// ---------------- QKV combine: Pq -> Qa / Kb / Vb ----------------
__global__ __launch_bounds__(256) void cqkv(const float* __restrict__ Pq,
                                            const float2* __restrict__ bq,
                                            const float2* __restrict__ bk,
                                            const float2* __restrict__ bv,
                                            bf16* __restrict__ Qa, bf16* __restrict__ Kb,
                                            bf16* __restrict__ Vb)
{
    long bid = blockIdx.x;
    int q3 = (int)(bid / 16384); bid -= (long)q3*16384;
    long idx = bid*256 + threadIdx.x;
    long m = idx >> 10; int n = (int)(idx & 1023);
    const long MN = (long)MR*1024;
    const float* P = Pq + (long)q3*3*MN;
    float p0 = P[idx], p1 = P[MN+idx], p2 = P[2*MN+idx];
    const float2* bi = (q3==0) ? bq : (q3==1 ? bk : bv);
    float2 bb = bi[n];
    float yr = p0 - p1 + bb.x;
    float yi = p2 - p0 - p1 + bb.y;
    int b=(int)(m>>9), s=(int)(m&511), hh=n>>6, d=n&63;
    long zz = b*16 + hh;
    if (q3 == 0) {
        bf162 h,l; split2(yr, yi, h, l);
        bf16* base = Qa + (zz*512 + s)*384 + 2*d;
        *(bf162*)(base)=h; *(bf162*)(base+128)=l; *(bf162*)(base+256)=h;
    } else {
        bf162 h0,l0,h1,l1; split2(yr,-yi,h0,l0); split2(yi,yr,h1,l1);
        if (q3 == 1) {
            bf16* r0p = Kb + (zz*1024 + 2*s)*384 + 2*d;
            bf16* r1p = r0p + 384;
            *(bf162*)(r0p)=h0; *(bf162*)(r0p+128)=h0; *(bf162*)(r0p+256)=l0;
            *(bf162*)(r1p)=h1; *(bf162*)(r1p+128)=h1; *(bf162*)(r1p+256)=l1;
        } else {
            bf16* r0p = Vb + (zz*128 + 2*d)*3072 + 2*s;
            bf16* r1p = r0p + 3072;
            *(bf162*)(r0p)=h0; *(bf162*)(r0p+1024)=h0; *(bf162*)(r0p+2048)=l0;
            *(bf162*)(r1p)=h1; *(bf162*)(r1p+1024)=h1; *(bf162*)(r1p+2048)=l1;
        }
    }
}

// ---------------- fc combine: Pfc -> modReLU -> Hmg (Gauss A layout, K=4096) ----------------
__global__ __launch_bounds__(256) void cfc(const float* __restrict__ Pfc,
                                           const float2* __restrict__ bfc,
                                           bf16* __restrict__ Hmg)
{
    long idx = (long)blockIdx.x*256 + threadIdx.x;
    long m = idx >> 12; int n = (int)(idx & 4095);
    const long MN = (long)MR*4096;
    float p0 = Pfc[idx], p1 = Pfc[MN+idx], p2 = Pfc[2*MN+idx];
    float2 bb = bfc[n];
    float yr = p0 - p1 + bb.x;
    float yi = p2 - p0 - p1 + bb.y;
    float mg = sqrtf(yr*yr + yi*yi);
    yr = 0.5f*(yr + mg); yi = 0.5f*yi;
    float comp[3] = { yr, yi, yr + yi };
    bf16* base = Hmg + m*36864 + n;
    #pragma unroll
    for (int c=0;c<3;c++){
        bf16 h,l; split1(comp[c], h, l);
        bf16* b = base + c*12288;
        b[0]=h; b[4096]=l; b[8192]=h;
    }
}

// ---------------- softmax + probs expansion ----------------
__global__ __launch_bounds__(256) void softmax_kernel(const float2* __restrict__ Sc, bf16* __restrict__ Pa)
{
    long rid = (long)blockIdx.x*8 + (threadIdx.x>>5);
    int lane = threadIdx.x & 31;
    const float2* r = Sc + rid*512;
    float2 v[16]; float mx=-1e30f, my=-1e30f;
    #pragma unroll
    for (int i=0;i<16;i++){ v[i]=r[lane+32*i]; mx=fmaxf(mx,v[i].x); my=fmaxf(my,v[i].y); }
    #pragma unroll
    for (int o=16;o>0;o>>=1){ mx=fmaxf(mx,__shfl_xor_sync(~0u,mx,o)); my=fmaxf(my,__shfl_xor_sync(~0u,my,o)); }
    float sx=0.f, sy=0.f;
    #pragma unroll
    for (int i=0;i<16;i++){ v[i].x=__expf(v[i].x-mx); v[i].y=__expf(v[i].y-my); sx+=v[i].x; sy+=v[i].y; }
    #pragma unroll
    for (int o=16;o>0;o>>=1){ sx+=__shfl_xor_sync(~0u,sx,o); sy+=__shfl_xor_sync(~0u,sy,o); }
    float ix=1.f/sx, iy=1.f/sy;
    bf16* base = Pa + rid*3072;
    #pragma unroll
    for (int i=0;i<16;i++){
        int k = lane + 32*i;
        bf162 h,l; split2(v[i].x*ix, v[i].y*iy, h, l);
        *(bf162*)(base+2*k)=h; *(bf162*)(base+1024+2*k)=l; *(bf162*)(base+2048+2*k)=h;
    }
}

// ---------------- layernorms ----------------
__device__ __forceinline__ void reduce4(float& a, float& b, float& c, float& d, float* sh)
{
    #pragma unroll
    for (int o=16;o>0;o>>=1){
        a+=__shfl_xor_sync(~0u,a,o); b+=__shfl_xor_sync(~0u,b,o);
        c+=__shfl_xor_sync(~0u,c,o); d+=__shfl_xor_sync(~0u,d,o);
    }
    int w = threadIdx.x>>5;
    __syncthreads();
    if ((threadIdx.x&31)==0){ sh[w]=a; sh[8+w]=b; sh[16+w]=c; sh[24+w]=d; }
    __syncthreads();
    float ra=0,rb=0,rc=0,rd=0;
    #pragma unroll
    for (int i=0;i<8;i++){ ra+=sh[i]; rb+=sh[8+i]; rc+=sh[16+i]; rd+=sh[24+i]; }
    a=ra; b=rb; c=rc; d=rd;
}

__global__ __launch_bounds__(256)
void ln_attn_kernel(const float2* __restrict__ O, const float2* __restrict__ query,
                    const float2* __restrict__ x,
                    const float* __restrict__ g, const float* __restrict__ bta,
                    float2* __restrict__ X2, bf16* __restrict__ X2g)
{
    __shared__ float sh[32];
    const long base = (long)blockIdx.x*DD;
    const float inv = 1.f/DD;
    float2 v[4]; float sr=0,sq=0,si=0,qi=0;
    #pragma unroll
    for (int i=0;i<4;i++){
        int d = threadIdx.x + i*256;
        float2 o=O[base+d], q=query[base+d];
        v[i]=make_float2(o.x+q.x, o.y+q.y);
        sr+=v[i].x; sq+=v[i].x*v[i].x; si+=v[i].y; qi+=v[i].y*v[i].y;
    }
    reduce4(sr,sq,si,qi,sh);
    float mr=sr*inv, mi=si*inv;
    float rr=rsqrtf(sq*inv-mr*mr+LN_EPS), ri=rsqrtf(qi*inv-mi*mi+LN_EPS);
    float2 u[4]; float s2=0,q2=0,s3=0,q3=0;
    #pragma unroll
    for (int i=0;i<4;i++){
        int d = threadIdx.x + i*256;
        float tr=(v[i].x-mr)*rr*g[d]+bta[d];
        float ti=(v[i].y-mi)*ri*g[DD+d]+bta[DD+d];
        float2 xx=x[base+d];
        u[i]=make_float2(xx.x+tr, xx.y+ti);
        s2+=u[i].x; q2+=u[i].x*u[i].x; s3+=u[i].y; q3+=u[i].y*u[i].y;
    }
    reduce4(s2,q2,s3,q3,sh);
    float m2=s2*inv, m3=s3*inv;
    float r2=rsqrtf(q2*inv-m2*m2+LN_EPS), r3=rsqrtf(q3*inv-m3*m3+LN_EPS);
    const float *g1=g+2*DD, *b1=bta+2*DD;
    #pragma unroll
    for (int i=0;i<4;i++){
        int d = threadIdx.x + i*256;
        float yr=(u[i].x-m2)*r2*g1[d]+b1[d];
        float yi=(u[i].y-m3)*r3*g1[DD+d]+b1[DD+d];
        X2[base+d]=make_float2(yr, yi);
        float comp[3] = { yr, yi, yr + yi };
        bf16* eb = X2g + (long)blockIdx.x*9216 + d;
        #pragma unroll
        for (int c=0;c<3;c++){
            bf16 h,l; split1(comp[c], h, l);
            bf16* b = eb + c*3072;
            b[0]=h; b[1024]=l; b[2048]=h;
        }
    }
}

// out = LN2(X2 + proj), proj = Gauss-combined from 6 partials (3 products x 2 split-K) + bias
__global__ __launch_bounds__(256)
void ln_final_kernel(const float2* __restrict__ X2, const float* __restrict__ Pp,
                     const float2* __restrict__ bpr,
                     const float* __restrict__ g, const float* __restrict__ bta,
                     float2* __restrict__ out)
{
    __shared__ float sh[32];
    const long base = (long)blockIdx.x*DD;
    const long S = (long)MR*1024;
    const float inv = 1.f/DD;
    float2 v[4]; float sr=0,sq=0,si=0,qi=0;
    #pragma unroll
    for (int i=0;i<4;i++){
        int d = threadIdx.x + i*256;
        long fi = base + d;
        float P1 = Pp[fi] + Pp[S+fi];
        float P2 = Pp[2*S+fi] + Pp[3*S+fi];
        float P3 = Pp[4*S+fi] + Pp[5*S+fi];
        float2 a = X2[fi]; float2 bb = bpr[d];
        v[i] = make_float2(a.x + (P1 - P2) + bb.x,
                           a.y + (P3 - P1 - P2) + bb.y);
        sr+=v[i].x; sq+=v[i].x*v[i].x; si+=v[i].y; qi+=v[i].y*v[i].y;
    }
    reduce4(sr,sq,si,qi,sh);
    float mr=sr*inv, mi=si*inv;
    float rr=rsqrtf(sq*inv-mr*mr+LN_EPS), ri=rsqrtf(qi*inv-mi*mi+LN_EPS);
    const float *g2=g+4*DD, *b2=bta+4*DD;
    #pragma unroll
    for (int i=0;i<4;i++){
        int d = threadIdx.x + i*256;
        out[base+d]=make_float2((v[i].x-mr)*rr*g2[d]+b2[d], (v[i].y-mi)*ri*g2[DD+d]+b2[DD+d]);
    }
}

// ---------------- host ----------------
static GP mkgp(const bf16* A, const bf16* A2, long lda, const bf16* B, long ldb, int kC,
               float2* C, long ldc, const float2* bias, float scale,
               int zdiv, long sA1, long sA2, long sB1, long sB2, long sC1, long sC2)
{
    GP p = {};
    p.A=A; p.A2=A2; p.B=B; p.lda=lda; p.ldb=ldb; p.kC=kC;
    p.C=C; p.ldc=ldc; p.bias=bias; p.scale=scale; p.zdiv=zdiv;
    p.sA1=sA1; p.sA2=sA2; p.sB1=sB1; p.sB2=sB2; p.sC1=sC1; p.sC2=sC2;
    return p;
}

extern "C" void kernel_launch(void* const* d_in, const int* in_sizes, int n_in,
                              void* d_out, int out_size)
{
    const float2* x     = (const float2*)d_in[0];
    const float2* query = (const float2*)d_in[1];
    const float2* wq    = (const float2*)d_in[2];
    const float2* bq    = (const float2*)d_in[3];
    const float2* wk    = (const float2*)d_in[4];
    const float2* bk    = (const float2*)d_in[5];
    const float2* wv    = (const float2*)d_in[6];
    const float2* bv    = (const float2*)d_in[7];
    const float2* wfc   = (const float2*)d_in[8];
    const float2* bfc   = (const float2*)d_in[9];
    const float2* wpr   = (const float2*)d_in[10];
    const float2* bpr   = (const float2*)d_in[11];
    const float*  lng   = (const float*)d_in[12];
    const float*  lnb   = (const float*)d_in[13];

    char* pool;
    cudaGetSymbolAddress((void**)&pool, g_pool);
    bf16 *Qg   = (bf16*)(pool + O_QG),   *Xg   = (bf16*)(pool + O_XG);
    bf16 *X2g  = (bf16*)(pool + O_X2G),  *Hmg  = (bf16*)(pool + O_HMG);
    bf16 *Wqkv = (bf16*)(pool + O_WQKV), *Wfcg = (bf16*)(pool + O_WFCG);
    bf16 *Wpg  = (bf16*)(pool + O_WPG);
    bf16 *Qa   = (bf16*)(pool + O_QA),   *Kb   = (bf16*)(pool + O_KB);
    bf16 *Vb   = (bf16*)(pool + O_VB),   *Pa   = (bf16*)(pool + O_PA);
    float *Pq  = (float*)(pool + O_PQ),  *Pfc  = (float*)(pool + O_PFC);
    float *Pp  = (float*)(pool + O_PP);
    float2 *O  = (float2*)(pool + O_OO), *X2   = (float2*)(pool + O_X2);
    float2 *Sc = (float2*)(pool + O_SC);

    cudaFuncSetAttribute(tgemm<0>, cudaFuncAttributeMaxDynamicSharedMemorySize, SMB);
    cudaFuncSetAttribute(tgemm<6>, cudaFuncAttributeMaxDynamicSharedMemorySize, SMB);

    // expansions
    expandAG<<<32768,256>>>(query, x, Qg, Xg);
    expandWG<<<45056,256>>>(wq, wk, wv, wfc, wpr, Wqkv, Wfcg, Wpg);

    // QKV Gauss: grid (8,32,9); z = inp*3 + product; z<3 uses Qg else Xg. kC=48.
    tgemm<6><<<dim3(8,32,9),256,SMB>>>(mkgp(Qg, Xg, 9216, Wqkv, 9216, 48,
        (float2*)Pq, 512, nullptr, 1.f,
        3, 0, 3072, (long)1024*9216, 3072, 3L*MR*512, (long)MR*512));
    cqkv<<<49152,256>>>(Pq, bq, bk, bv, Qa, Kb, Vb);

    // scores: per z=(b,h): [512 x 1024'], K_eff=384 (kC=6)
    tgemm<0><<<dim3(8,4,128),256,SMB>>>(mkgp(Qa, Qa, 384, Kb, 384, 6,
        Sc, 512, nullptr, 0.125f,
        1, 512L*384, 0, 1024L*384, 0, 512L*512, 0));
    softmax_kernel<<<128*512/8,256>>>(Sc, Pa);

    // AV: per z: [512 x 128'], K_eff=3072 (kC=48)
    tgemm<0><<<dim3(1,4,128),256,SMB>>>(mkgp(Pa, Pa, 3072, Vb, 3072, 48,
        O, 1024, nullptr, 1.f,
        16, 16L*512*3072, 512L*3072, 16L*128*3072, 128L*3072, 512L*1024, 64));

    ln_attn_kernel<<<MR,256>>>(O, query, x, lng, lnb, X2, X2g);

    // fc Gauss: grid (32,32,3); z = product. kC=48.
    tgemm<6><<<dim3(32,32,3),256,SMB>>>(mkgp(X2g, X2g, 9216, Wfcg, 9216, 48,
        (float2*)Pfc, 2048, nullptr, 1.f,
        3, 0, 3072, 0, 3072, 0, (long)MR*2048));
    cfc<<<65536,256>>>(Pfc, bfc, Hmg);

    // proj Gauss + split-K x2: grid (8,32,6); z = product*2 + khalf. kC=96.
    tgemm<6><<<dim3(8,32,6),256,SMB>>>(mkgp(Hmg, Hmg, 36864, Wpg, 36864, 96,
        (float2*)Pp, 512, nullptr, 1.f,
        2, 12288, 6144, 12288, 6144, 2L*MR*512, (long)MR*512));

    ln_final_kernel<<<MR,256>>>(X2, Pp, bpr, lng, lnb, (float2*)d_out);
}

// round 12
// speedup vs baseline: 3.5785x; 1.0059x over previous
#include <cuda_runtime.h>
#include <cuda_bf16.h>
#include <cstdint>
#include <math.h>

typedef __nv_bfloat16 bf16;
typedef __nv_bfloat162 bf162;

#define DD 1024
#define MR 4096
#define LN_EPS 1e-5f

// ---------------- pooled scratch (single symbol, lifetime-aliased) ----------------
constexpr size_t O_QG   = 0;
constexpr size_t O_XG   = O_QG  + (size_t)MR*9216*2;
constexpr size_t O_X2G  = O_XG  + (size_t)MR*9216*2;
constexpr size_t O_WQKV = O_X2G + (size_t)MR*9216*2;
constexpr size_t O_WFCG = O_WQKV + (size_t)3*1024*9216*2;
constexpr size_t O_WPG  = O_WFCG + (size_t)4096*9216*2;
constexpr size_t O_QA   = O_WPG  + (size_t)1024*36864*2;
constexpr size_t O_KB   = O_QA   + (size_t)128*512*384*2;
constexpr size_t O_VB   = O_KB   + (size_t)128*1024*384*2;
constexpr size_t O_PA   = O_VB   + (size_t)128*128*3072*2;
constexpr size_t O_OO   = O_PA   + (size_t)128*512*3072*2;
constexpr size_t O_X2   = O_OO   + (size_t)MR*DD*8;
constexpr size_t O_HMG  = O_X2   + (size_t)MR*DD*8;
constexpr size_t O_SC   = O_HMG  + (size_t)MR*36864*2;
constexpr size_t POOLSZ = O_SC   + (size_t)128*512*512*8;
// aliases (disjoint lifetimes in launch order):
constexpr size_t O_PQ  = O_HMG;  // Pq dead after cqkv; Hmg written at cfc
constexpr size_t O_PFC = O_SC;   // Pfc written at fc;  Sc dead after softmax
constexpr size_t O_PP  = O_PA;   // Pp written at proj; Pa dead after AV

__device__ __align__(256) char g_pool[POOLSZ];

// ---------------- helpers ----------------
__device__ __forceinline__ uint32_t s2u(const void* p){
    uint32_t a;
    asm("{ .reg .u64 t; cvta.to.shared.u64 t, %1; cvt.u32.u64 %0, t; }":"=r"(a):"l"(p));
    return a;
}
__device__ __forceinline__ void cpa16(uint32_t d, const void* g){
    asm volatile("cp.async.cg.shared.global [%0], [%1], 16;"::"r"(d),"l"(g));
}
__device__ __forceinline__ void split1(float v, bf16& h, bf16& l){
    h = __float2bfloat16_rn(v);
    l = __float2bfloat16_rn(v - __bfloat162float(h));
}
__device__ __forceinline__ void split2(float vr, float vi, bf162& h, bf162& l){
    split1(vr, h.x, l.x); split1(vi, h.y, l.y);
}
__device__ __forceinline__ float flo(float v){
    return v - __bfloat162float(__float2bfloat16_rn(v));
}
__device__ __forceinline__ uint32_t pk2(float a, float b){
    bf162 t; t.x=__float2bfloat16_rn(a); t.y=__float2bfloat16_rn(b);
    return *(uint32_t*)&t;
}
__device__ __forceinline__ void ldm4(uint32_t* r, uint32_t a){
    asm volatile("ldmatrix.sync.aligned.m8n8.x4.shared.b16 {%0,%1,%2,%3}, [%4];"
        :"=r"(r[0]),"=r"(r[1]),"=r"(r[2]),"=r"(r[3]):"r"(a));
}
__device__ __forceinline__ void mma16816(float* d, const uint32_t* a, uint32_t b0, uint32_t b1){
    asm volatile("mma.sync.aligned.m16n8k16.row.col.f32.bf16.bf16.f32 "
        "{%0,%1,%2,%3}, {%4,%5,%6,%7}, {%8,%9}, {%0,%1,%2,%3};"
        :"+f"(d[0]),"+f"(d[1]),"+f"(d[2]),"+f"(d[3])
        :"r"(a[0]),"r"(a[1]),"r"(a[2]),"r"(a[3]),"r"(b0),"r"(b1));
}

// ---------------- GEMM via mma.sync (unchanged from R10 checkpoint) ----------------
struct GP {
    const bf16 *A, *A2, *B;
    long lda, ldb;
    long sA1, sA2, sB1, sB2;
    float2* C; long ldc, sC1, sC2;
    const float2* bias;
    int zdiv, kC;
    float scale;
};
#define ROWB 144
#define ASZ  (128*ROWB)
#define STB  (2*ASZ)
#define SMB  (3*STB)

template<int MODE>
__global__ __launch_bounds__(256,2) void tgemm(GP p)
{
    extern __shared__ __align__(256) char sm[];
    uint32_t TILE = s2u(sm);
    const int tid = threadIdx.x, lane = tid & 31, wid = tid >> 5;
    const int warpM = wid & 3, warpN = wid >> 2;

    const int z = blockIdx.z;
    const bf16* Ap = (MODE == 6 && z >= 3) ? p.A2 : p.A;
    const long offA = (z/p.zdiv)*p.sA1 + (z%p.zdiv)*p.sA2;
    const long offB = (z/p.zdiv)*p.sB1 + (z%p.zdiv)*p.sB2;
    const bf16* Ag = Ap + offA + (long)blockIdx.y*128*p.lda;
    const bf16* Bg = p.B + offB + (long)blockIdx.x*128*p.ldb;

    auto loadStage = [&](int c){
        uint32_t st = TILE + (c%3)*STB;
        long kof = (long)c*64;
        #pragma unroll
        for (int i=0;i<4;i++){
            int idx = tid + i*256; int r = idx>>3, cc = idx&7;
            cpa16(st + r*ROWB + cc*16, Ag + (long)r*p.lda + kof + cc*8);
        }
        #pragma unroll
        for (int i=0;i<4;i++){
            int idx = tid + i*256; int r = idx>>3, cc = idx&7;
            cpa16(st + ASZ + r*ROWB + cc*16, Bg + (long)r*p.ldb + kof + cc*8);
        }
        asm volatile("cp.async.commit_group;":::"memory");
    };

    float acc[2][8][4];
    #pragma unroll
    for (int mf=0;mf<2;mf++)
        #pragma unroll
        for (int nf=0;nf<8;nf++)
            #pragma unroll
            for (int t=0;t<4;t++) acc[mf][nf][t] = 0.f;

    loadStage(0);
    if (p.kC > 1) loadStage(1);

    const uint32_t aRel = (uint32_t)((warpM*32 + (lane&15))*ROWB + (lane>>4)*16);
    const uint32_t bRel = (uint32_t)(ASZ + (warpN*64 + (lane&7))*ROWB + ((lane>>3)&3)*16);

    for (int c = 0; c < p.kC; c++) {
        if (c+1 < p.kC) asm volatile("cp.async.wait_group 1;":::"memory");
        else            asm volatile("cp.async.wait_group 0;":::"memory");
        __syncthreads();
        if (c+2 < p.kC) loadStage(c+2);

        uint32_t st = TILE + (c%3)*STB;
        uint32_t aB = st + aRel, bB = st + bRel;
        #pragma unroll
        for (int kh=0; kh<2; kh++){
            uint32_t bfr[8][4];
            #pragma unroll
            for (int nf=0; nf<8; nf++) ldm4(bfr[nf], bB + nf*(8*ROWB) + kh*64);
            #pragma unroll
            for (int s=0; s<2; s++){
                int ks = kh*2 + s;
                uint32_t af[2][4];
                #pragma unroll
                for (int mf=0; mf<2; mf++) ldm4(af[mf], aB + mf*(16*ROWB) + ks*32);
                #pragma unroll
                for (int mf=0; mf<2; mf++)
                    #pragma unroll
                    for (int nf=0; nf<8; nf++)
                        mma16816(acc[mf][nf], af[mf], bfr[nf][s*2], bfr[nf][s*2+1]);
            }
        }
    }

    const long coff = (z/p.zdiv)*p.sC1 + (z%p.zdiv)*p.sC2;
    const int ncBase = blockIdx.x*64 + warpN*32 + (lane&3);
    #pragma unroll
    for (int mf=0; mf<2; mf++){
        long r0 = (long)blockIdx.y*128 + warpM*32 + mf*16 + (lane>>2);
        #pragma unroll
        for (int nf=0; nf<8; nf++){
            int nc = ncBase + nf*4;
            float2 bb = (MODE==0 && p.bias) ? p.bias[nc] : make_float2(0.f,0.f);
            #pragma unroll
            for (int h2=0; h2<2; h2++){
                long m = r0 + h2*8;
                float cr = acc[mf][nf][2*h2]   * p.scale + bb.x;
                float ci = acc[mf][nf][2*h2+1] * p.scale + bb.y;
                p.C[coff + m*p.ldc + nc] = make_float2(cr, ci);
            }
        }
    }
}

// ---------------- expansions (paired, vectorized) ----------------
// blocks [0,8192): query->Qg ; [8192,16384): x->Xg ; 2 elements (k,k+1) per thread
__global__ __launch_bounds__(256) void expandAG2(const float2* __restrict__ q,
                                                 const float2* __restrict__ x,
                                                 bf16* __restrict__ Qg, bf16* __restrict__ Xg)
{
    long bid = blockIdx.x;
    const float2* src = q; bf16* dst = Qg;
    if (bid >= 8192) { bid -= 8192; src = x; dst = Xg; }
    long pidx = bid*256 + threadIdx.x;
    long m = pidx >> 9; int k = (int)(pidx & 511) * 2;
    float4 vv = *(const float4*)(src + m*1024 + k);
    float c0[3] = { vv.x, vv.y, vv.x + vv.y };
    float c1[3] = { vv.z, vv.w, vv.z + vv.w };
    bf16* base = dst + m*9216 + k;
    #pragma unroll
    for (int c=0;c<3;c++){
        uint32_t h = pk2(c0[c], c1[c]);
        uint32_t l = pk2(flo(c0[c]), flo(c1[c]));
        bf16* b = base + c*3072;
        *(uint32_t*)(b)        = h;
        *(uint32_t*)(b + 1024) = l;
        *(uint32_t*)(b + 2048) = h;
    }
}
// weights paired: wq/wk/wv (2048 pair-blocks each), wfc (8192), wpr (8192)
__global__ __launch_bounds__(256) void expandWG2(
    const float2* __restrict__ wq, const float2* __restrict__ wk, const float2* __restrict__ wv,
    const float2* __restrict__ wfc, const float2* __restrict__ wpr,
    bf16* __restrict__ Wqkv, bf16* __restrict__ Wfcg, bf16* __restrict__ Wpg)
{
    long bid = blockIdx.x;
    const float2* W; bf16* out; int K; long rstride;
    if      (bid < 2048)  { W=wq;  out=Wqkv;                    K=1024; rstride=9216; }
    else if (bid < 4096)  { W=wk;  out=Wqkv+(size_t)1024*9216;  K=1024; rstride=9216; bid-=2048; }
    else if (bid < 6144)  { W=wv;  out=Wqkv+(size_t)2048*9216;  K=1024; rstride=9216; bid-=4096; }
    else if (bid < 14336) { W=wfc; out=Wfcg;                    K=1024; rstride=9216; bid-=6144; }
    else                  { W=wpr; out=Wpg;                     K=4096; rstride=36864; bid-=14336; }
    long pidx = bid*256 + threadIdx.x;
    int Kp = K >> 1;
    long n = pidx / Kp; int k = (int)(pidx % Kp) * 2;
    float4 ww = *(const float4*)(W + n*K + k);
    float c0[3] = { ww.x, ww.y, ww.x + ww.y };
    float c1[3] = { ww.z, ww.w, ww.z + ww.w };
    bf16* base = out + n*rstride + k;
    #pragma unroll
    for (int c=0;c<3;c++){
        uint32_t h = pk2(c0[c], c1[c]);
        uint32_t l = pk2(flo(c0[c]), flo(c1[c]));
        bf16* b = base + (long)c*3*K;
        *(uint32_t*)(b)       = h;
        *(uint32_t*)(b + K)   = h;
        *(uint32_t*)(b + 2*K) = l;
    }
}

// ---------------- QKV combine (quad): Pq -> Qa / Kb / Vb ----------------
__global__ __launch_bounds__(256) void cqkv4(const float* __restrict__ Pq,
                                             const float2* __restrict__ bq,
                                             const float2* __restrict__ bk,
                                             const float2* __restrict__ bv,
                                             bf16* __restrict__ Qa, bf16* __restrict__ Kb,
                                             bf16* __restrict__ Vb)
{
    long bid = blockIdx.x;
    int q3 = (int)(bid >> 12); bid &= 4095;
    long qidx = bid*256 + threadIdx.x;
    long m = qidx >> 8; int n = (int)(qidx & 255) * 4;
    const long MN = (long)MR*1024;
    const float* P = Pq + (long)q3*3*MN;
    long e = m*1024 + n;
    float4 p0 = *(const float4*)(P + e);
    float4 p1 = *(const float4*)(P + MN + e);
    float4 p2 = *(const float4*)(P + 2*MN + e);
    const float2* bi = (q3==0) ? bq : (q3==1 ? bk : bv);
    float4 b01 = *(const float4*)(bi + n);
    float4 b23 = *(const float4*)(bi + n + 2);
    float yr[4], yi[4];
    yr[0]=p0.x-p1.x+b01.x; yi[0]=p2.x-p0.x-p1.x+b01.y;
    yr[1]=p0.y-p1.y+b01.z; yi[1]=p2.y-p0.y-p1.y+b01.w;
    yr[2]=p0.z-p1.z+b23.x; yi[2]=p2.z-p0.z-p1.z+b23.y;
    yr[3]=p0.w-p1.w+b23.z; yi[3]=p2.w-p0.w-p1.w+b23.w;

    int b=(int)(m>>9), s=(int)(m&511), hh=n>>6, d=n&63;
    long zz = b*16 + hh;
    if (q3 == 0) {
        uint4 H, L;
        H.x=pk2(yr[0],yi[0]); H.y=pk2(yr[1],yi[1]); H.z=pk2(yr[2],yi[2]); H.w=pk2(yr[3],yi[3]);
        L.x=pk2(flo(yr[0]),flo(yi[0])); L.y=pk2(flo(yr[1]),flo(yi[1]));
        L.z=pk2(flo(yr[2]),flo(yi[2])); L.w=pk2(flo(yr[3]),flo(yi[3]));
        bf16* base = Qa + (zz*512 + s)*384 + 2*d;
        *(uint4*)(base)       = H;
        *(uint4*)(base + 128) = L;
        *(uint4*)(base + 256) = H;
    } else if (q3 == 1) {
        uint4 H0, L0, H1, L1;
        #pragma unroll
        for (int j=0;j<4;j++){
            ((uint32_t*)&H0)[j] = pk2(yr[j], -yi[j]);
            ((uint32_t*)&L0)[j] = pk2(flo(yr[j]), flo(-yi[j]));
            ((uint32_t*)&H1)[j] = pk2(yi[j], yr[j]);
            ((uint32_t*)&L1)[j] = pk2(flo(yi[j]), flo(yr[j]));
        }
        bf16* r0p = Kb + (zz*1024 + 2*s)*384 + 2*d;
        bf16* r1p = r0p + 384;
        *(uint4*)(r0p)       = H0; *(uint4*)(r0p + 128) = H0; *(uint4*)(r0p + 256) = L0;
        *(uint4*)(r1p)       = H1; *(uint4*)(r1p + 128) = H1; *(uint4*)(r1p + 256) = L1;
    } else {
        #pragma unroll
        for (int j=0;j<4;j++){
            uint32_t h0 = pk2(yr[j], -yi[j]);
            uint32_t l0 = pk2(flo(yr[j]), flo(-yi[j]));
            uint32_t h1 = pk2(yi[j], yr[j]);
            uint32_t l1 = pk2(flo(yi[j]), flo(yr[j]));
            bf16* r0p = Vb + (zz*128 + 2*(d+j))*3072 + 2*s;
            bf16* r1p = r0p + 3072;
            *(uint32_t*)(r0p)        = h0;
            *(uint32_t*)(r0p + 1024) = h0;
            *(uint32_t*)(r0p + 2048) = l0;
            *(uint32_t*)(r1p)        = h1;
            *(uint32_t*)(r1p + 1024) = h1;
            *(uint32_t*)(r1p + 2048) = l1;
        }
    }
}

// ---------------- fc combine (quad): Pfc -> modReLU -> Hmg ----------------
__global__ __launch_bounds__(256) void cfc4(const float* __restrict__ Pfc,
                                            const float2* __restrict__ bfc,
                                            bf16* __restrict__ Hmg)
{
    long qidx = (long)blockIdx.x*256 + threadIdx.x;
    long m = qidx >> 10; int n = (int)(qidx & 1023) * 4;
    const long MN = (long)MR*4096;
    long e = m*4096 + n;
    float4 p0 = *(const float4*)(Pfc + e);
    float4 p1 = *(const float4*)(Pfc + MN + e);
    float4 p2 = *(const float4*)(Pfc + 2*MN + e);
    float4 b01 = *(const float4*)(bfc + n);
    float4 b23 = *(const float4*)(bfc + n + 2);
    float yr[4], yi[4];
    yr[0]=p0.x-p1.x+b01.x; yi[0]=p2.x-p0.x-p1.x+b01.y;
    yr[1]=p0.y-p1.y+b01.z; yi[1]=p2.y-p0.y-p1.y+b01.w;
    yr[2]=p0.z-p1.z+b23.x; yi[2]=p2.z-p0.z-p1.z+b23.y;
    yr[3]=p0.w-p1.w+b23.z; yi[3]=p2.w-p0.w-p1.w+b23.w;
    float cs[3][4];
    #pragma unroll
    for (int j=0;j<4;j++){
        float mg = sqrtf(yr[j]*yr[j] + yi[j]*yi[j]);
        float r = 0.5f*(yr[j] + mg), ii = 0.5f*yi[j];
        cs[0][j] = r; cs[1][j] = ii; cs[2][j] = r + ii;
    }
    bf16* base = Hmg + m*36864 + n;
    #pragma unroll
    for (int c=0;c<3;c++){
        uint2 H, L;
        H.x = pk2(cs[c][0], cs[c][1]); H.y = pk2(cs[c][2], cs[c][3]);
        L.x = pk2(flo(cs[c][0]), flo(cs[c][1])); L.y = pk2(flo(cs[c][2]), flo(cs[c][3]));
        bf16* b = base + c*12288;
        *(uint2*)(b)        = H;
        *(uint2*)(b + 4096) = L;
        *(uint2*)(b + 8192) = H;
    }
}

// ---------------- softmax + probs expansion (unchanged) ----------------
__global__ __launch_bounds__(256) void softmax_kernel(const float2* __restrict__ Sc, bf16* __restrict__ Pa)
{
    long rid = (long)blockIdx.x*8 + (threadIdx.x>>5);
    int lane = threadIdx.x & 31;
    const float2* r = Sc + rid*512;
    float2 v[16]; float mx=-1e30f, my=-1e30f;
    #pragma unroll
    for (int i=0;i<16;i++){ v[i]=r[lane+32*i]; mx=fmaxf(mx,v[i].x); my=fmaxf(my,v[i].y); }
    #pragma unroll
    for (int o=16;o>0;o>>=1){ mx=fmaxf(mx,__shfl_xor_sync(~0u,mx,o)); my=fmaxf(my,__shfl_xor_sync(~0u,my,o)); }
    float sx=0.f, sy=0.f;
    #pragma unroll
    for (int i=0;i<16;i++){ v[i].x=__expf(v[i].x-mx); v[i].y=__expf(v[i].y-my); sx+=v[i].x; sy+=v[i].y; }
    #pragma unroll
    for (int o=16;o>0;o>>=1){ sx+=__shfl_xor_sync(~0u,sx,o); sy+=__shfl_xor_sync(~0u,sy,o); }
    float ix=1.f/sx, iy=1.f/sy;
    bf16* base = Pa + rid*3072;
    #pragma unroll
    for (int i=0;i<16;i++){
        int k = lane + 32*i;
        bf162 h,l; split2(v[i].x*ix, v[i].y*iy, h, l);
        *(bf162*)(base+2*k)=h; *(bf162*)(base+1024+2*k)=l; *(bf162*)(base+2048+2*k)=h;
    }
}

// ---------------- layernorms ----------------
__device__ __forceinline__ void reduce4(float& a, float& b, float& c, float& d, float* sh)
{
    #pragma unroll
    for (int o=16;o>0;o>>=1){
        a+=__shfl_xor_sync(~0u,a,o); b+=__shfl_xor_sync(~0u,b,o);
        c+=__shfl_xor_sync(~0u,c,o); d+=__shfl_xor_sync(~0u,d,o);
    }
    int w = threadIdx.x>>5;
    __syncthreads();
    if ((threadIdx.x&31)==0){ sh[w]=a; sh[8+w]=b; sh[16+w]=c; sh[24+w]=d; }
    __syncthreads();
    float ra=0,rb=0,rc=0,rd=0;
    #pragma unroll
    for (int i=0;i<8;i++){ ra+=sh[i]; rb+=sh[8+i]; rc+=sh[16+i]; rd+=sh[24+i]; }
    a=ra; b=rb; c=rc; d=rd;
}

// paired version: thread handles d = 2*(tid + i*256), d+1 for i in {0,1}
__global__ __launch_bounds__(256)
void ln_attn_kernel(const float2* __restrict__ O, const float2* __restrict__ query,
                    const float2* __restrict__ x,
                    const float* __restrict__ g, const float* __restrict__ bta,
                    float2* __restrict__ X2, bf16* __restrict__ X2g)
{
    __shared__ float sh[32];
    const long base = (long)blockIdx.x*DD;
    const float inv = 1.f/DD;
    float2 v[4]; float sr=0,sq=0,si=0,qi=0;
    #pragma unroll
    for (int i=0;i<2;i++){
        int d = 2*(threadIdx.x + i*256);
        float4 o = *(const float4*)(O + base + d);
        float4 q = *(const float4*)(query + base + d);
        v[2*i]   = make_float2(o.x+q.x, o.y+q.y);
        v[2*i+1] = make_float2(o.z+q.z, o.w+q.w);
        sr+=v[2*i].x+v[2*i+1].x; sq+=v[2*i].x*v[2*i].x+v[2*i+1].x*v[2*i+1].x;
        si+=v[2*i].y+v[2*i+1].y; qi+=v[2*i].y*v[2*i].y+v[2*i+1].y*v[2*i+1].y;
    }
    reduce4(sr,sq,si,qi,sh);
    float mr=sr*inv, mi=si*inv;
    float rr=rsqrtf(sq*inv-mr*mr+LN_EPS), ri=rsqrtf(qi*inv-mi*mi+LN_EPS);
    float2 u[4]; float s2=0,q2=0,s3=0,q3=0;
    #pragma unroll
    for (int i=0;i<2;i++){
        int d = 2*(threadIdx.x + i*256);
        float2 gr = *(const float2*)(g + d);
        float2 gi2 = *(const float2*)(g + DD + d);
        float2 br = *(const float2*)(bta + d);
        float2 bi2 = *(const float2*)(bta + DD + d);
        float4 xx = *(const float4*)(x + base + d);
        float tr0=(v[2*i].x-mr)*rr*gr.x+br.x,   ti0=(v[2*i].y-mi)*ri*gi2.x+bi2.x;
        float tr1=(v[2*i+1].x-mr)*rr*gr.y+br.y, ti1=(v[2*i+1].y-mi)*ri*gi2.y+bi2.y;
        u[2*i]   = make_float2(xx.x+tr0, xx.y+ti0);
        u[2*i+1] = make_float2(xx.z+tr1, xx.w+ti1);
        s2+=u[2*i].x+u[2*i+1].x; q2+=u[2*i].x*u[2*i].x+u[2*i+1].x*u[2*i+1].x;
        s3+=u[2*i].y+u[2*i+1].y; q3+=u[2*i].y*u[2*i].y+u[2*i+1].y*u[2*i+1].y;
    }
    reduce4(s2,q2,s3,q3,sh);
    float m2=s2*inv, m3=s3*inv;
    float r2=rsqrtf(q2*inv-m2*m2+LN_EPS), r3=rsqrtf(q3*inv-m3*m3+LN_EPS);
    const float *g1=g+2*DD, *b1=bta+2*DD;
    #pragma unroll
    for (int i=0;i<2;i++){
        int d = 2*(threadIdx.x + i*256);
        float2 gr = *(const float2*)(g1 + d);
        float2 gi2 = *(const float2*)(g1 + DD + d);
        float2 br = *(const float2*)(b1 + d);
        float2 bi2 = *(const float2*)(b1 + DD + d);
        float y0r=(u[2*i].x-m2)*r2*gr.x+br.x,   y0i=(u[2*i].y-m3)*r3*gi2.x+bi2.x;
        float y1r=(u[2*i+1].x-m2)*r2*gr.y+br.y, y1i=(u[2*i+1].y-m3)*r3*gi2.y+bi2.y;
        float4 o4; o4.x=y0r; o4.y=y0i; o4.z=y1r; o4.w=y1i;
        *(float4*)(X2 + base + d) = o4;
        float c0[3] = { y0r, y0i, y0r + y0i };
        float c1[3] = { y1r, y1i, y1r + y1i };
        bf16* eb = X2g + (long)blockIdx.x*9216 + d;
        #pragma unroll
        for (int c=0;c<3;c++){
            uint32_t h = pk2(c0[c], c1[c]);
            uint32_t l = pk2(flo(c0[c]), flo(c1[c]));
            bf16* b = eb + c*3072;
            *(uint32_t*)(b)        = h;
            *(uint32_t*)(b + 1024) = l;
            *(uint32_t*)(b + 2048) = h;
        }
    }
}

// out = LN2(X2 + proj), proj = Gauss-combined from 6 partials + bias (unchanged)
__global__ __launch_bounds__(256)
void ln_final_kernel(const float2* __restrict__ X2, const float* __restrict__ Pp,
                     const float2* __restrict__ bpr,
                     const float* __restrict__ g, const float* __restrict__ bta,
                     float2* __restrict__ out)
{
    __shared__ float sh[32];
    const long base = (long)blockIdx.x*DD;
    const long S = (long)MR*1024;
    const float inv = 1.f/DD;
    float2 v[4]; float sr=0,sq=0,si=0,qi=0;
    #pragma unroll
    for (int i=0;i<4;i++){
        int d = threadIdx.x + i*256;
        long fi = base + d;
        float P1 = Pp[fi] + Pp[S+fi];
        float P2 = Pp[2*S+fi] + Pp[3*S+fi];
        float P3 = Pp[4*S+fi] + Pp[5*S+fi];
        float2 a = X2[fi]; float2 bb = bpr[d];
        v[i] = make_float2(a.x + (P1 - P2) + bb.x,
                           a.y + (P3 - P1 - P2) + bb.y);
        sr+=v[i].x; sq+=v[i].x*v[i].x; si+=v[i].y; qi+=v[i].y*v[i].y;
    }
    reduce4(sr,sq,si,qi,sh);
    float mr=sr*inv, mi=si*inv;
    float rr=rsqrtf(sq*inv-mr*mr+LN_EPS), ri=rsqrtf(qi*inv-mi*mi+LN_EPS);
    const float *g2=g+4*DD, *b2=bta+4*DD;
    #pragma unroll
    for (int i=0;i<4;i++){
        int d = threadIdx.x + i*256;
        out[base+d]=make_float2((v[i].x-mr)*rr*g2[d]+b2[d], (v[i].y-mi)*ri*g2[DD+d]+b2[DD+d]);
    }
}

// ---------------- host ----------------
static GP mkgp(const bf16* A, const bf16* A2, long lda, const bf16* B, long ldb, int kC,
               float2* C, long ldc, const float2* bias, float scale,
               int zdiv, long sA1, long sA2, long sB1, long sB2, long sC1, long sC2)
{
    GP p = {};
    p.A=A; p.A2=A2; p.B=B; p.lda=lda; p.ldb=ldb; p.kC=kC;
    p.C=C; p.ldc=ldc; p.bias=bias; p.scale=scale; p.zdiv=zdiv;
    p.sA1=sA1; p.sA2=sA2; p.sB1=sB1; p.sB2=sB2; p.sC1=sC1; p.sC2=sC2;
    return p;
}

extern "C" void kernel_launch(void* const* d_in, const int* in_sizes, int n_in,
                              void* d_out, int out_size)
{
    const float2* x     = (const float2*)d_in[0];
    const float2* query = (const float2*)d_in[1];
    const float2* wq    = (const float2*)d_in[2];
    const float2* bq    = (const float2*)d_in[3];
    const float2* wk    = (const float2*)d_in[4];
    const float2* bk    = (const float2*)d_in[5];
    const float2* wv    = (const float2*)d_in[6];
    const float2* bv    = (const float2*)d_in[7];
    const float2* wfc   = (const float2*)d_in[8];
    const float2* bfc   = (const float2*)d_in[9];
    const float2* wpr   = (const float2*)d_in[10];
    const float2* bpr   = (const float2*)d_in[11];
    const float*  lng   = (const float*)d_in[12];
    const float*  lnb   = (const float*)d_in[13];

    char* pool;
    cudaGetSymbolAddress((void**)&pool, g_pool);
    bf16 *Qg   = (bf16*)(pool + O_QG),   *Xg   = (bf16*)(pool + O_XG);
    bf16 *X2g  = (bf16*)(pool + O_X2G),  *Hmg  = (bf16*)(pool + O_HMG);
    bf16 *Wqkv = (bf16*)(pool + O_WQKV), *Wfcg = (bf16*)(pool + O_WFCG);
    bf16 *Wpg  = (bf16*)(pool + O_WPG);
    bf16 *Qa   = (bf16*)(pool + O_QA),   *Kb   = (bf16*)(pool + O_KB);
    bf16 *Vb   = (bf16*)(pool + O_VB),   *Pa   = (bf16*)(pool + O_PA);
    float *Pq  = (float*)(pool + O_PQ),  *Pfc  = (float*)(pool + O_PFC);
    float *Pp  = (float*)(pool + O_PP);
    float2 *O  = (float2*)(pool + O_OO), *X2   = (float2*)(pool + O_X2);
    float2 *Sc = (float2*)(pool + O_SC);

    cudaFuncSetAttribute(tgemm<0>, cudaFuncAttributeMaxDynamicSharedMemorySize, SMB);
    cudaFuncSetAttribute(tgemm<6>, cudaFuncAttributeMaxDynamicSharedMemorySize, SMB);

    // expansions (paired/vectorized)
    expandAG2<<<16384,256>>>(query, x, Qg, Xg);
    expandWG2<<<22528,256>>>(wq, wk, wv, wfc, wpr, Wqkv, Wfcg, Wpg);

    // QKV Gauss: grid (8,32,9); z = inp*3 + product; z<3 uses Qg else Xg. kC=48.
    tgemm<6><<<dim3(8,32,9),256,SMB>>>(mkgp(Qg, Xg, 9216, Wqkv, 9216, 48,
        (float2*)Pq, 512, nullptr, 1.f,
        3, 0, 3072, (long)1024*9216, 3072, 3L*MR*512, (long)MR*512));
    cqkv4<<<12288,256>>>(Pq, bq, bk, bv, Qa, Kb, Vb);

    // scores: per z=(b,h): [512 x 1024'], K_eff=384 (kC=6)   <-- ncu -s 5 lands here
    tgemm<0><<<dim3(8,4,128),256,SMB>>>(mkgp(Qa, Qa, 384, Kb, 384, 6,
        Sc, 512, nullptr, 0.125f,
        1, 512L*384, 0, 1024L*384, 0, 512L*512, 0));
    softmax_kernel<<<128*512/8,256>>>(Sc, Pa);

    // AV: per z: [512 x 128'], K_eff=3072 (kC=48)
    tgemm<0><<<dim3(1,4,128),256,SMB>>>(mkgp(Pa, Pa, 3072, Vb, 3072, 48,
        O, 1024, nullptr, 1.f,
        16, 16L*512*3072, 512L*3072, 16L*128*3072, 128L*3072, 512L*1024, 64));

    ln_attn_kernel<<<MR,256>>>(O, query, x, lng, lnb, X2, X2g);

    // fc Gauss: grid (32,32,3); z = product. kC=48.
    tgemm<6><<<dim3(32,32,3),256,SMB>>>(mkgp(X2g, X2g, 9216, Wfcg, 9216, 48,
        (float2*)Pfc, 2048, nullptr, 1.f,
        3, 0, 3072, 0, 3072, 0, (long)MR*2048));
    cfc4<<<16384,256>>>(Pfc, bfc, Hmg);

    // proj Gauss + split-K x2: grid (8,32,6); z = product*2 + khalf. kC=96.
    tgemm<6><<<dim3(8,32,6),256,SMB>>>(mkgp(Hmg, Hmg, 36864, Wpg, 36864, 96,
        (float2*)Pp, 512, nullptr, 1.f,
        2, 12288, 6144, 12288, 6144, 2L*MR*512, (long)MR*512));

    ln_final_kernel<<<MR,256>>>(X2, Pp, bpr, lng, lnb, (float2*)d_out);
}

// round 13
// speedup vs baseline: 3.7430x; 1.0460x over previous
#include <cuda_runtime.h>
#include <cuda_bf16.h>
#include <cstdint>
#include <math.h>

typedef __nv_bfloat16 bf16;
typedef __nv_bfloat162 bf162;

#define DD 1024
#define MR 4096
#define LN_EPS 1e-5f

// ---------------- pooled scratch (single symbol, lifetime-aliased) ----------------
constexpr size_t O_QG   = 0;
constexpr size_t O_XG   = O_QG  + (size_t)MR*9216*2;
constexpr size_t O_X2G  = O_XG  + (size_t)MR*9216*2;
constexpr size_t O_WQKV = O_X2G + (size_t)MR*9216*2;
constexpr size_t O_WFCG = O_WQKV + (size_t)3*1024*9216*2;
constexpr size_t O_WPG  = O_WFCG + (size_t)4096*9216*2;
constexpr size_t O_QA   = O_WPG  + (size_t)1024*36864*2;
constexpr size_t O_KB   = O_QA   + (size_t)128*512*384*2;
constexpr size_t O_VB   = O_KB   + (size_t)128*1024*384*2;
constexpr size_t O_PA   = O_VB   + (size_t)128*128*3072*2;
constexpr size_t O_OO   = O_PA   + (size_t)128*512*3072*2;
constexpr size_t O_X2   = O_OO   + (size_t)MR*DD*8;
constexpr size_t O_HMG  = O_X2   + (size_t)MR*DD*8;
constexpr size_t O_SC   = O_HMG  + (size_t)MR*36864*2;
constexpr size_t POOLSZ = O_SC   + (size_t)128*512*512*8;
// aliases (disjoint lifetimes in launch order):
constexpr size_t O_PQ  = O_HMG;  // Pq dead after cqk4/cvb_t; Hmg written at cfc
constexpr size_t O_PFC = O_SC;   // Pfc written at fc;  Sc dead after softmax
constexpr size_t O_PP  = O_PA;   // Pp written at proj; Pa dead after AV

__device__ __align__(256) char g_pool[POOLSZ];

// ---------------- helpers ----------------
__device__ __forceinline__ uint32_t s2u(const void* p){
    uint32_t a;
    asm("{ .reg .u64 t; cvta.to.shared.u64 t, %1; cvt.u32.u64 %0, t; }":"=r"(a):"l"(p));
    return a;
}
__device__ __forceinline__ void cpa16(uint32_t d, const void* g){
    asm volatile("cp.async.cg.shared.global [%0], [%1], 16;"::"r"(d),"l"(g));
}
__device__ __forceinline__ void split1(float v, bf16& h, bf16& l){
    h = __float2bfloat16_rn(v);
    l = __float2bfloat16_rn(v - __bfloat162float(h));
}
__device__ __forceinline__ void split2(float vr, float vi, bf162& h, bf162& l){
    split1(vr, h.x, l.x); split1(vi, h.y, l.y);
}
__device__ __forceinline__ float flo(float v){
    return v - __bfloat162float(__float2bfloat16_rn(v));
}
__device__ __forceinline__ uint32_t pk2(float a, float b){
    bf162 t; t.x=__float2bfloat16_rn(a); t.y=__float2bfloat16_rn(b);
    return *(uint32_t*)&t;
}
__device__ __forceinline__ void ldm4(uint32_t* r, uint32_t a){
    asm volatile("ldmatrix.sync.aligned.m8n8.x4.shared.b16 {%0,%1,%2,%3}, [%4];"
        :"=r"(r[0]),"=r"(r[1]),"=r"(r[2]),"=r"(r[3]):"r"(a));
}
__device__ __forceinline__ void mma16816(float* d, const uint32_t* a, uint32_t b0, uint32_t b1){
    asm volatile("mma.sync.aligned.m16n8k16.row.col.f32.bf16.bf16.f32 "
        "{%0,%1,%2,%3}, {%4,%5,%6,%7}, {%8,%9}, {%0,%1,%2,%3};"
        :"+f"(d[0]),"+f"(d[1]),"+f"(d[2]),"+f"(d[3])
        :"r"(a[0]),"r"(a[1]),"r"(a[2]),"r"(a[3]),"r"(b0),"r"(b1));
}

// ---------------- GEMM via mma.sync ----------------
// MODE 0: attention GEMM, float2 C; MODE 6: Gauss product GEMM; MODE 8: like 0 but
// A K-sections remapped [h|l|h] over physical [h|l] (lda=2048): sec {0,1024,0} per 16 chunks.
struct GP {
    const bf16 *A, *A2, *B;
    long lda, ldb;
    long sA1, sA2, sB1, sB2;
    float2* C; long ldc, sC1, sC2;
    const float2* bias;
    int zdiv, kC;
    float scale;
};
#define ROWB 144
#define ASZ  (128*ROWB)
#define STB  (2*ASZ)
#define SMB  (3*STB)

template<int MODE>
__global__ __launch_bounds__(256,2) void tgemm(GP p)
{
    extern __shared__ __align__(256) char sm[];
    uint32_t TILE = s2u(sm);
    const int tid = threadIdx.x, lane = tid & 31, wid = tid >> 5;
    const int warpM = wid & 3, warpN = wid >> 2;

    const int z = blockIdx.z;
    const bf16* Ap = (MODE == 6 && z >= 3) ? p.A2 : p.A;
    const long offA = (z/p.zdiv)*p.sA1 + (z%p.zdiv)*p.sA2;
    const long offB = (z/p.zdiv)*p.sB1 + (z%p.zdiv)*p.sB2;
    const bf16* Ag = Ap + offA + (long)blockIdx.y*128*p.lda;
    const bf16* Bg = p.B + offB + (long)blockIdx.x*128*p.ldb;

    auto loadStage = [&](int c){
        uint32_t st = TILE + (c%3)*STB;
        long kofB = (long)c*64;
        long kofA = kofB;
        if (MODE == 8) kofA = (((c>>4)==1) ? 1024L : 0L) + (long)(c&15)*64;
        #pragma unroll
        for (int i=0;i<4;i++){
            int idx = tid + i*256; int r = idx>>3, cc = idx&7;
            cpa16(st + r*ROWB + cc*16, Ag + (long)r*p.lda + kofA + cc*8);
        }
        #pragma unroll
        for (int i=0;i<4;i++){
            int idx = tid + i*256; int r = idx>>3, cc = idx&7;
            cpa16(st + ASZ + r*ROWB + cc*16, Bg + (long)r*p.ldb + kofB + cc*8);
        }
        asm volatile("cp.async.commit_group;":::"memory");
    };

    float acc[2][8][4];
    #pragma unroll
    for (int mf=0;mf<2;mf++)
        #pragma unroll
        for (int nf=0;nf<8;nf++)
            #pragma unroll
            for (int t=0;t<4;t++) acc[mf][nf][t] = 0.f;

    loadStage(0);
    if (p.kC > 1) loadStage(1);

    const uint32_t aRel = (uint32_t)((warpM*32 + (lane&15))*ROWB + (lane>>4)*16);
    const uint32_t bRel = (uint32_t)(ASZ + (warpN*64 + (lane&7))*ROWB + ((lane>>3)&3)*16);

    for (int c = 0; c < p.kC; c++) {
        if (c+1 < p.kC) asm volatile("cp.async.wait_group 1;":::"memory");
        else            asm volatile("cp.async.wait_group 0;":::"memory");
        __syncthreads();
        if (c+2 < p.kC) loadStage(c+2);

        uint32_t st = TILE + (c%3)*STB;
        uint32_t aB = st + aRel, bB = st + bRel;
        #pragma unroll
        for (int kh=0; kh<2; kh++){
            uint32_t bfr[8][4];
            #pragma unroll
            for (int nf=0; nf<8; nf++) ldm4(bfr[nf], bB + nf*(8*ROWB) + kh*64);
            #pragma unroll
            for (int s=0; s<2; s++){
                int ks = kh*2 + s;
                uint32_t af[2][4];
                #pragma unroll
                for (int mf=0; mf<2; mf++) ldm4(af[mf], aB + mf*(16*ROWB) + ks*32);
                #pragma unroll
                for (int mf=0; mf<2; mf++)
                    #pragma unroll
                    for (int nf=0; nf<8; nf++)
                        mma16816(acc[mf][nf], af[mf], bfr[nf][s*2], bfr[nf][s*2+1]);
            }
        }
    }

    const long coff = (z/p.zdiv)*p.sC1 + (z%p.zdiv)*p.sC2;
    const int ncBase = blockIdx.x*64 + warpN*32 + (lane&3);
    #pragma unroll
    for (int mf=0; mf<2; mf++){
        long r0 = (long)blockIdx.y*128 + warpM*32 + mf*16 + (lane>>2);
        #pragma unroll
        for (int nf=0; nf<8; nf++){
            int nc = ncBase + nf*4;
            float2 bb = ((MODE==0||MODE==8) && p.bias) ? p.bias[nc] : make_float2(0.f,0.f);
            #pragma unroll
            for (int h2=0; h2<2; h2++){
                long m = r0 + h2*8;
                float cr = acc[mf][nf][2*h2]   * p.scale + bb.x;
                float ci = acc[mf][nf][2*h2+1] * p.scale + bb.y;
                p.C[coff + m*p.ldc + nc] = make_float2(cr, ci);
            }
        }
    }
}

// ---------------- expansions (paired, vectorized; unchanged) ----------------
__global__ __launch_bounds__(256) void expandAG2(const float2* __restrict__ q,
                                                 const float2* __restrict__ x,
                                                 bf16* __restrict__ Qg, bf16* __restrict__ Xg)
{
    long bid = blockIdx.x;
    const float2* src = q; bf16* dst = Qg;
    if (bid >= 8192) { bid -= 8192; src = x; dst = Xg; }
    long pidx = bid*256 + threadIdx.x;
    long m = pidx >> 9; int k = (int)(pidx & 511) * 2;
    float4 vv = *(const float4*)(src + m*1024 + k);
    float c0[3] = { vv.x, vv.y, vv.x + vv.y };
    float c1[3] = { vv.z, vv.w, vv.z + vv.w };
    bf16* base = dst + m*9216 + k;
    #pragma unroll
    for (int c=0;c<3;c++){
        uint32_t h = pk2(c0[c], c1[c]);
        uint32_t l = pk2(flo(c0[c]), flo(c1[c]));
        bf16* b = base + c*3072;
        *(uint32_t*)(b)        = h;
        *(uint32_t*)(b + 1024) = l;
        *(uint32_t*)(b + 2048) = h;
    }
}
__global__ __launch_bounds__(256) void expandWG2(
    const float2* __restrict__ wq, const float2* __restrict__ wk, const float2* __restrict__ wv,
    const float2* __restrict__ wfc, const float2* __restrict__ wpr,
    bf16* __restrict__ Wqkv, bf16* __restrict__ Wfcg, bf16* __restrict__ Wpg)
{
    long bid = blockIdx.x;
    const float2* W; bf16* out; int K; long rstride;
    if      (bid < 2048)  { W=wq;  out=Wqkv;                    K=1024; rstride=9216; }
    else if (bid < 4096)  { W=wk;  out=Wqkv+(size_t)1024*9216;  K=1024; rstride=9216; bid-=2048; }
    else if (bid < 6144)  { W=wv;  out=Wqkv+(size_t)2048*9216;  K=1024; rstride=9216; bid-=4096; }
    else if (bid < 14336) { W=wfc; out=Wfcg;                    K=1024; rstride=9216; bid-=6144; }
    else                  { W=wpr; out=Wpg;                     K=4096; rstride=36864; bid-=14336; }
    long pidx = bid*256 + threadIdx.x;
    int Kp = K >> 1;
    long n = pidx / Kp; int k = (int)(pidx % Kp) * 2;
    float4 ww = *(const float4*)(W + n*K + k);
    float c0[3] = { ww.x, ww.y, ww.x + ww.y };
    float c1[3] = { ww.z, ww.w, ww.z + ww.w };
    bf16* base = out + n*rstride + k;
    #pragma unroll
    for (int c=0;c<3;c++){
        uint32_t h = pk2(c0[c], c1[c]);
        uint32_t l = pk2(flo(c0[c]), flo(c1[c]));
        bf16* b = base + (long)c*3*K;
        *(uint32_t*)(b)       = h;
        *(uint32_t*)(b + K)   = h;
        *(uint32_t*)(b + 2*K) = l;
    }
}

// ---------------- Q/K combine (quad, coalesced stores) ----------------
__global__ __launch_bounds__(256) void cqk4(const float* __restrict__ Pq,
                                            const float2* __restrict__ bq,
                                            const float2* __restrict__ bk,
                                            bf16* __restrict__ Qa, bf16* __restrict__ Kb)
{
    long bid = blockIdx.x;
    int q3 = (int)(bid >> 12); bid &= 4095;     // q3 in {0,1}
    long qidx = bid*256 + threadIdx.x;
    long m = qidx >> 8; int n = (int)(qidx & 255) * 4;
    const long MN = (long)MR*1024;
    const float* P = Pq + (long)q3*3*MN;
    long e = m*1024 + n;
    float4 p0 = *(const float4*)(P + e);
    float4 p1 = *(const float4*)(P + MN + e);
    float4 p2 = *(const float4*)(P + 2*MN + e);
    const float2* bi = (q3==0) ? bq : bk;
    float4 b01 = *(const float4*)(bi + n);
    float4 b23 = *(const float4*)(bi + n + 2);
    float yr[4], yi[4];
    yr[0]=p0.x-p1.x+b01.x; yi[0]=p2.x-p0.x-p1.x+b01.y;
    yr[1]=p0.y-p1.y+b01.z; yi[1]=p2.y-p0.y-p1.y+b01.w;
    yr[2]=p0.z-p1.z+b23.x; yi[2]=p2.z-p0.z-p1.z+b23.y;
    yr[3]=p0.w-p1.w+b23.z; yi[3]=p2.w-p0.w-p1.w+b23.w;

    int b=(int)(m>>9), s=(int)(m&511), hh=n>>6, d=n&63;
    long zz = b*16 + hh;
    if (q3 == 0) {
        uint4 H, L;
        H.x=pk2(yr[0],yi[0]); H.y=pk2(yr[1],yi[1]); H.z=pk2(yr[2],yi[2]); H.w=pk2(yr[3],yi[3]);
        L.x=pk2(flo(yr[0]),flo(yi[0])); L.y=pk2(flo(yr[1]),flo(yi[1]));
        L.z=pk2(flo(yr[2]),flo(yi[2])); L.w=pk2(flo(yr[3]),flo(yi[3]));
        bf16* base = Qa + (zz*512 + s)*384 + 2*d;
        *(uint4*)(base)       = H;
        *(uint4*)(base + 128) = L;
        *(uint4*)(base + 256) = H;
    } else {
        uint4 H0, L0, H1, L1;
        #pragma unroll
        for (int j=0;j<4;j++){
            ((uint32_t*)&H0)[j] = pk2(yr[j], -yi[j]);
            ((uint32_t*)&L0)[j] = pk2(flo(yr[j]), flo(-yi[j]));
            ((uint32_t*)&H1)[j] = pk2(yi[j], yr[j]);
            ((uint32_t*)&L1)[j] = pk2(flo(yi[j]), flo(yr[j]));
        }
        bf16* r0p = Kb + (zz*1024 + 2*s)*384 + 2*d;
        bf16* r1p = r0p + 384;
        *(uint4*)(r0p)       = H0; *(uint4*)(r0p + 128) = H0; *(uint4*)(r0p + 256) = L0;
        *(uint4*)(r1p)       = H1; *(uint4*)(r1p + 128) = H1; *(uint4*)(r1p + 256) = L1;
    }
}

// ---------------- V combine: smem-staged transpose, coalesced writes ----------------
// grid (16 s-tiles, 2 d-tiles, 128 zz); 32x32 (d x s) tile per block.
__global__ __launch_bounds__(256) void cvb_t(const float* __restrict__ Pq,
                                             const float2* __restrict__ bv,
                                             bf16* __restrict__ Vb)
{
    __shared__ float syr[32][33], syi[32][33];
    const int zz = blockIdx.z, s0 = blockIdx.x*32, d0 = blockIdx.y*32;
    const int b = zz >> 4, h = zz & 15;
    const long MN = (long)MR*1024;
    const float* P = Pq + 2L*3*MN;          // q3 = 2 (V products)
    const int tl = threadIdx.x & 31, tw = threadIdx.x >> 5;

    // phase 1: coalesced reads along d; smem[s][d]
    #pragma unroll
    for (int r=0;r<4;r++){
        int sl = tw + 8*r;
        long e = ((long)(b*512 + s0 + sl))*1024 + h*64 + d0 + tl;
        float p0 = P[e], p1 = P[MN+e], p2 = P[2*MN+e];
        float2 bb = bv[h*64 + d0 + tl];
        syr[sl][tl] = p0 - p1 + bb.x;
        syi[sl][tl] = p2 - p0 - p1 + bb.y;
    }
    __syncthreads();

    // phase 2: coalesced writes along s (lane = s)
    #pragma unroll
    for (int r=0;r<4;r++){
        int dl = tw + 8*r;
        float yr = syr[tl][dl], yi = syi[tl][dl];
        uint32_t h0 = pk2(yr, -yi), l0 = pk2(flo(yr), flo(-yi));
        uint32_t h1 = pk2(yi, yr),  l1 = pk2(flo(yi), flo(yr));
        bf16* r0p = Vb + ((long)zz*128 + 2*(d0+dl))*3072 + 2*(s0+tl);
        bf16* r1p = r0p + 3072;
        *(uint32_t*)(r0p)        = h0;
        *(uint32_t*)(r0p + 1024) = h0;
        *(uint32_t*)(r0p + 2048) = l0;
        *(uint32_t*)(r1p)        = h1;
        *(uint32_t*)(r1p + 1024) = h1;
        *(uint32_t*)(r1p + 2048) = l1;
    }
}

// ---------------- fc combine (quad; unchanged) ----------------
__global__ __launch_bounds__(256) void cfc4(const float* __restrict__ Pfc,
                                            const float2* __restrict__ bfc,
                                            bf16* __restrict__ Hmg)
{
    long qidx = (long)blockIdx.x*256 + threadIdx.x;
    long m = qidx >> 10; int n = (int)(qidx & 1023) * 4;
    const long MN = (long)MR*4096;
    long e = m*4096 + n;
    float4 p0 = *(const float4*)(Pfc + e);
    float4 p1 = *(const float4*)(Pfc + MN + e);
    float4 p2 = *(const float4*)(Pfc + 2*MN + e);
    float4 b01 = *(const float4*)(bfc + n);
    float4 b23 = *(const float4*)(bfc + n + 2);
    float yr[4], yi[4];
    yr[0]=p0.x-p1.x+b01.x; yi[0]=p2.x-p0.x-p1.x+b01.y;
    yr[1]=p0.y-p1.y+b01.z; yi[1]=p2.y-p0.y-p1.y+b01.w;
    yr[2]=p0.z-p1.z+b23.x; yi[2]=p2.z-p0.z-p1.z+b23.y;
    yr[3]=p0.w-p1.w+b23.z; yi[3]=p2.w-p0.w-p1.w+b23.w;
    float cs[3][4];
    #pragma unroll
    for (int j=0;j<4;j++){
        float mg = sqrtf(yr[j]*yr[j] + yi[j]*yi[j]);
        float r = 0.5f*(yr[j] + mg), ii = 0.5f*yi[j];
        cs[0][j] = r; cs[1][j] = ii; cs[2][j] = r + ii;
    }
    bf16* base = Hmg + m*36864 + n;
    #pragma unroll
    for (int c=0;c<3;c++){
        uint2 H, L;
        H.x = pk2(cs[c][0], cs[c][1]); H.y = pk2(cs[c][2], cs[c][3]);
        L.x = pk2(flo(cs[c][0]), flo(cs[c][1])); L.y = pk2(flo(cs[c][2]), flo(cs[c][3]));
        bf16* b = base + c*12288;
        *(uint2*)(b)        = H;
        *(uint2*)(b + 4096) = L;
        *(uint2*)(b + 8192) = H;
    }
}

// ---------------- softmax + probs expansion ([h|l] layout, width 2048) ----------------
__global__ __launch_bounds__(256) void softmax_kernel(const float2* __restrict__ Sc, bf16* __restrict__ Pa)
{
    long rid = (long)blockIdx.x*8 + (threadIdx.x>>5);
    int lane = threadIdx.x & 31;
    const float2* r = Sc + rid*512;
    float2 v[16]; float mx=-1e30f, my=-1e30f;
    #pragma unroll
    for (int i=0;i<16;i++){ v[i]=r[lane+32*i]; mx=fmaxf(mx,v[i].x); my=fmaxf(my,v[i].y); }
    #pragma unroll
    for (int o=16;o>0;o>>=1){ mx=fmaxf(mx,__shfl_xor_sync(~0u,mx,o)); my=fmaxf(my,__shfl_xor_sync(~0u,my,o)); }
    float sx=0.f, sy=0.f;
    #pragma unroll
    for (int i=0;i<16;i++){ v[i].x=__expf(v[i].x-mx); v[i].y=__expf(v[i].y-my); sx+=v[i].x; sy+=v[i].y; }
    #pragma unroll
    for (int o=16;o>0;o>>=1){ sx+=__shfl_xor_sync(~0u,sx,o); sy+=__shfl_xor_sync(~0u,sy,o); }
    float ix=1.f/sx, iy=1.f/sy;
    bf16* base = Pa + rid*2048;
    #pragma unroll
    for (int i=0;i<16;i++){
        int k = lane + 32*i;
        bf162 h,l; split2(v[i].x*ix, v[i].y*iy, h, l);
        *(bf162*)(base+2*k)=h; *(bf162*)(base+1024+2*k)=l;
    }
}

// ---------------- layernorms (unchanged) ----------------
__device__ __forceinline__ void reduce4(float& a, float& b, float& c, float& d, float* sh)
{
    #pragma unroll
    for (int o=16;o>0;o>>=1){
        a+=__shfl_xor_sync(~0u,a,o); b+=__shfl_xor_sync(~0u,b,o);
        c+=__shfl_xor_sync(~0u,c,o); d+=__shfl_xor_sync(~0u,d,o);
    }
    int w = threadIdx.x>>5;
    __syncthreads();
    if ((threadIdx.x&31)==0){ sh[w]=a; sh[8+w]=b; sh[16+w]=c; sh[24+w]=d; }
    __syncthreads();
    float ra=0,rb=0,rc=0,rd=0;
    #pragma unroll
    for (int i=0;i<8;i++){ ra+=sh[i]; rb+=sh[8+i]; rc+=sh[16+i]; rd+=sh[24+i]; }
    a=ra; b=rb; c=rc; d=rd;
}

__global__ __launch_bounds__(256)
void ln_attn_kernel(const float2* __restrict__ O, const float2* __restrict__ query,
                    const float2* __restrict__ x,
                    const float* __restrict__ g, const float* __restrict__ bta,
                    float2* __restrict__ X2, bf16* __restrict__ X2g)
{
    __shared__ float sh[32];
    const long base = (long)blockIdx.x*DD;
    const float inv = 1.f/DD;
    float2 v[4]; float sr=0,sq=0,si=0,qi=0;
    #pragma unroll
    for (int i=0;i<2;i++){
        int d = 2*(threadIdx.x + i*256);
        float4 o = *(const float4*)(O + base + d);
        float4 q = *(const float4*)(query + base + d);
        v[2*i]   = make_float2(o.x+q.x, o.y+q.y);
        v[2*i+1] = make_float2(o.z+q.z, o.w+q.w);
        sr+=v[2*i].x+v[2*i+1].x; sq+=v[2*i].x*v[2*i].x+v[2*i+1].x*v[2*i+1].x;
        si+=v[2*i].y+v[2*i+1].y; qi+=v[2*i].y*v[2*i].y+v[2*i+1].y*v[2*i+1].y;
    }
    reduce4(sr,sq,si,qi,sh);
    float mr=sr*inv, mi=si*inv;
    float rr=rsqrtf(sq*inv-mr*mr+LN_EPS), ri=rsqrtf(qi*inv-mi*mi+LN_EPS);
    float2 u[4]; float s2=0,q2=0,s3=0,q3=0;
    #pragma unroll
    for (int i=0;i<2;i++){
        int d = 2*(threadIdx.x + i*256);
        float2 gr = *(const float2*)(g + d);
        float2 gi2 = *(const float2*)(g + DD + d);
        float2 br = *(const float2*)(bta + d);
        float2 bi2 = *(const float2*)(bta + DD + d);
        float4 xx = *(const float4*)(x + base + d);
        float tr0=(v[2*i].x-mr)*rr*gr.x+br.x,   ti0=(v[2*i].y-mi)*ri*gi2.x+bi2.x;
        float tr1=(v[2*i+1].x-mr)*rr*gr.y+br.y, ti1=(v[2*i+1].y-mi)*ri*gi2.y+bi2.y;
        u[2*i]   = make_float2(xx.x+tr0, xx.y+ti0);
        u[2*i+1] = make_float2(xx.z+tr1, xx.w+ti1);
        s2+=u[2*i].x+u[2*i+1].x; q2+=u[2*i].x*u[2*i].x+u[2*i+1].x*u[2*i+1].x;
        s3+=u[2*i].y+u[2*i+1].y; q3+=u[2*i].y*u[2*i].y+u[2*i+1].y*u[2*i+1].y;
    }
    reduce4(s2,q2,s3,q3,sh);
    float m2=s2*inv, m3=s3*inv;
    float r2=rsqrtf(q2*inv-m2*m2+LN_EPS), r3=rsqrtf(q3*inv-m3*m3+LN_EPS);
    const float *g1=g+2*DD, *b1=bta+2*DD;
    #pragma unroll
    for (int i=0;i<2;i++){
        int d = 2*(threadIdx.x + i*256);
        float2 gr = *(const float2*)(g1 + d);
        float2 gi2 = *(const float2*)(g1 + DD + d);
        float2 br = *(const float2*)(b1 + d);
        float2 bi2 = *(const float2*)(b1 + DD + d);
        float y0r=(u[2*i].x-m2)*r2*gr.x+br.x,   y0i=(u[2*i].y-m3)*r3*gi2.x+bi2.x;
        float y1r=(u[2*i+1].x-m2)*r2*gr.y+br.y, y1i=(u[2*i+1].y-m3)*r3*gi2.y+bi2.y;
        float4 o4; o4.x=y0r; o4.y=y0i; o4.z=y1r; o4.w=y1i;
        *(float4*)(X2 + base + d) = o4;
        float c0[3] = { y0r, y0i, y0r + y0i };
        float c1[3] = { y1r, y1i, y1r + y1i };
        bf16* eb = X2g + (long)blockIdx.x*9216 + d;
        #pragma unroll
        for (int c=0;c<3;c++){
            uint32_t h = pk2(c0[c], c1[c]);
            uint32_t l = pk2(flo(c0[c]), flo(c1[c]));
            bf16* b = eb + c*3072;
            *(uint32_t*)(b)        = h;
            *(uint32_t*)(b + 1024) = l;
            *(uint32_t*)(b + 2048) = h;
        }
    }
}

__global__ __launch_bounds__(256)
void ln_final_kernel(const float2* __restrict__ X2, const float* __restrict__ Pp,
                     const float2* __restrict__ bpr,
                     const float* __restrict__ g, const float* __restrict__ bta,
                     float2* __restrict__ out)
{
    __shared__ float sh[32];
    const long base = (long)blockIdx.x*DD;
    const long S = (long)MR*1024;
    const float inv = 1.f/DD;
    float2 v[4]; float sr=0,sq=0,si=0,qi=0;
    #pragma unroll
    for (int i=0;i<4;i++){
        int d = threadIdx.x + i*256;
        long fi = base + d;
        float P1 = Pp[fi] + Pp[S+fi];
        float P2 = Pp[2*S+fi] + Pp[3*S+fi];
        float P3 = Pp[4*S+fi] + Pp[5*S+fi];
        float2 a = X2[fi]; float2 bb = bpr[d];
        v[i] = make_float2(a.x + (P1 - P2) + bb.x,
                           a.y + (P3 - P1 - P2) + bb.y);
        sr+=v[i].x; sq+=v[i].x*v[i].x; si+=v[i].y; qi+=v[i].y*v[i].y;
    }
    reduce4(sr,sq,si,qi,sh);
    float mr=sr*inv, mi=si*inv;
    float rr=rsqrtf(sq*inv-mr*mr+LN_EPS), ri=rsqrtf(qi*inv-mi*mi+LN_EPS);
    const float *g2=g+4*DD, *b2=bta+4*DD;
    #pragma unroll
    for (int i=0;i<4;i++){
        int d = threadIdx.x + i*256;
        out[base+d]=make_float2((v[i].x-mr)*rr*g2[d]+b2[d], (v[i].y-mi)*ri*g2[DD+d]+b2[DD+d]);
    }
}

// ---------------- host ----------------
static GP mkgp(const bf16* A, const bf16* A2, long lda, const bf16* B, long ldb, int kC,
               float2* C, long ldc, const float2* bias, float scale,
               int zdiv, long sA1, long sA2, long sB1, long sB2, long sC1, long sC2)
{
    GP p = {};
    p.A=A; p.A2=A2; p.B=B; p.lda=lda; p.ldb=ldb; p.kC=kC;
    p.C=C; p.ldc=ldc; p.bias=bias; p.scale=scale; p.zdiv=zdiv;
    p.sA1=sA1; p.sA2=sA2; p.sB1=sB1; p.sB2=sB2; p.sC1=sC1; p.sC2=sC2;
    return p;
}

extern "C" void kernel_launch(void* const* d_in, const int* in_sizes, int n_in,
                              void* d_out, int out_size)
{
    const float2* x     = (const float2*)d_in[0];
    const float2* query = (const float2*)d_in[1];
    const float2* wq    = (const float2*)d_in[2];
    const float2* bq    = (const float2*)d_in[3];
    const float2* wk    = (const float2*)d_in[4];
    const float2* bk    = (const float2*)d_in[5];
    const float2* wv    = (const float2*)d_in[6];
    const float2* bv    = (const float2*)d_in[7];
    const float2* wfc   = (const float2*)d_in[8];
    const float2* bfc   = (const float2*)d_in[9];
    const float2* wpr   = (const float2*)d_in[10];
    const float2* bpr   = (const float2*)d_in[11];
    const float*  lng   = (const float*)d_in[12];
    const float*  lnb   = (const float*)d_in[13];

    char* pool;
    cudaGetSymbolAddress((void**)&pool, g_pool);
    bf16 *Qg   = (bf16*)(pool + O_QG),   *Xg   = (bf16*)(pool + O_XG);
    bf16 *X2g  = (bf16*)(pool + O_X2G),  *Hmg  = (bf16*)(pool + O_HMG);
    bf16 *Wqkv = (bf16*)(pool + O_WQKV), *Wfcg = (bf16*)(pool + O_WFCG);
    bf16 *Wpg  = (bf16*)(pool + O_WPG);
    bf16 *Qa   = (bf16*)(pool + O_QA),   *Kb   = (bf16*)(pool + O_KB);
    bf16 *Vb   = (bf16*)(pool + O_VB),   *Pa   = (bf16*)(pool + O_PA);
    float *Pq  = (float*)(pool + O_PQ),  *Pfc  = (float*)(pool + O_PFC);
    float *Pp  = (float*)(pool + O_PP);
    float2 *O  = (float2*)(pool + O_OO), *X2   = (float2*)(pool + O_X2);
    float2 *Sc = (float2*)(pool + O_SC);

    cudaFuncSetAttribute(tgemm<0>, cudaFuncAttributeMaxDynamicSharedMemorySize, SMB);
    cudaFuncSetAttribute(tgemm<6>, cudaFuncAttributeMaxDynamicSharedMemorySize, SMB);
    cudaFuncSetAttribute(tgemm<8>, cudaFuncAttributeMaxDynamicSharedMemorySize, SMB);

    // expansions
    expandAG2<<<16384,256>>>(query, x, Qg, Xg);
    expandWG2<<<22528,256>>>(wq, wk, wv, wfc, wpr, Wqkv, Wfcg, Wpg);

    // QKV Gauss: grid (8,32,9); z = inp*3 + product; z<3 uses Qg else Xg. kC=48.
    tgemm<6><<<dim3(8,32,9),256,SMB>>>(mkgp(Qg, Xg, 9216, Wqkv, 9216, 48,
        (float2*)Pq, 512, nullptr, 1.f,
        3, 0, 3072, (long)1024*9216, 3072, 3L*MR*512, (long)MR*512));
    cqk4<<<8192,256>>>(Pq, bq, bk, Qa, Kb);
    cvb_t<<<dim3(16,2,128),256>>>(Pq, bv, Vb);

    // scores: per z=(b,h): [512 x 1024'], K_eff=384 (kC=6)
    tgemm<0><<<dim3(8,4,128),256,SMB>>>(mkgp(Qa, Qa, 384, Kb, 384, 6,
        Sc, 512, nullptr, 0.125f,
        1, 512L*384, 0, 1024L*384, 0, 512L*512, 0));
    softmax_kernel<<<128*512/8,256>>>(Sc, Pa);

    // AV: per z: [512 x 128'], A = Pa [h|l] (lda=2048) with MODE-8 section remap; kC=48.
    tgemm<8><<<dim3(1,4,128),256,SMB>>>(mkgp(Pa, Pa, 2048, Vb, 3072, 48,
        O, 1024, nullptr, 1.f,
        16, 16L*512*2048, 512L*2048, 16L*128*3072, 128L*3072, 512L*1024, 64));

    ln_attn_kernel<<<MR,256>>>(O, query, x, lng, lnb, X2, X2g);

    // fc Gauss: grid (32,32,3); z = product. kC=48.
    tgemm<6><<<dim3(32,32,3),256,SMB>>>(mkgp(X2g, X2g, 9216, Wfcg, 9216, 48,
        (float2*)Pfc, 2048, nullptr, 1.f,
        3, 0, 3072, 0, 3072, 0, (long)MR*2048));
    cfc4<<<16384,256>>>(Pfc, bfc, Hmg);

    // proj Gauss + split-K x2: grid (8,32,6); z = product*2 + khalf. kC=96.
    tgemm<6><<<dim3(8,32,6),256,SMB>>>(mkgp(Hmg, Hmg, 36864, Wpg, 36864, 96,
        (float2*)Pp, 512, nullptr, 1.f,
        2, 12288, 6144, 12288, 6144, 2L*MR*512, (long)MR*512));

    ln_final_kernel<<<MR,256>>>(X2, Pp, bpr, lng, lnb, (float2*)d_out);
}

// round 14
// speedup vs baseline: 3.7707x; 1.0074x over previous
#include <cuda_runtime.h>
#include <cuda_bf16.h>
#include <cstdint>
#include <math.h>

typedef __nv_bfloat16 bf16;
typedef __nv_bfloat162 bf162;

#define DD 1024
#define MR 4096
#define LN_EPS 1e-5f

// ---------------- pooled scratch (single symbol, lifetime-aliased) ----------------
constexpr size_t O_QG   = 0;
constexpr size_t O_XG   = O_QG  + (size_t)MR*9216*2;
constexpr size_t O_X2G  = O_XG  + (size_t)MR*9216*2;
constexpr size_t O_WQKV = O_X2G + (size_t)MR*9216*2;
constexpr size_t O_WFCG = O_WQKV + (size_t)3*1024*9216*2;
constexpr size_t O_WPG  = O_WFCG + (size_t)4096*9216*2;
constexpr size_t O_QA   = O_WPG  + (size_t)1024*36864*2;
constexpr size_t O_KB   = O_QA   + (size_t)128*512*384*2;
constexpr size_t O_VB   = O_KB   + (size_t)128*1024*384*2;
constexpr size_t O_PA   = O_VB   + (size_t)128*128*3072*2;
constexpr size_t O_OO   = O_PA   + (size_t)128*512*3072*2;
constexpr size_t O_X2   = O_OO   + (size_t)MR*DD*8;
constexpr size_t O_HMG  = O_X2   + (size_t)MR*DD*8;
constexpr size_t O_SC   = O_HMG  + (size_t)MR*36864*2;
constexpr size_t POOLSZ = O_SC   + (size_t)128*512*512*8;
// aliases (disjoint lifetimes in launch order):
constexpr size_t O_PQ  = O_HMG;  // Pq dead after cqk4/cvb_t; Hmg written at cfc
constexpr size_t O_PFC = O_SC;   // Pfc written at fc;  Sc dead after softmax
constexpr size_t O_PP  = O_PA;   // Pp (9 x 16.8MB = 151MB) fits Pa region (402MB); Pa dead after AV

__device__ __align__(256) char g_pool[POOLSZ];

// ---------------- helpers ----------------
__device__ __forceinline__ uint32_t s2u(const void* p){
    uint32_t a;
    asm("{ .reg .u64 t; cvta.to.shared.u64 t, %1; cvt.u32.u64 %0, t; }":"=r"(a):"l"(p));
    return a;
}
__device__ __forceinline__ void cpa16(uint32_t d, const void* g){
    asm volatile("cp.async.cg.shared.global [%0], [%1], 16;"::"r"(d),"l"(g));
}
__device__ __forceinline__ void split1(float v, bf16& h, bf16& l){
    h = __float2bfloat16_rn(v);
    l = __float2bfloat16_rn(v - __bfloat162float(h));
}
__device__ __forceinline__ void split2(float vr, float vi, bf162& h, bf162& l){
    split1(vr, h.x, l.x); split1(vi, h.y, l.y);
}
__device__ __forceinline__ float flo(float v){
    return v - __bfloat162float(__float2bfloat16_rn(v));
}
__device__ __forceinline__ uint32_t pk2(float a, float b){
    bf162 t; t.x=__float2bfloat16_rn(a); t.y=__float2bfloat16_rn(b);
    return *(uint32_t*)&t;
}
__device__ __forceinline__ void ldm4(uint32_t* r, uint32_t a){
    asm volatile("ldmatrix.sync.aligned.m8n8.x4.shared.b16 {%0,%1,%2,%3}, [%4];"
        :"=r"(r[0]),"=r"(r[1]),"=r"(r[2]),"=r"(r[3]):"r"(a));
}
__device__ __forceinline__ void mma16816(float* d, const uint32_t* a, uint32_t b0, uint32_t b1){
    asm volatile("mma.sync.aligned.m16n8k16.row.col.f32.bf16.bf16.f32 "
        "{%0,%1,%2,%3}, {%4,%5,%6,%7}, {%8,%9}, {%0,%1,%2,%3};"
        :"+f"(d[0]),"+f"(d[1]),"+f"(d[2]),"+f"(d[3])
        :"r"(a[0]),"r"(a[1]),"r"(a[2]),"r"(a[3]),"r"(b0),"r"(b1));
}

// ---------------- GEMM via mma.sync ----------------
// MODE 0: attention GEMM, float2 C; MODE 6: Gauss product GEMM; MODE 8: like 0 but
// A K-sections remapped [h|l|h] over physical [h|l] (lda=2048): sec {0,1024,0} per 16 chunks.
struct GP {
    const bf16 *A, *A2, *B;
    long lda, ldb;
    long sA1, sA2, sB1, sB2;
    float2* C; long ldc, sC1, sC2;
    const float2* bias;
    int zdiv, kC;
    float scale;
};
#define ROWB 144
#define ASZ  (128*ROWB)
#define STB  (2*ASZ)
#define SMB  (3*STB)

template<int MODE>
__global__ __launch_bounds__(256,2) void tgemm(GP p)
{
    extern __shared__ __align__(256) char sm[];
    uint32_t TILE = s2u(sm);
    const int tid = threadIdx.x, lane = tid & 31, wid = tid >> 5;
    const int warpM = wid & 3, warpN = wid >> 2;

    const int z = blockIdx.z;
    const bf16* Ap = (MODE == 6 && z >= 3) ? p.A2 : p.A;
    const long offA = (z/p.zdiv)*p.sA1 + (z%p.zdiv)*p.sA2;
    const long offB = (z/p.zdiv)*p.sB1 + (z%p.zdiv)*p.sB2;
    const bf16* Ag = Ap + offA + (long)blockIdx.y*128*p.lda;
    const bf16* Bg = p.B + offB + (long)blockIdx.x*128*p.ldb;

    auto loadStage = [&](int c){
        uint32_t st = TILE + (c%3)*STB;
        long kofB = (long)c*64;
        long kofA = kofB;
        if (MODE == 8) kofA = (((c>>4)==1) ? 1024L : 0L) + (long)(c&15)*64;
        #pragma unroll
        for (int i=0;i<4;i++){
            int idx = tid + i*256; int r = idx>>3, cc = idx&7;
            cpa16(st + r*ROWB + cc*16, Ag + (long)r*p.lda + kofA + cc*8);
        }
        #pragma unroll
        for (int i=0;i<4;i++){
            int idx = tid + i*256; int r = idx>>3, cc = idx&7;
            cpa16(st + ASZ + r*ROWB + cc*16, Bg + (long)r*p.ldb + kofB + cc*8);
        }
        asm volatile("cp.async.commit_group;":::"memory");
    };

    float acc[2][8][4];
    #pragma unroll
    for (int mf=0;mf<2;mf++)
        #pragma unroll
        for (int nf=0;nf<8;nf++)
            #pragma unroll
            for (int t=0;t<4;t++) acc[mf][nf][t] = 0.f;

    loadStage(0);
    if (p.kC > 1) loadStage(1);

    const uint32_t aRel = (uint32_t)((warpM*32 + (lane&15))*ROWB + (lane>>4)*16);
    const uint32_t bRel = (uint32_t)(ASZ + (warpN*64 + (lane&7))*ROWB + ((lane>>3)&3)*16);

    for (int c = 0; c < p.kC; c++) {
        if (c+1 < p.kC) asm volatile("cp.async.wait_group 1;":::"memory");
        else            asm volatile("cp.async.wait_group 0;":::"memory");
        __syncthreads();
        if (c+2 < p.kC) loadStage(c+2);

        uint32_t st = TILE + (c%3)*STB;
        uint32_t aB = st + aRel, bB = st + bRel;
        #pragma unroll
        for (int kh=0; kh<2; kh++){
            uint32_t bfr[8][4];
            #pragma unroll
            for (int nf=0; nf<8; nf++) ldm4(bfr[nf], bB + nf*(8*ROWB) + kh*64);
            #pragma unroll
            for (int s=0; s<2; s++){
                int ks = kh*2 + s;
                uint32_t af[2][4];
                #pragma unroll
                for (int mf=0; mf<2; mf++) ldm4(af[mf], aB + mf*(16*ROWB) + ks*32);
                #pragma unroll
                for (int mf=0; mf<2; mf++)
                    #pragma unroll
                    for (int nf=0; nf<8; nf++)
                        mma16816(acc[mf][nf], af[mf], bfr[nf][s*2], bfr[nf][s*2+1]);
            }
        }
    }

    const long coff = (z/p.zdiv)*p.sC1 + (z%p.zdiv)*p.sC2;
    const int ncBase = blockIdx.x*64 + warpN*32 + (lane&3);
    #pragma unroll
    for (int mf=0; mf<2; mf++){
        long r0 = (long)blockIdx.y*128 + warpM*32 + mf*16 + (lane>>2);
        #pragma unroll
        for (int nf=0; nf<8; nf++){
            int nc = ncBase + nf*4;
            float2 bb = ((MODE==0||MODE==8) && p.bias) ? p.bias[nc] : make_float2(0.f,0.f);
            #pragma unroll
            for (int h2=0; h2<2; h2++){
                long m = r0 + h2*8;
                float cr = acc[mf][nf][2*h2]   * p.scale + bb.x;
                float ci = acc[mf][nf][2*h2+1] * p.scale + bb.y;
                p.C[coff + m*p.ldc + nc] = make_float2(cr, ci);
            }
        }
    }
}

// ---------------- expansions (paired, vectorized) ----------------
__global__ __launch_bounds__(256) void expandAG2(const float2* __restrict__ q,
                                                 const float2* __restrict__ x,
                                                 bf16* __restrict__ Qg, bf16* __restrict__ Xg)
{
    long bid = blockIdx.x;
    const float2* src = q; bf16* dst = Qg;
    if (bid >= 8192) { bid -= 8192; src = x; dst = Xg; }
    long pidx = bid*256 + threadIdx.x;
    long m = pidx >> 9; int k = (int)(pidx & 511) * 2;
    float4 vv = *(const float4*)(src + m*1024 + k);
    float c0[3] = { vv.x, vv.y, vv.x + vv.y };
    float c1[3] = { vv.z, vv.w, vv.z + vv.w };
    bf16* base = dst + m*9216 + k;
    #pragma unroll
    for (int c=0;c<3;c++){
        uint32_t h = pk2(c0[c], c1[c]);
        uint32_t l = pk2(flo(c0[c]), flo(c1[c]));
        bf16* b = base + c*3072;
        *(uint32_t*)(b)        = h;
        *(uint32_t*)(b + 1024) = l;
        *(uint32_t*)(b + 2048) = h;
    }
}
__global__ __launch_bounds__(256) void expandWG2(
    const float2* __restrict__ wq, const float2* __restrict__ wk, const float2* __restrict__ wv,
    const float2* __restrict__ wfc, const float2* __restrict__ wpr,
    bf16* __restrict__ Wqkv, bf16* __restrict__ Wfcg, bf16* __restrict__ Wpg)
{
    long bid = blockIdx.x;
    const float2* W; bf16* out; int K; long rstride;
    if      (bid < 2048)  { W=wq;  out=Wqkv;                    K=1024; rstride=9216; }
    else if (bid < 4096)  { W=wk;  out=Wqkv+(size_t)1024*9216;  K=1024; rstride=9216; bid-=2048; }
    else if (bid < 6144)  { W=wv;  out=Wqkv+(size_t)2048*9216;  K=1024; rstride=9216; bid-=4096; }
    else if (bid < 14336) { W=wfc; out=Wfcg;                    K=1024; rstride=9216; bid-=6144; }
    else                  { W=wpr; out=Wpg;                     K=4096; rstride=36864; bid-=14336; }
    long pidx = bid*256 + threadIdx.x;
    int Kp = K >> 1;
    long n = pidx / Kp; int k = (int)(pidx % Kp) * 2;
    float4 ww = *(const float4*)(W + n*K + k);
    float c0[3] = { ww.x, ww.y, ww.x + ww.y };
    float c1[3] = { ww.z, ww.w, ww.z + ww.w };
    bf16* base = out + n*rstride + k;
    #pragma unroll
    for (int c=0;c<3;c++){
        uint32_t h = pk2(c0[c], c1[c]);
        uint32_t l = pk2(flo(c0[c]), flo(c1[c]));
        bf16* b = base + (long)c*3*K;
        *(uint32_t*)(b)       = h;
        *(uint32_t*)(b + K)   = h;
        *(uint32_t*)(b + 2*K) = l;
    }
}

// ---------------- Q/K combine (quad, coalesced stores) ----------------
__global__ __launch_bounds__(256) void cqk4(const float* __restrict__ Pq,
                                            const float2* __restrict__ bq,
                                            const float2* __restrict__ bk,
                                            bf16* __restrict__ Qa, bf16* __restrict__ Kb)
{
    long bid = blockIdx.x;
    int q3 = (int)(bid >> 12); bid &= 4095;     // q3 in {0,1}
    long qidx = bid*256 + threadIdx.x;
    long m = qidx >> 8; int n = (int)(qidx & 255) * 4;
    const long MN = (long)MR*1024;
    const float* P = Pq + (long)q3*3*MN;
    long e = m*1024 + n;
    float4 p0 = *(const float4*)(P + e);
    float4 p1 = *(const float4*)(P + MN + e);
    float4 p2 = *(const float4*)(P + 2*MN + e);
    const float2* bi = (q3==0) ? bq : bk;
    float4 b01 = *(const float4*)(bi + n);
    float4 b23 = *(const float4*)(bi + n + 2);
    float yr[4], yi[4];
    yr[0]=p0.x-p1.x+b01.x; yi[0]=p2.x-p0.x-p1.x+b01.y;
    yr[1]=p0.y-p1.y+b01.z; yi[1]=p2.y-p0.y-p1.y+b01.w;
    yr[2]=p0.z-p1.z+b23.x; yi[2]=p2.z-p0.z-p1.z+b23.y;
    yr[3]=p0.w-p1.w+b23.z; yi[3]=p2.w-p0.w-p1.w+b23.w;

    int b=(int)(m>>9), s=(int)(m&511), hh=n>>6, d=n&63;
    long zz = b*16 + hh;
    if (q3 == 0) {
        uint4 H, L;
        H.x=pk2(yr[0],yi[0]); H.y=pk2(yr[1],yi[1]); H.z=pk2(yr[2],yi[2]); H.w=pk2(yr[3],yi[3]);
        L.x=pk2(flo(yr[0]),flo(yi[0])); L.y=pk2(flo(yr[1]),flo(yi[1]));
        L.z=pk2(flo(yr[2]),flo(yi[2])); L.w=pk2(flo(yr[3]),flo(yi[3]));
        bf16* base = Qa + (zz*512 + s)*384 + 2*d;
        *(uint4*)(base)       = H;
        *(uint4*)(base + 128) = L;
        *(uint4*)(base + 256) = H;
    } else {
        uint4 H0, L0, H1, L1;
        #pragma unroll
        for (int j=0;j<4;j++){
            ((uint32_t*)&H0)[j] = pk2(yr[j], -yi[j]);
            ((uint32_t*)&L0)[j] = pk2(flo(yr[j]), flo(-yi[j]));
            ((uint32_t*)&H1)[j] = pk2(yi[j], yr[j]);
            ((uint32_t*)&L1)[j] = pk2(flo(yi[j]), flo(yr[j]));
        }
        bf16* r0p = Kb + (zz*1024 + 2*s)*384 + 2*d;
        bf16* r1p = r0p + 384;
        *(uint4*)(r0p)       = H0; *(uint4*)(r0p + 128) = H0; *(uint4*)(r0p + 256) = L0;
        *(uint4*)(r1p)       = H1; *(uint4*)(r1p + 128) = H1; *(uint4*)(r1p + 256) = L1;
    }
}

// ---------------- V combine: smem-staged transpose, coalesced writes ----------------
__global__ __launch_bounds__(256) void cvb_t(const float* __restrict__ Pq,
                                             const float2* __restrict__ bv,
                                             bf16* __restrict__ Vb)
{
    __shared__ float syr[32][33], syi[32][33];
    const int zz = blockIdx.z, s0 = blockIdx.x*32, d0 = blockIdx.y*32;
    const int b = zz >> 4, h = zz & 15;
    const long MN = (long)MR*1024;
    const float* P = Pq + 2L*3*MN;          // q3 = 2 (V products)
    const int tl = threadIdx.x & 31, tw = threadIdx.x >> 5;

    #pragma unroll
    for (int r=0;r<4;r++){
        int sl = tw + 8*r;
        long e = ((long)(b*512 + s0 + sl))*1024 + h*64 + d0 + tl;
        float p0 = P[e], p1 = P[MN+e], p2 = P[2*MN+e];
        float2 bb = bv[h*64 + d0 + tl];
        syr[sl][tl] = p0 - p1 + bb.x;
        syi[sl][tl] = p2 - p0 - p1 + bb.y;
    }
    __syncthreads();

    #pragma unroll
    for (int r=0;r<4;r++){
        int dl = tw + 8*r;
        float yr = syr[tl][dl], yi = syi[tl][dl];
        uint32_t h0 = pk2(yr, -yi), l0 = pk2(flo(yr), flo(-yi));
        uint32_t h1 = pk2(yi, yr),  l1 = pk2(flo(yi), flo(yr));
        bf16* r0p = Vb + ((long)zz*128 + 2*(d0+dl))*3072 + 2*(s0+tl);
        bf16* r1p = r0p + 3072;
        *(uint32_t*)(r0p)        = h0;
        *(uint32_t*)(r0p + 1024) = h0;
        *(uint32_t*)(r0p + 2048) = l0;
        *(uint32_t*)(r1p)        = h1;
        *(uint32_t*)(r1p + 1024) = h1;
        *(uint32_t*)(r1p + 2048) = l1;
    }
}

// ---------------- fc combine (quad) ----------------
__global__ __launch_bounds__(256) void cfc4(const float* __restrict__ Pfc,
                                            const float2* __restrict__ bfc,
                                            bf16* __restrict__ Hmg)
{
    long qidx = (long)blockIdx.x*256 + threadIdx.x;
    long m = qidx >> 10; int n = (int)(qidx & 1023) * 4;
    const long MN = (long)MR*4096;
    long e = m*4096 + n;
    float4 p0 = *(const float4*)(Pfc + e);
    float4 p1 = *(const float4*)(Pfc + MN + e);
    float4 p2 = *(const float4*)(Pfc + 2*MN + e);
    float4 b01 = *(const float4*)(bfc + n);
    float4 b23 = *(const float4*)(bfc + n + 2);
    float yr[4], yi[4];
    yr[0]=p0.x-p1.x+b01.x; yi[0]=p2.x-p0.x-p1.x+b01.y;
    yr[1]=p0.y-p1.y+b01.z; yi[1]=p2.y-p0.y-p1.y+b01.w;
    yr[2]=p0.z-p1.z+b23.x; yi[2]=p2.z-p0.z-p1.z+b23.y;
    yr[3]=p0.w-p1.w+b23.z; yi[3]=p2.w-p0.w-p1.w+b23.w;
    float cs[3][4];
    #pragma unroll
    for (int j=0;j<4;j++){
        float mg = sqrtf(yr[j]*yr[j] + yi[j]*yi[j]);
        float r = 0.5f*(yr[j] + mg), ii = 0.5f*yi[j];
        cs[0][j] = r; cs[1][j] = ii; cs[2][j] = r + ii;
    }
    bf16* base = Hmg + m*36864 + n;
    #pragma unroll
    for (int c=0;c<3;c++){
        uint2 H, L;
        H.x = pk2(cs[c][0], cs[c][1]); H.y = pk2(cs[c][2], cs[c][3]);
        L.x = pk2(flo(cs[c][0]), flo(cs[c][1])); L.y = pk2(flo(cs[c][2]), flo(cs[c][3]));
        bf16* b = base + c*12288;
        *(uint2*)(b)        = H;
        *(uint2*)(b + 4096) = L;
        *(uint2*)(b + 8192) = H;
    }
}

// ---------------- softmax + probs expansion ([h|l] layout, width 2048) ----------------
__global__ __launch_bounds__(256) void softmax_kernel(const float2* __restrict__ Sc, bf16* __restrict__ Pa)
{
    long rid = (long)blockIdx.x*8 + (threadIdx.x>>5);
    int lane = threadIdx.x & 31;
    const float2* r = Sc + rid*512;
    float2 v[16]; float mx=-1e30f, my=-1e30f;
    #pragma unroll
    for (int i=0;i<16;i++){ v[i]=r[lane+32*i]; mx=fmaxf(mx,v[i].x); my=fmaxf(my,v[i].y); }
    #pragma unroll
    for (int o=16;o>0;o>>=1){ mx=fmaxf(mx,__shfl_xor_sync(~0u,mx,o)); my=fmaxf(my,__shfl_xor_sync(~0u,my,o)); }
    float sx=0.f, sy=0.f;
    #pragma unroll
    for (int i=0;i<16;i++){ v[i].x=__expf(v[i].x-mx); v[i].y=__expf(v[i].y-my); sx+=v[i].x; sy+=v[i].y; }
    #pragma unroll
    for (int o=16;o>0;o>>=1){ sx+=__shfl_xor_sync(~0u,sx,o); sy+=__shfl_xor_sync(~0u,sy,o); }
    float ix=1.f/sx, iy=1.f/sy;
    bf16* base = Pa + rid*2048;
    #pragma unroll
    for (int i=0;i<16;i++){
        int k = lane + 32*i;
        bf162 h,l; split2(v[i].x*ix, v[i].y*iy, h, l);
        *(bf162*)(base+2*k)=h; *(bf162*)(base+1024+2*k)=l;
    }
}

// ---------------- layernorms ----------------
__device__ __forceinline__ void reduce4(float& a, float& b, float& c, float& d, float* sh)
{
    #pragma unroll
    for (int o=16;o>0;o>>=1){
        a+=__shfl_xor_sync(~0u,a,o); b+=__shfl_xor_sync(~0u,b,o);
        c+=__shfl_xor_sync(~0u,c,o); d+=__shfl_xor_sync(~0u,d,o);
    }
    int w = threadIdx.x>>5;
    __syncthreads();
    if ((threadIdx.x&31)==0){ sh[w]=a; sh[8+w]=b; sh[16+w]=c; sh[24+w]=d; }
    __syncthreads();
    float ra=0,rb=0,rc=0,rd=0;
    #pragma unroll
    for (int i=0;i<8;i++){ ra+=sh[i]; rb+=sh[8+i]; rc+=sh[16+i]; rd+=sh[24+i]; }
    a=ra; b=rb; c=rc; d=rd;
}

__global__ __launch_bounds__(256)
void ln_attn_kernel(const float2* __restrict__ O, const float2* __restrict__ query,
                    const float2* __restrict__ x,
                    const float* __restrict__ g, const float* __restrict__ bta,
                    float2* __restrict__ X2, bf16* __restrict__ X2g)
{
    __shared__ float sh[32];
    const long base = (long)blockIdx.x*DD;
    const float inv = 1.f/DD;
    float2 v[4]; float sr=0,sq=0,si=0,qi=0;
    #pragma unroll
    for (int i=0;i<2;i++){
        int d = 2*(threadIdx.x + i*256);
        float4 o = *(const float4*)(O + base + d);
        float4 q = *(const float4*)(query + base + d);
        v[2*i]   = make_float2(o.x+q.x, o.y+q.y);
        v[2*i+1] = make_float2(o.z+q.z, o.w+q.w);
        sr+=v[2*i].x+v[2*i+1].x; sq+=v[2*i].x*v[2*i].x+v[2*i+1].x*v[2*i+1].x;
        si+=v[2*i].y+v[2*i+1].y; qi+=v[2*i].y*v[2*i].y+v[2*i+1].y*v[2*i+1].y;
    }
    reduce4(sr,sq,si,qi,sh);
    float mr=sr*inv, mi=si*inv;
    float rr=rsqrtf(sq*inv-mr*mr+LN_EPS), ri=rsqrtf(qi*inv-mi*mi+LN_EPS);
    float2 u[4]; float s2=0,q2=0,s3=0,q3=0;
    #pragma unroll
    for (int i=0;i<2;i++){
        int d = 2*(threadIdx.x + i*256);
        float2 gr = *(const float2*)(g + d);
        float2 gi2 = *(const float2*)(g + DD + d);
        float2 br = *(const float2*)(bta + d);
        float2 bi2 = *(const float2*)(bta + DD + d);
        float4 xx = *(const float4*)(x + base + d);
        float tr0=(v[2*i].x-mr)*rr*gr.x+br.x,   ti0=(v[2*i].y-mi)*ri*gi2.x+bi2.x;
        float tr1=(v[2*i+1].x-mr)*rr*gr.y+br.y, ti1=(v[2*i+1].y-mi)*ri*gi2.y+bi2.y;
        u[2*i]   = make_float2(xx.x+tr0, xx.y+ti0);
        u[2*i+1] = make_float2(xx.z+tr1, xx.w+ti1);
        s2+=u[2*i].x+u[2*i+1].x; q2+=u[2*i].x*u[2*i].x+u[2*i+1].x*u[2*i+1].x;
        s3+=u[2*i].y+u[2*i+1].y; q3+=u[2*i].y*u[2*i].y+u[2*i+1].y*u[2*i+1].y;
    }
    reduce4(s2,q2,s3,q3,sh);
    float m2=s2*inv, m3=s3*inv;
    float r2=rsqrtf(q2*inv-m2*m2+LN_EPS), r3=rsqrtf(q3*inv-m3*m3+LN_EPS);
    const float *g1=g+2*DD, *b1=bta+2*DD;
    #pragma unroll
    for (int i=0;i<2;i++){
        int d = 2*(threadIdx.x + i*256);
        float2 gr = *(const float2*)(g1 + d);
        float2 gi2 = *(const float2*)(g1 + DD + d);
        float2 br = *(const float2*)(b1 + d);
        float2 bi2 = *(const float2*)(b1 + DD + d);
        float y0r=(u[2*i].x-m2)*r2*gr.x+br.x,   y0i=(u[2*i].y-m3)*r3*gi2.x+bi2.x;
        float y1r=(u[2*i+1].x-m2)*r2*gr.y+br.y, y1i=(u[2*i+1].y-m3)*r3*gi2.y+bi2.y;
        float4 o4; o4.x=y0r; o4.y=y0i; o4.z=y1r; o4.w=y1i;
        *(float4*)(X2 + base + d) = o4;
        float c0[3] = { y0r, y0i, y0r + y0i };
        float c1[3] = { y1r, y1i, y1r + y1i };
        bf16* eb = X2g + (long)blockIdx.x*9216 + d;
        #pragma unroll
        for (int c=0;c<3;c++){
            uint32_t h = pk2(c0[c], c1[c]);
            uint32_t l = pk2(flo(c0[c]), flo(c1[c]));
            bf16* b = eb + c*3072;
            *(uint32_t*)(b)        = h;
            *(uint32_t*)(b + 1024) = l;
            *(uint32_t*)(b + 2048) = h;
        }
    }
}

// out = LN2(X2 + proj), proj = Gauss from 9 partials (3 products x 3 k-thirds) + bias
__global__ __launch_bounds__(256)
void ln_final_kernel(const float2* __restrict__ X2, const float* __restrict__ Pp,
                     const float2* __restrict__ bpr,
                     const float* __restrict__ g, const float* __restrict__ bta,
                     float2* __restrict__ out)
{
    __shared__ float sh[32];
    const long base = (long)blockIdx.x*DD;
    const long S = (long)MR*1024;
    const float inv = 1.f/DD;
    float2 v[4]; float sr=0,sq=0,si=0,qi=0;
    #pragma unroll
    for (int i=0;i<4;i++){
        int d = threadIdx.x + i*256;
        long fi = base + d;
        float P1 = Pp[fi]     + Pp[S+fi]   + Pp[2*S+fi];
        float P2 = Pp[3*S+fi] + Pp[4*S+fi] + Pp[5*S+fi];
        float P3 = Pp[6*S+fi] + Pp[7*S+fi] + Pp[8*S+fi];
        float2 a = X2[fi]; float2 bb = bpr[d];
        v[i] = make_float2(a.x + (P1 - P2) + bb.x,
                           a.y + (P3 - P1 - P2) + bb.y);
        sr+=v[i].x; sq+=v[i].x*v[i].x; si+=v[i].y; qi+=v[i].y*v[i].y;
    }
    reduce4(sr,sq,si,qi,sh);
    float mr=sr*inv, mi=si*inv;
    float rr=rsqrtf(sq*inv-mr*mr+LN_EPS), ri=rsqrtf(qi*inv-mi*mi+LN_EPS);
    const float *g2=g+4*DD, *b2=bta+4*DD;
    #pragma unroll
    for (int i=0;i<4;i++){
        int d = threadIdx.x + i*256;
        out[base+d]=make_float2((v[i].x-mr)*rr*g2[d]+b2[d], (v[i].y-mi)*ri*g2[DD+d]+b2[DD+d]);
    }
}

// ---------------- host ----------------
static GP mkgp(const bf16* A, const bf16* A2, long lda, const bf16* B, long ldb, int kC,
               float2* C, long ldc, const float2* bias, float scale,
               int zdiv, long sA1, long sA2, long sB1, long sB2, long sC1, long sC2)
{
    GP p = {};
    p.A=A; p.A2=A2; p.B=B; p.lda=lda; p.ldb=ldb; p.kC=kC;
    p.C=C; p.ldc=ldc; p.bias=bias; p.scale=scale; p.zdiv=zdiv;
    p.sA1=sA1; p.sA2=sA2; p.sB1=sB1; p.sB2=sB2; p.sC1=sC1; p.sC2=sC2;
    return p;
}

extern "C" void kernel_launch(void* const* d_in, const int* in_sizes, int n_in,
                              void* d_out, int out_size)
{
    const float2* x     = (const float2*)d_in[0];
    const float2* query = (const float2*)d_in[1];
    const float2* wq    = (const float2*)d_in[2];
    const float2* bq    = (const float2*)d_in[3];
    const float2* wk    = (const float2*)d_in[4];
    const float2* bk    = (const float2*)d_in[5];
    const float2* wv    = (const float2*)d_in[6];
    const float2* bv    = (const float2*)d_in[7];
    const float2* wfc   = (const float2*)d_in[8];
    const float2* bfc   = (const float2*)d_in[9];
    const float2* wpr   = (const float2*)d_in[10];
    const float2* bpr   = (const float2*)d_in[11];
    const float*  lng   = (const float*)d_in[12];
    const float*  lnb   = (const float*)d_in[13];

    char* pool;
    cudaGetSymbolAddress((void**)&pool, g_pool);
    bf16 *Qg   = (bf16*)(pool + O_QG),   *Xg   = (bf16*)(pool + O_XG);
    bf16 *X2g  = (bf16*)(pool + O_X2G),  *Hmg  = (bf16*)(pool + O_HMG);
    bf16 *Wqkv = (bf16*)(pool + O_WQKV), *Wfcg = (bf16*)(pool + O_WFCG);
    bf16 *Wpg  = (bf16*)(pool + O_WPG);
    bf16 *Qa   = (bf16*)(pool + O_QA),   *Kb   = (bf16*)(pool + O_KB);
    bf16 *Vb   = (bf16*)(pool + O_VB),   *Pa   = (bf16*)(pool + O_PA);
    float *Pq  = (float*)(pool + O_PQ),  *Pfc  = (float*)(pool + O_PFC);
    float *Pp  = (float*)(pool + O_PP);
    float2 *O  = (float2*)(pool + O_OO), *X2   = (float2*)(pool + O_X2);
    float2 *Sc = (float2*)(pool + O_SC);

    cudaFuncSetAttribute(tgemm<0>, cudaFuncAttributeMaxDynamicSharedMemorySize, SMB);
    cudaFuncSetAttribute(tgemm<6>, cudaFuncAttributeMaxDynamicSharedMemorySize, SMB);
    cudaFuncSetAttribute(tgemm<8>, cudaFuncAttributeMaxDynamicSharedMemorySize, SMB);

    // expansions
    expandAG2<<<16384,256>>>(query, x, Qg, Xg);
    expandWG2<<<22528,256>>>(wq, wk, wv, wfc, wpr, Wqkv, Wfcg, Wpg);

    // QKV Gauss: grid (8,32,9); z = inp*3 + product; z<3 uses Qg else Xg. kC=48.
    tgemm<6><<<dim3(8,32,9),256,SMB>>>(mkgp(Qg, Xg, 9216, Wqkv, 9216, 48,
        (float2*)Pq, 512, nullptr, 1.f,
        3, 0, 3072, (long)1024*9216, 3072, 3L*MR*512, (long)MR*512));
    cqk4<<<8192,256>>>(Pq, bq, bk, Qa, Kb);
    cvb_t<<<dim3(16,2,128),256>>>(Pq, bv, Vb);

    // scores: per z=(b,h): [512 x 1024'], K_eff=384 (kC=6)
    tgemm<0><<<dim3(8,4,128),256,SMB>>>(mkgp(Qa, Qa, 384, Kb, 384, 6,
        Sc, 512, nullptr, 0.125f,
        1, 512L*384, 0, 1024L*384, 0, 512L*512, 0));
    softmax_kernel<<<128*512/8,256>>>(Sc, Pa);

    // AV: per z: [512 x 128'], A = Pa [h|l] (lda=2048) with MODE-8 section remap; kC=48.
    tgemm<8><<<dim3(1,4,128),256,SMB>>>(mkgp(Pa, Pa, 2048, Vb, 3072, 48,
        O, 1024, nullptr, 1.f,
        16, 16L*512*2048, 512L*2048, 16L*128*3072, 128L*3072, 512L*1024, 64));

    ln_attn_kernel<<<MR,256>>>(O, query, x, lng, lnb, X2, X2g);

    // fc Gauss: grid (32,32,3); z = product. kC=48.
    tgemm<6><<<dim3(32,32,3),256,SMB>>>(mkgp(X2g, X2g, 9216, Wfcg, 9216, 48,
        (float2*)Pfc, 2048, nullptr, 1.f,
        3, 0, 3072, 0, 3072, 0, (long)MR*2048));
    cfc4<<<16384,256>>>(Pfc, bfc, Hmg);

    // proj Gauss + split-K x3: grid (8,32,9); z = product*3 + kthird; kC=64.
    // k-thirds align with the 4096-wide [h|l|h]/[h|h|l] sections exactly.
    tgemm<6><<<dim3(8,32,9),256,SMB>>>(mkgp(Hmg, Hmg, 36864, Wpg, 36864, 64,
        (float2*)Pp, 512, nullptr, 1.f,
        3, 12288, 4096, 12288, 4096, 3L*MR*512, (long)MR*512));

    ln_final_kernel<<<MR,256>>>(X2, Pp, bpr, lng, lnb, (float2*)d_out);
}

// round 15
// speedup vs baseline: 3.7942x; 1.0062x over previous
#include <cuda_runtime.h>
#include <cuda_bf16.h>
#include <cstdint>
#include <math.h>

typedef __nv_bfloat16 bf16;
typedef __nv_bfloat162 bf162;

#define DD 1024
#define MR 4096
#define LN_EPS 1e-5f

// ---------------- pooled scratch (deduped layouts: A=[h|l], B=[h|l]) ----------------
constexpr size_t O_QG   = 0;                                      // MR x 6144 (3 comps x [h|l])
constexpr size_t O_XG   = O_QG   + (size_t)MR*6144*2;
constexpr size_t O_X2G  = O_XG   + (size_t)MR*6144*2;
constexpr size_t O_WQKV = O_X2G  + (size_t)MR*6144*2;             // 3 x 1024 x 6144
constexpr size_t O_WFCG = O_WQKV + (size_t)3*1024*6144*2;         // 4096 x 6144
constexpr size_t O_WPG  = O_WFCG + (size_t)4096*6144*2;           // 1024 x 24576
constexpr size_t O_QA   = O_WPG  + (size_t)1024*24576*2;          // 128 x 512 x 256
constexpr size_t O_KB   = O_QA   + (size_t)128*512*256*2;         // 128 x 1024 x 256
constexpr size_t O_VB   = O_KB   + (size_t)128*1024*256*2;        // 128 x 128 x 2048
constexpr size_t O_PA   = O_VB   + (size_t)128*128*2048*2;        // 128 x 512 x 2048
constexpr size_t O_OO   = O_PA   + (size_t)128*512*2048*2;
constexpr size_t O_X2   = O_OO   + (size_t)MR*DD*8;
constexpr size_t O_HMG  = O_X2   + (size_t)MR*DD*8;               // MR x 24576
constexpr size_t O_SC   = O_HMG  + (size_t)MR*24576*2;
constexpr size_t POOLSZ = O_SC   + (size_t)128*512*512*8;         // ~1.26 GB
// aliases (disjoint lifetimes): Pq(151MB)<=Hmg(201MB); Pfc(201MB)<=Sc(268MB); Pp(151MB)<=Pa(268MB)
constexpr size_t O_PQ  = O_HMG;
constexpr size_t O_PFC = O_SC;
constexpr size_t O_PP  = O_PA;

__device__ __align__(256) char g_pool[POOLSZ];

// ---------------- helpers ----------------
__device__ __forceinline__ uint32_t s2u(const void* p){
    uint32_t a;
    asm("{ .reg .u64 t; cvta.to.shared.u64 t, %1; cvt.u32.u64 %0, t; }":"=r"(a):"l"(p));
    return a;
}
__device__ __forceinline__ void cpa16(uint32_t d, const void* g){
    asm volatile("cp.async.cg.shared.global [%0], [%1], 16;"::"r"(d),"l"(g));
}
__device__ __forceinline__ void split2(float vr, float vi, bf162& h, bf162& l){
    h.x=__float2bfloat16_rn(vr); h.y=__float2bfloat16_rn(vi);
    l.x=__float2bfloat16_rn(vr-__bfloat162float(h.x));
    l.y=__float2bfloat16_rn(vi-__bfloat162float(h.y));
}
__device__ __forceinline__ float flo(float v){
    return v - __bfloat162float(__float2bfloat16_rn(v));
}
__device__ __forceinline__ uint32_t pk2(float a, float b){
    bf162 t; t.x=__float2bfloat16_rn(a); t.y=__float2bfloat16_rn(b);
    return *(uint32_t*)&t;
}
__device__ __forceinline__ void ldm4(uint32_t* r, uint32_t a){
    asm volatile("ldmatrix.sync.aligned.m8n8.x4.shared.b16 {%0,%1,%2,%3}, [%4];"
        :"=r"(r[0]),"=r"(r[1]),"=r"(r[2]),"=r"(r[3]):"r"(a));
}
__device__ __forceinline__ void mma16816(float* d, const uint32_t* a, uint32_t b0, uint32_t b1){
    asm volatile("mma.sync.aligned.m16n8k16.row.col.f32.bf16.bf16.f32 "
        "{%0,%1,%2,%3}, {%4,%5,%6,%7}, {%8,%9}, {%0,%1,%2,%3};"
        :"+f"(d[0]),"+f"(d[1]),"+f"(d[2]),"+f"(d[3])
        :"r"(a[0]),"r"(a[1]),"r"(a[2]),"r"(a[3]),"r"(b0),"r"(b1));
}

// ---------------- GEMM via mma.sync, section-remapped operands ----------------
// Logical A K-layout [h|l|h], physical [h|l]: sec==1 -> +CPSA*64 else 0.
// Logical B K-layout [h|h|l], physical [h|l]: sec==2 -> +CPSB*64 else 0.
// CBZ: chunk index biased by (z % zdiv)*kC (split-K thirds). A2Z: z >= A2Z uses A2.
struct GP {
    const bf16 *A, *A2, *B;
    long lda, ldb;
    long sA1, sA2, sB1, sB2;
    float2* C; long ldc, sC1, sC2;
    const float2* bias;
    int zdiv, kC;
    float scale;
};
#define ROWB 144
#define ASZ  (128*ROWB)
#define STB  (2*ASZ)
#define SMB  (3*STB)

template<int CPSA, int CPSB, int CBZ, int A2Z>
__global__ __launch_bounds__(256,2) void tgemm(GP p)
{
    extern __shared__ __align__(256) char sm[];
    uint32_t TILE = s2u(sm);
    const int tid = threadIdx.x, lane = tid & 31, wid = tid >> 5;
    const int warpM = wid & 3, warpN = wid >> 2;

    const int z = blockIdx.z;
    const bf16* Ap = (z >= A2Z) ? p.A2 : p.A;
    const long offA = (z/p.zdiv)*p.sA1 + (z%p.zdiv)*p.sA2;
    const long offB = (z/p.zdiv)*p.sB1 + (z%p.zdiv)*p.sB2;
    const bf16* Ag = Ap + offA + (long)blockIdx.y*128*p.lda;
    const bf16* Bg = p.B + offB + (long)blockIdx.x*128*p.ldb;
    const int cbase = CBZ ? (z % p.zdiv) * p.kC : 0;

    auto loadStage = [&](int c){
        uint32_t st = TILE + (c%3)*STB;
        int ct = c + cbase;
        int sa = ct / CPSA, sb = ct / CPSB;
        long kofA = ((sa==1) ? (long)CPSA*64 : 0L) + (long)(ct % CPSA)*64;
        long kofB = ((sb==2) ? (long)CPSB*64 : 0L) + (long)(ct % CPSB)*64;
        #pragma unroll
        for (int i=0;i<4;i++){
            int idx = tid + i*256; int r = idx>>3, cc = idx&7;
            cpa16(st + r*ROWB + cc*16, Ag + (long)r*p.lda + kofA + cc*8);
        }
        #pragma unroll
        for (int i=0;i<4;i++){
            int idx = tid + i*256; int r = idx>>3, cc = idx&7;
            cpa16(st + ASZ + r*ROWB + cc*16, Bg + (long)r*p.ldb + kofB + cc*8);
        }
        asm volatile("cp.async.commit_group;":::"memory");
    };

    float acc[2][8][4];
    #pragma unroll
    for (int mf=0;mf<2;mf++)
        #pragma unroll
        for (int nf=0;nf<8;nf++)
            #pragma unroll
            for (int t=0;t<4;t++) acc[mf][nf][t] = 0.f;

    loadStage(0);
    if (p.kC > 1) loadStage(1);

    const uint32_t aRel = (uint32_t)((warpM*32 + (lane&15))*ROWB + (lane>>4)*16);
    const uint32_t bRel = (uint32_t)(ASZ + (warpN*64 + (lane&7))*ROWB + ((lane>>3)&3)*16);

    for (int c = 0; c < p.kC; c++) {
        if (c+1 < p.kC) asm volatile("cp.async.wait_group 1;":::"memory");
        else            asm volatile("cp.async.wait_group 0;":::"memory");
        __syncthreads();
        if (c+2 < p.kC) loadStage(c+2);

        uint32_t st = TILE + (c%3)*STB;
        uint32_t aB = st + aRel, bB = st + bRel;
        #pragma unroll
        for (int kh=0; kh<2; kh++){
            uint32_t bfr[8][4];
            #pragma unroll
            for (int nf=0; nf<8; nf++) ldm4(bfr[nf], bB + nf*(8*ROWB) + kh*64);
            #pragma unroll
            for (int s=0; s<2; s++){
                int ks = kh*2 + s;
                uint32_t af[2][4];
                #pragma unroll
                for (int mf=0; mf<2; mf++) ldm4(af[mf], aB + mf*(16*ROWB) + ks*32);
                #pragma unroll
                for (int mf=0; mf<2; mf++)
                    #pragma unroll
                    for (int nf=0; nf<8; nf++)
                        mma16816(acc[mf][nf], af[mf], bfr[nf][s*2], bfr[nf][s*2+1]);
            }
        }
    }

    const long coff = (z/p.zdiv)*p.sC1 + (z%p.zdiv)*p.sC2;
    const int ncBase = blockIdx.x*64 + warpN*32 + (lane&3);
    #pragma unroll
    for (int mf=0; mf<2; mf++){
        long r0 = (long)blockIdx.y*128 + warpM*32 + mf*16 + (lane>>2);
        #pragma unroll
        for (int nf=0; nf<8; nf++){
            int nc = ncBase + nf*4;
            float2 bb = p.bias ? p.bias[nc] : make_float2(0.f,0.f);
            #pragma unroll
            for (int h2=0; h2<2; h2++){
                long m = r0 + h2*8;
                float cr = acc[mf][nf][2*h2]   * p.scale + bb.x;
                float ci = acc[mf][nf][2*h2+1] * p.scale + bb.y;
                p.C[coff + m*p.ldc + nc] = make_float2(cr, ci);
            }
        }
    }
}

// ---------------- expansions (deduped [h|l] per comp) ----------------
__global__ __launch_bounds__(256) void expandAG2(const float2* __restrict__ q,
                                                 const float2* __restrict__ x,
                                                 bf16* __restrict__ Qg, bf16* __restrict__ Xg)
{
    long bid = blockIdx.x;
    const float2* src = q; bf16* dst = Qg;
    if (bid >= 8192) { bid -= 8192; src = x; dst = Xg; }
    long pidx = bid*256 + threadIdx.x;
    long m = pidx >> 9; int k = (int)(pidx & 511) * 2;
    float4 vv = *(const float4*)(src + m*1024 + k);
    float c0[3] = { vv.x, vv.y, vv.x + vv.y };
    float c1[3] = { vv.z, vv.w, vv.z + vv.w };
    bf16* base = dst + m*6144 + k;
    #pragma unroll
    for (int c=0;c<3;c++){
        bf16* b = base + c*2048;
        *(uint32_t*)(b)        = pk2(c0[c], c1[c]);
        *(uint32_t*)(b + 1024) = pk2(flo(c0[c]), flo(c1[c]));
    }
}
__global__ __launch_bounds__(256) void expandWG2(
    const float2* __restrict__ wq, const float2* __restrict__ wk, const float2* __restrict__ wv,
    const float2* __restrict__ wfc, const float2* __restrict__ wpr,
    bf16* __restrict__ Wqkv, bf16* __restrict__ Wfcg, bf16* __restrict__ Wpg)
{
    long bid = blockIdx.x;
    const float2* W; bf16* out; int K; long rstride;
    if      (bid < 2048)  { W=wq;  out=Wqkv;                    K=1024; rstride=6144; }
    else if (bid < 4096)  { W=wk;  out=Wqkv+(size_t)1024*6144;  K=1024; rstride=6144; bid-=2048; }
    else if (bid < 6144)  { W=wv;  out=Wqkv+(size_t)2048*6144;  K=1024; rstride=6144; bid-=4096; }
    else if (bid < 14336) { W=wfc; out=Wfcg;                    K=1024; rstride=6144; bid-=6144; }
    else                  { W=wpr; out=Wpg;                     K=4096; rstride=24576; bid-=14336; }
    long pidx = bid*256 + threadIdx.x;
    int Kp = K >> 1;
    long n = pidx / Kp; int k = (int)(pidx % Kp) * 2;
    float4 ww = *(const float4*)(W + n*K + k);
    float c0[3] = { ww.x, ww.y, ww.x + ww.y };
    float c1[3] = { ww.z, ww.w, ww.z + ww.w };
    bf16* base = out + n*rstride + k;
    #pragma unroll
    for (int c=0;c<3;c++){
        bf16* b = base + (long)c*2*K;
        *(uint32_t*)(b)     = pk2(c0[c], c1[c]);
        *(uint32_t*)(b + K) = pk2(flo(c0[c]), flo(c1[c]));
    }
}

// ---------------- Q/K combine (quad, coalesced; deduped widths) ----------------
__global__ __launch_bounds__(256) void cqk4(const float* __restrict__ Pq,
                                            const float2* __restrict__ bq,
                                            const float2* __restrict__ bk,
                                            bf16* __restrict__ Qa, bf16* __restrict__ Kb)
{
    long bid = blockIdx.x;
    int q3 = (int)(bid >> 12); bid &= 4095;
    long qidx = bid*256 + threadIdx.x;
    long m = qidx >> 8; int n = (int)(qidx & 255) * 4;
    const long MN = (long)MR*1024;
    const float* P = Pq + (long)q3*3*MN;
    long e = m*1024 + n;
    float4 p0 = *(const float4*)(P + e);
    float4 p1 = *(const float4*)(P + MN + e);
    float4 p2 = *(const float4*)(P + 2*MN + e);
    const float2* bi = (q3==0) ? bq : bk;
    float4 b01 = *(const float4*)(bi + n);
    float4 b23 = *(const float4*)(bi + n + 2);
    float yr[4], yi[4];
    yr[0]=p0.x-p1.x+b01.x; yi[0]=p2.x-p0.x-p1.x+b01.y;
    yr[1]=p0.y-p1.y+b01.z; yi[1]=p2.y-p0.y-p1.y+b01.w;
    yr[2]=p0.z-p1.z+b23.x; yi[2]=p2.z-p0.z-p1.z+b23.y;
    yr[3]=p0.w-p1.w+b23.z; yi[3]=p2.w-p0.w-p1.w+b23.w;

    int b=(int)(m>>9), s=(int)(m&511), hh=n>>6, d=n&63;
    long zz = b*16 + hh;
    if (q3 == 0) {
        uint4 H, L;
        H.x=pk2(yr[0],yi[0]); H.y=pk2(yr[1],yi[1]); H.z=pk2(yr[2],yi[2]); H.w=pk2(yr[3],yi[3]);
        L.x=pk2(flo(yr[0]),flo(yi[0])); L.y=pk2(flo(yr[1]),flo(yi[1]));
        L.z=pk2(flo(yr[2]),flo(yi[2])); L.w=pk2(flo(yr[3]),flo(yi[3]));
        bf16* base = Qa + (zz*512 + s)*256 + 2*d;
        *(uint4*)(base)       = H;
        *(uint4*)(base + 128) = L;
    } else {
        uint4 H0, L0, H1, L1;
        #pragma unroll
        for (int j=0;j<4;j++){
            ((uint32_t*)&H0)[j] = pk2(yr[j], -yi[j]);
            ((uint32_t*)&L0)[j] = pk2(flo(yr[j]), flo(-yi[j]));
            ((uint32_t*)&H1)[j] = pk2(yi[j], yr[j]);
            ((uint32_t*)&L1)[j] = pk2(flo(yi[j]), flo(yr[j]));
        }
        bf16* r0p = Kb + (zz*1024 + 2*s)*256 + 2*d;
        bf16* r1p = r0p + 256;
        *(uint4*)(r0p) = H0; *(uint4*)(r0p + 128) = L0;
        *(uint4*)(r1p) = H1; *(uint4*)(r1p + 128) = L1;
    }
}

// ---------------- V combine: smem transpose, deduped Vb width 2048 ----------------
__global__ __launch_bounds__(256) void cvb_t(const float* __restrict__ Pq,
                                             const float2* __restrict__ bv,
                                             bf16* __restrict__ Vb)
{
    __shared__ float syr[32][33], syi[32][33];
    const int zz = blockIdx.z, s0 = blockIdx.x*32, d0 = blockIdx.y*32;
    const int b = zz >> 4, h = zz & 15;
    const long MN = (long)MR*1024;
    const float* P = Pq + 2L*3*MN;
    const int tl = threadIdx.x & 31, tw = threadIdx.x >> 5;

    #pragma unroll
    for (int r=0;r<4;r++){
        int sl = tw + 8*r;
        long e = ((long)(b*512 + s0 + sl))*1024 + h*64 + d0 + tl;
        float p0 = P[e], p1 = P[MN+e], p2 = P[2*MN+e];
        float2 bb = bv[h*64 + d0 + tl];
        syr[sl][tl] = p0 - p1 + bb.x;
        syi[sl][tl] = p2 - p0 - p1 + bb.y;
    }
    __syncthreads();

    #pragma unroll
    for (int r=0;r<4;r++){
        int dl = tw + 8*r;
        float yr = syr[tl][dl], yi = syi[tl][dl];
        bf16* r0p = Vb + ((long)zz*128 + 2*(d0+dl))*2048 + 2*(s0+tl);
        bf16* r1p = r0p + 2048;
        *(uint32_t*)(r0p)        = pk2(yr, -yi);
        *(uint32_t*)(r0p + 1024) = pk2(flo(yr), flo(-yi));
        *(uint32_t*)(r1p)        = pk2(yi, yr);
        *(uint32_t*)(r1p + 1024) = pk2(flo(yi), flo(yr));
    }
}

// ---------------- fc combine (quad; Hmg deduped width 24576, comps [h|l] 8192) ----------------
__global__ __launch_bounds__(256) void cfc4(const float* __restrict__ Pfc,
                                            const float2* __restrict__ bfc,
                                            bf16* __restrict__ Hmg)
{
    long qidx = (long)blockIdx.x*256 + threadIdx.x;
    long m = qidx >> 10; int n = (int)(qidx & 1023) * 4;
    const long MN = (long)MR*4096;
    long e = m*4096 + n;
    float4 p0 = *(const float4*)(Pfc + e);
    float4 p1 = *(const float4*)(Pfc + MN + e);
    float4 p2 = *(const float4*)(Pfc + 2*MN + e);
    float4 b01 = *(const float4*)(bfc + n);
    float4 b23 = *(const float4*)(bfc + n + 2);
    float yr[4], yi[4];
    yr[0]=p0.x-p1.x+b01.x; yi[0]=p2.x-p0.x-p1.x+b01.y;
    yr[1]=p0.y-p1.y+b01.z; yi[1]=p2.y-p0.y-p1.y+b01.w;
    yr[2]=p0.z-p1.z+b23.x; yi[2]=p2.z-p0.z-p1.z+b23.y;
    yr[3]=p0.w-p1.w+b23.z; yi[3]=p2.w-p0.w-p1.w+b23.w;
    float cs[3][4];
    #pragma unroll
    for (int j=0;j<4;j++){
        float mg = sqrtf(yr[j]*yr[j] + yi[j]*yi[j]);
        float r = 0.5f*(yr[j] + mg), ii = 0.5f*yi[j];
        cs[0][j] = r; cs[1][j] = ii; cs[2][j] = r + ii;
    }
    bf16* base = Hmg + m*24576 + n;
    #pragma unroll
    for (int c=0;c<3;c++){
        uint2 H, L;
        H.x = pk2(cs[c][0], cs[c][1]); H.y = pk2(cs[c][2], cs[c][3]);
        L.x = pk2(flo(cs[c][0]), flo(cs[c][1])); L.y = pk2(flo(cs[c][2]), flo(cs[c][3]));
        bf16* b = base + c*8192;
        *(uint2*)(b)        = H;
        *(uint2*)(b + 4096) = L;
    }
}

// ---------------- softmax + probs ([h|l], width 2048; unchanged) ----------------
__global__ __launch_bounds__(256) void softmax_kernel(const float2* __restrict__ Sc, bf16* __restrict__ Pa)
{
    long rid = (long)blockIdx.x*8 + (threadIdx.x>>5);
    int lane = threadIdx.x & 31;
    const float2* r = Sc + rid*512;
    float2 v[16]; float mx=-1e30f, my=-1e30f;
    #pragma unroll
    for (int i=0;i<16;i++){ v[i]=r[lane+32*i]; mx=fmaxf(mx,v[i].x); my=fmaxf(my,v[i].y); }
    #pragma unroll
    for (int o=16;o>0;o>>=1){ mx=fmaxf(mx,__shfl_xor_sync(~0u,mx,o)); my=fmaxf(my,__shfl_xor_sync(~0u,my,o)); }
    float sx=0.f, sy=0.f;
    #pragma unroll
    for (int i=0;i<16;i++){ v[i].x=__expf(v[i].x-mx); v[i].y=__expf(v[i].y-my); sx+=v[i].x; sy+=v[i].y; }
    #pragma unroll
    for (int o=16;o>0;o>>=1){ sx+=__shfl_xor_sync(~0u,sx,o); sy+=__shfl_xor_sync(~0u,sy,o); }
    float ix=1.f/sx, iy=1.f/sy;
    bf16* base = Pa + rid*2048;
    #pragma unroll
    for (int i=0;i<16;i++){
        int k = lane + 32*i;
        bf162 h,l; split2(v[i].x*ix, v[i].y*iy, h, l);
        *(bf162*)(base+2*k)=h; *(bf162*)(base+1024+2*k)=l;
    }
}

// ---------------- layernorms ----------------
__device__ __forceinline__ void reduce4(float& a, float& b, float& c, float& d, float* sh)
{
    #pragma unroll
    for (int o=16;o>0;o>>=1){
        a+=__shfl_xor_sync(~0u,a,o); b+=__shfl_xor_sync(~0u,b,o);
        c+=__shfl_xor_sync(~0u,c,o); d+=__shfl_xor_sync(~0u,d,o);
    }
    int w = threadIdx.x>>5;
    __syncthreads();
    if ((threadIdx.x&31)==0){ sh[w]=a; sh[8+w]=b; sh[16+w]=c; sh[24+w]=d; }
    __syncthreads();
    float ra=0,rb=0,rc=0,rd=0;
    #pragma unroll
    for (int i=0;i<8;i++){ ra+=sh[i]; rb+=sh[8+i]; rc+=sh[16+i]; rd+=sh[24+i]; }
    a=ra; b=rb; c=rc; d=rd;
}

__global__ __launch_bounds__(256)
void ln_attn_kernel(const float2* __restrict__ O, const float2* __restrict__ query,
                    const float2* __restrict__ x,
                    const float* __restrict__ g, const float* __restrict__ bta,
                    float2* __restrict__ X2, bf16* __restrict__ X2g)
{
    __shared__ float sh[32];
    const long base = (long)blockIdx.x*DD;
    const float inv = 1.f/DD;
    float2 v[4]; float sr=0,sq=0,si=0,qi=0;
    #pragma unroll
    for (int i=0;i<2;i++){
        int d = 2*(threadIdx.x + i*256);
        float4 o = *(const float4*)(O + base + d);
        float4 q = *(const float4*)(query + base + d);
        v[2*i]   = make_float2(o.x+q.x, o.y+q.y);
        v[2*i+1] = make_float2(o.z+q.z, o.w+q.w);
        sr+=v[2*i].x+v[2*i+1].x; sq+=v[2*i].x*v[2*i].x+v[2*i+1].x*v[2*i+1].x;
        si+=v[2*i].y+v[2*i+1].y; qi+=v[2*i].y*v[2*i].y+v[2*i+1].y*v[2*i+1].y;
    }
    reduce4(sr,sq,si,qi,sh);
    float mr=sr*inv, mi=si*inv;
    float rr=rsqrtf(sq*inv-mr*mr+LN_EPS), ri=rsqrtf(qi*inv-mi*mi+LN_EPS);
    float2 u[4]; float s2=0,q2=0,s3=0,q3=0;
    #pragma unroll
    for (int i=0;i<2;i++){
        int d = 2*(threadIdx.x + i*256);
        float2 gr = *(const float2*)(g + d);
        float2 gi2 = *(const float2*)(g + DD + d);
        float2 br = *(const float2*)(bta + d);
        float2 bi2 = *(const float2*)(bta + DD + d);
        float4 xx = *(const float4*)(x + base + d);
        float tr0=(v[2*i].x-mr)*rr*gr.x+br.x,   ti0=(v[2*i].y-mi)*ri*gi2.x+bi2.x;
        float tr1=(v[2*i+1].x-mr)*rr*gr.y+br.y, ti1=(v[2*i+1].y-mi)*ri*gi2.y+bi2.y;
        u[2*i]   = make_float2(xx.x+tr0, xx.y+ti0);
        u[2*i+1] = make_float2(xx.z+tr1, xx.w+ti1);
        s2+=u[2*i].x+u[2*i+1].x; q2+=u[2*i].x*u[2*i].x+u[2*i+1].x*u[2*i+1].x;
        s3+=u[2*i].y+u[2*i+1].y; q3+=u[2*i].y*u[2*i].y+u[2*i+1].y*u[2*i+1].y;
    }
    reduce4(s2,q2,s3,q3,sh);
    float m2=s2*inv, m3=s3*inv;
    float r2=rsqrtf(q2*inv-m2*m2+LN_EPS), r3=rsqrtf(q3*inv-m3*m3+LN_EPS);
    const float *g1=g+2*DD, *b1=bta+2*DD;
    #pragma unroll
    for (int i=0;i<2;i++){
        int d = 2*(threadIdx.x + i*256);
        float2 gr = *(const float2*)(g1 + d);
        float2 gi2 = *(const float2*)(g1 + DD + d);
        float2 br = *(const float2*)(b1 + d);
        float2 bi2 = *(const float2*)(b1 + DD + d);
        float y0r=(u[2*i].x-m2)*r2*gr.x+br.x,   y0i=(u[2*i].y-m3)*r3*gi2.x+bi2.x;
        float y1r=(u[2*i+1].x-m2)*r2*gr.y+br.y, y1i=(u[2*i+1].y-m3)*r3*gi2.y+bi2.y;
        float4 o4; o4.x=y0r; o4.y=y0i; o4.z=y1r; o4.w=y1i;
        *(float4*)(X2 + base + d) = o4;
        float c0[3] = { y0r, y0i, y0r + y0i };
        float c1[3] = { y1r, y1i, y1r + y1i };
        bf16* eb = X2g + (long)blockIdx.x*6144 + d;
        #pragma unroll
        for (int c=0;c<3;c++){
            bf16* b = eb + c*2048;
            *(uint32_t*)(b)        = pk2(c0[c], c1[c]);
            *(uint32_t*)(b + 1024) = pk2(flo(c0[c]), flo(c1[c]));
        }
    }
}

// out = LN2(X2 + proj), proj = Gauss from 9 partials (3 products x 3 k-thirds) + bias
__global__ __launch_bounds__(256)
void ln_final_kernel(const float2* __restrict__ X2, const float* __restrict__ Pp,
                     const float2* __restrict__ bpr,
                     const float* __restrict__ g, const float* __restrict__ bta,
                     float2* __restrict__ out)
{
    __shared__ float sh[32];
    const long base = (long)blockIdx.x*DD;
    const long S = (long)MR*1024;
    const float inv = 1.f/DD;
    float2 v[4]; float sr=0,sq=0,si=0,qi=0;
    #pragma unroll
    for (int i=0;i<4;i++){
        int d = threadIdx.x + i*256;
        long fi = base + d;
        float P1 = Pp[fi]     + Pp[S+fi]   + Pp[2*S+fi];
        float P2 = Pp[3*S+fi] + Pp[4*S+fi] + Pp[5*S+fi];
        float P3 = Pp[6*S+fi] + Pp[7*S+fi] + Pp[8*S+fi];
        float2 a = X2[fi]; float2 bb = bpr[d];
        v[i] = make_float2(a.x + (P1 - P2) + bb.x,
                           a.y + (P3 - P1 - P2) + bb.y);
        sr+=v[i].x; sq+=v[i].x*v[i].x; si+=v[i].y; qi+=v[i].y*v[i].y;
    }
    reduce4(sr,sq,si,qi,sh);
    float mr=sr*inv, mi=si*inv;
    float rr=rsqrtf(sq*inv-mr*mr+LN_EPS), ri=rsqrtf(qi*inv-mi*mi+LN_EPS);
    const float *g2=g+4*DD, *b2=bta+4*DD;
    #pragma unroll
    for (int i=0;i<4;i++){
        int d = threadIdx.x + i*256;
        out[base+d]=make_float2((v[i].x-mr)*rr*g2[d]+b2[d], (v[i].y-mi)*ri*g2[DD+d]+b2[DD+d]);
    }
}

// ---------------- host ----------------
static GP mkgp(const bf16* A, const bf16* A2, long lda, const bf16* B, long ldb, int kC,
               float2* C, long ldc, const float2* bias, float scale,
               int zdiv, long sA1, long sA2, long sB1, long sB2, long sC1, long sC2)
{
    GP p = {};
    p.A=A; p.A2=A2; p.B=B; p.lda=lda; p.ldb=ldb; p.kC=kC;
    p.C=C; p.ldc=ldc; p.bias=bias; p.scale=scale; p.zdiv=zdiv;
    p.sA1=sA1; p.sA2=sA2; p.sB1=sB1; p.sB2=sB2; p.sC1=sC1; p.sC2=sC2;
    return p;
}

extern "C" void kernel_launch(void* const* d_in, const int* in_sizes, int n_in,
                              void* d_out, int out_size)
{
    const float2* x     = (const float2*)d_in[0];
    const float2* query = (const float2*)d_in[1];
    const float2* wq    = (const float2*)d_in[2];
    const float2* bq    = (const float2*)d_in[3];
    const float2* wk    = (const float2*)d_in[4];
    const float2* bk    = (const float2*)d_in[5];
    const float2* wv    = (const float2*)d_in[6];
    const float2* bv    = (const float2*)d_in[7];
    const float2* wfc   = (const float2*)d_in[8];
    const float2* bfc   = (const float2*)d_in[9];
    const float2* wpr   = (const float2*)d_in[10];
    const float2* bpr   = (const float2*)d_in[11];
    const float*  lng   = (const float*)d_in[12];
    const float*  lnb   = (const float*)d_in[13];

    char* pool;
    cudaGetSymbolAddress((void**)&pool, g_pool);
    bf16 *Qg   = (bf16*)(pool + O_QG),   *Xg   = (bf16*)(pool + O_XG);
    bf16 *X2g  = (bf16*)(pool + O_X2G),  *Hmg  = (bf16*)(pool + O_HMG);
    bf16 *Wqkv = (bf16*)(pool + O_WQKV), *Wfcg = (bf16*)(pool + O_WFCG);
    bf16 *Wpg  = (bf16*)(pool + O_WPG);
    bf16 *Qa   = (bf16*)(pool + O_QA),   *Kb   = (bf16*)(pool + O_KB);
    bf16 *Vb   = (bf16*)(pool + O_VB),   *Pa   = (bf16*)(pool + O_PA);
    float *Pq  = (float*)(pool + O_PQ),  *Pfc  = (float*)(pool + O_PFC);
    float *Pp  = (float*)(pool + O_PP);
    float2 *O  = (float2*)(pool + O_OO), *X2   = (float2*)(pool + O_X2);
    float2 *Sc = (float2*)(pool + O_SC);

    cudaFuncSetAttribute(tgemm<16,16,0,3>,   cudaFuncAttributeMaxDynamicSharedMemorySize, SMB);
    cudaFuncSetAttribute(tgemm<2,2,0,100>,   cudaFuncAttributeMaxDynamicSharedMemorySize, SMB);
    cudaFuncSetAttribute(tgemm<16,16,0,100>, cudaFuncAttributeMaxDynamicSharedMemorySize, SMB);
    cudaFuncSetAttribute(tgemm<64,64,1,100>, cudaFuncAttributeMaxDynamicSharedMemorySize, SMB);

    // expansions (deduped writes)
    expandAG2<<<16384,256>>>(query, x, Qg, Xg);
    expandWG2<<<22528,256>>>(wq, wk, wv, wfc, wpr, Wqkv, Wfcg, Wpg);

    // QKV Gauss: grid (8,32,9); z = inp*3 + prod; z>=3 uses Xg. kC=48, cps=16.
    tgemm<16,16,0,3><<<dim3(8,32,9),256,SMB>>>(mkgp(Qg, Xg, 6144, Wqkv, 6144, 48,
        (float2*)Pq, 512, nullptr, 1.f,
        3, 0, 2048, 1024L*6144, 2048, 3L*MR*512, (long)MR*512));
    cqk4<<<8192,256>>>(Pq, bq, bk, Qa, Kb);
    cvb_t<<<dim3(16,2,128),256>>>(Pq, bv, Vb);

    // scores: per z=(b,h); kC=6, cps=2 (sections 128 wide).
    tgemm<2,2,0,100><<<dim3(8,4,128),256,SMB>>>(mkgp(Qa, Qa, 256, Kb, 256, 6,
        Sc, 512, nullptr, 0.125f,
        1, 512L*256, 0, 1024L*256, 0, 512L*512, 0));
    softmax_kernel<<<128*512/8,256>>>(Sc, Pa);

    // AV: per z; kC=48, cps=16.
    tgemm<16,16,0,100><<<dim3(1,4,128),256,SMB>>>(mkgp(Pa, Pa, 2048, Vb, 2048, 48,
        O, 1024, nullptr, 1.f,
        16, 16L*512*2048, 512L*2048, 16L*128*2048, 128L*2048, 512L*1024, 64));

    ln_attn_kernel<<<MR,256>>>(O, query, x, lng, lnb, X2, X2g);

    // fc Gauss: grid (32,32,3); z = product. kC=48, cps=16.
    tgemm<16,16,0,100><<<dim3(32,32,3),256,SMB>>>(mkgp(X2g, X2g, 6144, Wfcg, 6144, 48,
        (float2*)Pfc, 2048, nullptr, 1.f,
        3, 0, 2048, 0, 2048, 0, (long)MR*2048));
    cfc4<<<16384,256>>>(Pfc, bfc, Hmg);

    // proj Gauss + split-K x3: grid (8,32,9); z = prod*3 + third; kC=64, cps=64, cbase=(z%3)*64.
    tgemm<64,64,1,100><<<dim3(8,32,9),256,SMB>>>(mkgp(Hmg, Hmg, 24576, Wpg, 24576, 64,
        (float2*)Pp, 512, nullptr, 1.f,
        3, 8192, 0, 8192, 0, 3L*MR*512, (long)MR*512));

    ln_final_kernel<<<MR,256>>>(X2, Pp, bpr, lng, lnb, (float2*)d_out);
}

// round 16
// speedup vs baseline: 3.8058x; 1.0030x over previous
#include <cuda_runtime.h>
#include <cuda_bf16.h>
#include <cstdint>
#include <math.h>

typedef __nv_bfloat16 bf16;
typedef __nv_bfloat162 bf162;

#define DD 1024
#define MR 4096
#define LN_EPS 1e-5f

// ---------------- pooled scratch (deduped layouts: A=[h|l], B=[h|l]) ----------------
constexpr size_t O_QG   = 0;
constexpr size_t O_XG   = O_QG   + (size_t)MR*6144*2;
constexpr size_t O_X2G  = O_XG   + (size_t)MR*6144*2;
constexpr size_t O_WQKV = O_X2G  + (size_t)MR*6144*2;
constexpr size_t O_WFCG = O_WQKV + (size_t)3*1024*6144*2;
constexpr size_t O_WPG  = O_WFCG + (size_t)4096*6144*2;
constexpr size_t O_QA   = O_WPG  + (size_t)1024*24576*2;
constexpr size_t O_KB   = O_QA   + (size_t)128*512*256*2;
constexpr size_t O_VB   = O_KB   + (size_t)128*1024*256*2;
constexpr size_t O_PA   = O_VB   + (size_t)128*128*2048*2;
constexpr size_t O_OO   = O_PA   + (size_t)128*512*2048*2;
constexpr size_t O_X2   = O_OO   + (size_t)MR*DD*8;
constexpr size_t O_HMG  = O_X2   + (size_t)MR*DD*8;
constexpr size_t O_SC   = O_HMG  + (size_t)MR*24576*2;
constexpr size_t POOLSZ = O_SC   + (size_t)128*512*512*8;
// aliases (disjoint lifetimes in launch order):
constexpr size_t O_PQ  = O_HMG;
constexpr size_t O_PFC = O_SC;
constexpr size_t O_PP  = O_PA;

__device__ __align__(256) char g_pool[POOLSZ];

// ---------------- helpers ----------------
__device__ __forceinline__ uint32_t s2u(const void* p){
    uint32_t a;
    asm("{ .reg .u64 t; cvta.to.shared.u64 t, %1; cvt.u32.u64 %0, t; }":"=r"(a):"l"(p));
    return a;
}
__device__ __forceinline__ void cpa16(uint32_t d, const void* g){
    asm volatile("cp.async.cg.shared.global [%0], [%1], 16;"::"r"(d),"l"(g));
}
__device__ __forceinline__ void split2(float vr, float vi, bf162& h, bf162& l){
    h.x=__float2bfloat16_rn(vr); h.y=__float2bfloat16_rn(vi);
    l.x=__float2bfloat16_rn(vr-__bfloat162float(h.x));
    l.y=__float2bfloat16_rn(vi-__bfloat162float(h.y));
}
__device__ __forceinline__ float flo(float v){
    return v - __bfloat162float(__float2bfloat16_rn(v));
}
__device__ __forceinline__ uint32_t pk2(float a, float b){
    bf162 t; t.x=__float2bfloat16_rn(a); t.y=__float2bfloat16_rn(b);
    return *(uint32_t*)&t;
}
__device__ __forceinline__ void ldm4(uint32_t* r, uint32_t a){
    asm volatile("ldmatrix.sync.aligned.m8n8.x4.shared.b16 {%0,%1,%2,%3}, [%4];"
        :"=r"(r[0]),"=r"(r[1]),"=r"(r[2]),"=r"(r[3]):"r"(a));
}
__device__ __forceinline__ void mma16816(float* d, const uint32_t* a, uint32_t b0, uint32_t b1){
    asm volatile("mma.sync.aligned.m16n8k16.row.col.f32.bf16.bf16.f32 "
        "{%0,%1,%2,%3}, {%4,%5,%6,%7}, {%8,%9}, {%0,%1,%2,%3};"
        :"+f"(d[0]),"+f"(d[1]),"+f"(d[2]),"+f"(d[3])
        :"r"(a[0]),"r"(a[1]),"r"(a[2]),"r"(a[3]),"r"(b0),"r"(b1));
}

// ---------------- GEMM via mma.sync, section-remapped operands ----------------
struct GP {
    const bf16 *A, *A2, *B;
    long lda, ldb;
    long sA1, sA2, sB1, sB2;
    float2* C; long ldc, sC1, sC2;
    const float2* bias;
    int zdiv, kC;
    float scale;
};
#define ROWB 144
#define ASZ  (128*ROWB)
#define STB  (2*ASZ)
#define SMB  (3*STB)

template<int CPSA, int CPSB, int CBZ, int A2Z>
__global__ __launch_bounds__(256,2) void tgemm(GP p)
{
    extern __shared__ __align__(256) char sm[];
    uint32_t TILE = s2u(sm);
    const int tid = threadIdx.x, lane = tid & 31, wid = tid >> 5;
    const int warpM = wid & 3, warpN = wid >> 2;

    const int z = blockIdx.z;
    const bf16* Ap = (z >= A2Z) ? p.A2 : p.A;
    const long offA = (z/p.zdiv)*p.sA1 + (z%p.zdiv)*p.sA2;
    const long offB = (z/p.zdiv)*p.sB1 + (z%p.zdiv)*p.sB2;
    const bf16* Ag = Ap + offA + (long)blockIdx.y*128*p.lda;
    const bf16* Bg = p.B + offB + (long)blockIdx.x*128*p.ldb;
    const int cbase = CBZ ? (z % p.zdiv) * p.kC : 0;

    auto loadStage = [&](int c){
        uint32_t st = TILE + (c%3)*STB;
        int ct = c + cbase;
        int sa = ct / CPSA, sb = ct / CPSB;
        long kofA = ((sa==1) ? (long)CPSA*64 : 0L) + (long)(ct % CPSA)*64;
        long kofB = ((sb==2) ? (long)CPSB*64 : 0L) + (long)(ct % CPSB)*64;
        #pragma unroll
        for (int i=0;i<4;i++){
            int idx = tid + i*256; int r = idx>>3, cc = idx&7;
            cpa16(st + r*ROWB + cc*16, Ag + (long)r*p.lda + kofA + cc*8);
        }
        #pragma unroll
        for (int i=0;i<4;i++){
            int idx = tid + i*256; int r = idx>>3, cc = idx&7;
            cpa16(st + ASZ + r*ROWB + cc*16, Bg + (long)r*p.ldb + kofB + cc*8);
        }
        asm volatile("cp.async.commit_group;":::"memory");
    };

    float acc[2][8][4];
    #pragma unroll
    for (int mf=0;mf<2;mf++)
        #pragma unroll
        for (int nf=0;nf<8;nf++)
            #pragma unroll
            for (int t=0;t<4;t++) acc[mf][nf][t] = 0.f;

    loadStage(0);
    if (p.kC > 1) loadStage(1);

    const uint32_t aRel = (uint32_t)((warpM*32 + (lane&15))*ROWB + (lane>>4)*16);
    const uint32_t bRel = (uint32_t)(ASZ + (warpN*64 + (lane&7))*ROWB + ((lane>>3)&3)*16);

    for (int c = 0; c < p.kC; c++) {
        if (c+1 < p.kC) asm volatile("cp.async.wait_group 1;":::"memory");
        else            asm volatile("cp.async.wait_group 0;":::"memory");
        __syncthreads();
        if (c+2 < p.kC) loadStage(c+2);

        uint32_t st = TILE + (c%3)*STB;
        uint32_t aB = st + aRel, bB = st + bRel;
        #pragma unroll
        for (int kh=0; kh<2; kh++){
            uint32_t bfr[8][4];
            #pragma unroll
            for (int nf=0; nf<8; nf++) ldm4(bfr[nf], bB + nf*(8*ROWB) + kh*64);
            #pragma unroll
            for (int s=0; s<2; s++){
                int ks = kh*2 + s;
                uint32_t af[2][4];
                #pragma unroll
                for (int mf=0; mf<2; mf++) ldm4(af[mf], aB + mf*(16*ROWB) + ks*32);
                #pragma unroll
                for (int mf=0; mf<2; mf++)
                    #pragma unroll
                    for (int nf=0; nf<8; nf++)
                        mma16816(acc[mf][nf], af[mf], bfr[nf][s*2], bfr[nf][s*2+1]);
            }
        }
    }

    const long coff = (z/p.zdiv)*p.sC1 + (z%p.zdiv)*p.sC2;
    const int ncBase = blockIdx.x*64 + warpN*32 + (lane&3);
    #pragma unroll
    for (int mf=0; mf<2; mf++){
        long r0 = (long)blockIdx.y*128 + warpM*32 + mf*16 + (lane>>2);
        #pragma unroll
        for (int nf=0; nf<8; nf++){
            int nc = ncBase + nf*4;
            float2 bb = p.bias ? p.bias[nc] : make_float2(0.f,0.f);
            #pragma unroll
            for (int h2=0; h2<2; h2++){
                long m = r0 + h2*8;
                float cr = acc[mf][nf][2*h2]   * p.scale + bb.x;
                float ci = acc[mf][nf][2*h2+1] * p.scale + bb.y;
                p.C[coff + m*p.ldc + nc] = make_float2(cr, ci);
            }
        }
    }
}

// ---------------- merged expansions: [0,16384)=activations, [16384,38912)=weights ----------------
__global__ __launch_bounds__(256) void expandALL(
    const float2* __restrict__ q, const float2* __restrict__ x,
    const float2* __restrict__ wq, const float2* __restrict__ wk, const float2* __restrict__ wv,
    const float2* __restrict__ wfc, const float2* __restrict__ wpr,
    bf16* __restrict__ Qg, bf16* __restrict__ Xg,
    bf16* __restrict__ Wqkv, bf16* __restrict__ Wfcg, bf16* __restrict__ Wpg)
{
    long bid = blockIdx.x;
    if (bid < 16384) {
        const float2* src = q; bf16* dst = Qg;
        if (bid >= 8192) { bid -= 8192; src = x; dst = Xg; }
        long pidx = bid*256 + threadIdx.x;
        long m = pidx >> 9; int k = (int)(pidx & 511) * 2;
        float4 vv = *(const float4*)(src + m*1024 + k);
        float c0[3] = { vv.x, vv.y, vv.x + vv.y };
        float c1[3] = { vv.z, vv.w, vv.z + vv.w };
        bf16* base = dst + m*6144 + k;
        #pragma unroll
        for (int c=0;c<3;c++){
            bf16* b = base + c*2048;
            *(uint32_t*)(b)        = pk2(c0[c], c1[c]);
            *(uint32_t*)(b + 1024) = pk2(flo(c0[c]), flo(c1[c]));
        }
        return;
    }
    bid -= 16384;
    const float2* W; bf16* out; int K; long rstride;
    if      (bid < 2048)  { W=wq;  out=Wqkv;                    K=1024; rstride=6144; }
    else if (bid < 4096)  { W=wk;  out=Wqkv+(size_t)1024*6144;  K=1024; rstride=6144; bid-=2048; }
    else if (bid < 6144)  { W=wv;  out=Wqkv+(size_t)2048*6144;  K=1024; rstride=6144; bid-=4096; }
    else if (bid < 14336) { W=wfc; out=Wfcg;                    K=1024; rstride=6144; bid-=6144; }
    else                  { W=wpr; out=Wpg;                     K=4096; rstride=24576; bid-=14336; }
    long pidx = bid*256 + threadIdx.x;
    int Kp = K >> 1;
    long n = pidx / Kp; int k = (int)(pidx % Kp) * 2;
    float4 ww = *(const float4*)(W + n*K + k);
    float c0[3] = { ww.x, ww.y, ww.x + ww.y };
    float c1[3] = { ww.z, ww.w, ww.z + ww.w };
    bf16* base = out + n*rstride + k;
    #pragma unroll
    for (int c=0;c<3;c++){
        bf16* b = base + (long)c*2*K;
        *(uint32_t*)(b)     = pk2(c0[c], c1[c]);
        *(uint32_t*)(b + K) = pk2(flo(c0[c]), flo(c1[c]));
    }
}

// ---------------- merged QKV combine: [0,8192)=Q/K quad, [8192,12288)=V transpose ----------------
__global__ __launch_bounds__(256) void cqkvall(const float* __restrict__ Pq,
                                               const float2* __restrict__ bq,
                                               const float2* __restrict__ bk,
                                               const float2* __restrict__ bv,
                                               bf16* __restrict__ Qa, bf16* __restrict__ Kb,
                                               bf16* __restrict__ Vb)
{
    __shared__ float syr[32][33], syi[32][33];
    long bid = blockIdx.x;
    const long MN = (long)MR*1024;
    if (bid < 8192) {
        int q3 = (int)(bid >> 12); bid &= 4095;
        long qidx = bid*256 + threadIdx.x;
        long m = qidx >> 8; int n = (int)(qidx & 255) * 4;
        const float* P = Pq + (long)q3*3*MN;
        long e = m*1024 + n;
        float4 p0 = *(const float4*)(P + e);
        float4 p1 = *(const float4*)(P + MN + e);
        float4 p2 = *(const float4*)(P + 2*MN + e);
        const float2* bi = (q3==0) ? bq : bk;
        float4 b01 = *(const float4*)(bi + n);
        float4 b23 = *(const float4*)(bi + n + 2);
        float yr[4], yi[4];
        yr[0]=p0.x-p1.x+b01.x; yi[0]=p2.x-p0.x-p1.x+b01.y;
        yr[1]=p0.y-p1.y+b01.z; yi[1]=p2.y-p0.y-p1.y+b01.w;
        yr[2]=p0.z-p1.z+b23.x; yi[2]=p2.z-p0.z-p1.z+b23.y;
        yr[3]=p0.w-p1.w+b23.z; yi[3]=p2.w-p0.w-p1.w+b23.w;

        int b=(int)(m>>9), s=(int)(m&511), hh=n>>6, d=n&63;
        long zz = b*16 + hh;
        if (q3 == 0) {
            uint4 H, L;
            H.x=pk2(yr[0],yi[0]); H.y=pk2(yr[1],yi[1]); H.z=pk2(yr[2],yi[2]); H.w=pk2(yr[3],yi[3]);
            L.x=pk2(flo(yr[0]),flo(yi[0])); L.y=pk2(flo(yr[1]),flo(yi[1]));
            L.z=pk2(flo(yr[2]),flo(yi[2])); L.w=pk2(flo(yr[3]),flo(yi[3]));
            bf16* base = Qa + (zz*512 + s)*256 + 2*d;
            *(uint4*)(base)       = H;
            *(uint4*)(base + 128) = L;
        } else {
            uint4 H0, L0, H1, L1;
            #pragma unroll
            for (int j=0;j<4;j++){
                ((uint32_t*)&H0)[j] = pk2(yr[j], -yi[j]);
                ((uint32_t*)&L0)[j] = pk2(flo(yr[j]), flo(-yi[j]));
                ((uint32_t*)&H1)[j] = pk2(yi[j], yr[j]);
                ((uint32_t*)&L1)[j] = pk2(flo(yi[j]), flo(yr[j]));
            }
            bf16* r0p = Kb + (zz*1024 + 2*s)*256 + 2*d;
            bf16* r1p = r0p + 256;
            *(uint4*)(r0p) = H0; *(uint4*)(r0p + 128) = L0;
            *(uint4*)(r1p) = H1; *(uint4*)(r1p + 128) = L1;
        }
        return;
    }
    // V path: smem-staged transpose
    long bid2 = bid - 8192;                  // [0,4096)
    const int s0 = ((int)bid2 & 15) * 32;
    const int d0 = (((int)bid2 >> 4) & 1) * 32;
    const int zz = (int)(bid2 >> 5);
    const int b = zz >> 4, h = zz & 15;
    const float* P = Pq + 2L*3*MN;
    const int tl = threadIdx.x & 31, tw = threadIdx.x >> 5;

    #pragma unroll
    for (int r=0;r<4;r++){
        int sl = tw + 8*r;
        long e = ((long)(b*512 + s0 + sl))*1024 + h*64 + d0 + tl;
        float p0 = P[e], p1 = P[MN+e], p2 = P[2*MN+e];
        float2 bb = bv[h*64 + d0 + tl];
        syr[sl][tl] = p0 - p1 + bb.x;
        syi[sl][tl] = p2 - p0 - p1 + bb.y;
    }
    __syncthreads();

    #pragma unroll
    for (int r=0;r<4;r++){
        int dl = tw + 8*r;
        float yr = syr[tl][dl], yi = syi[tl][dl];
        bf16* r0p = Vb + ((long)zz*128 + 2*(d0+dl))*2048 + 2*(s0+tl);
        bf16* r1p = r0p + 2048;
        *(uint32_t*)(r0p)        = pk2(yr, -yi);
        *(uint32_t*)(r0p + 1024) = pk2(flo(yr), flo(-yi));
        *(uint32_t*)(r1p)        = pk2(yi, yr);
        *(uint32_t*)(r1p + 1024) = pk2(flo(yi), flo(yr));
    }
}

// ---------------- fc combine (quad) ----------------
__global__ __launch_bounds__(256) void cfc4(const float* __restrict__ Pfc,
                                            const float2* __restrict__ bfc,
                                            bf16* __restrict__ Hmg)
{
    long qidx = (long)blockIdx.x*256 + threadIdx.x;
    long m = qidx >> 10; int n = (int)(qidx & 1023) * 4;
    const long MN = (long)MR*4096;
    long e = m*4096 + n;
    float4 p0 = *(const float4*)(Pfc + e);
    float4 p1 = *(const float4*)(Pfc + MN + e);
    float4 p2 = *(const float4*)(Pfc + 2*MN + e);
    float4 b01 = *(const float4*)(bfc + n);
    float4 b23 = *(const float4*)(bfc + n + 2);
    float yr[4], yi[4];
    yr[0]=p0.x-p1.x+b01.x; yi[0]=p2.x-p0.x-p1.x+b01.y;
    yr[1]=p0.y-p1.y+b01.z; yi[1]=p2.y-p0.y-p1.y+b01.w;
    yr[2]=p0.z-p1.z+b23.x; yi[2]=p2.z-p0.z-p1.z+b23.y;
    yr[3]=p0.w-p1.w+b23.z; yi[3]=p2.w-p0.w-p1.w+b23.w;
    float cs[3][4];
    #pragma unroll
    for (int j=0;j<4;j++){
        float mg = sqrtf(yr[j]*yr[j] + yi[j]*yi[j]);
        float r = 0.5f*(yr[j] + mg), ii = 0.5f*yi[j];
        cs[0][j] = r; cs[1][j] = ii; cs[2][j] = r + ii;
    }
    bf16* base = Hmg + m*24576 + n;
    #pragma unroll
    for (int c=0;c<3;c++){
        uint2 H, L;
        H.x = pk2(cs[c][0], cs[c][1]); H.y = pk2(cs[c][2], cs[c][3]);
        L.x = pk2(flo(cs[c][0]), flo(cs[c][1])); L.y = pk2(flo(cs[c][2]), flo(cs[c][3]));
        bf16* b = base + c*8192;
        *(uint2*)(b)        = H;
        *(uint2*)(b + 4096) = L;
    }
}

// ---------------- softmax + probs ([h|l], width 2048) ----------------
__global__ __launch_bounds__(256) void softmax_kernel(const float2* __restrict__ Sc, bf16* __restrict__ Pa)
{
    long rid = (long)blockIdx.x*8 + (threadIdx.x>>5);
    int lane = threadIdx.x & 31;
    const float2* r = Sc + rid*512;
    float2 v[16]; float mx=-1e30f, my=-1e30f;
    #pragma unroll
    for (int i=0;i<16;i++){ v[i]=r[lane+32*i]; mx=fmaxf(mx,v[i].x); my=fmaxf(my,v[i].y); }
    #pragma unroll
    for (int o=16;o>0;o>>=1){ mx=fmaxf(mx,__shfl_xor_sync(~0u,mx,o)); my=fmaxf(my,__shfl_xor_sync(~0u,my,o)); }
    float sx=0.f, sy=0.f;
    #pragma unroll
    for (int i=0;i<16;i++){ v[i].x=__expf(v[i].x-mx); v[i].y=__expf(v[i].y-my); sx+=v[i].x; sy+=v[i].y; }
    #pragma unroll
    for (int o=16;o>0;o>>=1){ sx+=__shfl_xor_sync(~0u,sx,o); sy+=__shfl_xor_sync(~0u,sy,o); }
    float ix=1.f/sx, iy=1.f/sy;
    bf16* base = Pa + rid*2048;
    #pragma unroll
    for (int i=0;i<16;i++){
        int k = lane + 32*i;
        bf162 h,l; split2(v[i].x*ix, v[i].y*iy, h, l);
        *(bf162*)(base+2*k)=h; *(bf162*)(base+1024+2*k)=l;
    }
}

// ---------------- layernorms ----------------
__device__ __forceinline__ void reduce4(float& a, float& b, float& c, float& d, float* sh)
{
    #pragma unroll
    for (int o=16;o>0;o>>=1){
        a+=__shfl_xor_sync(~0u,a,o); b+=__shfl_xor_sync(~0u,b,o);
        c+=__shfl_xor_sync(~0u,c,o); d+=__shfl_xor_sync(~0u,d,o);
    }
    int w = threadIdx.x>>5;
    __syncthreads();
    if ((threadIdx.x&31)==0){ sh[w]=a; sh[8+w]=b; sh[16+w]=c; sh[24+w]=d; }
    __syncthreads();
    float ra=0,rb=0,rc=0,rd=0;
    #pragma unroll
    for (int i=0;i<8;i++){ ra+=sh[i]; rb+=sh[8+i]; rc+=sh[16+i]; rd+=sh[24+i]; }
    a=ra; b=rb; c=rc; d=rd;
}

__global__ __launch_bounds__(256)
void ln_attn_kernel(const float2* __restrict__ O, const float2* __restrict__ query,
                    const float2* __restrict__ x,
                    const float* __restrict__ g, const float* __restrict__ bta,
                    float2* __restrict__ X2, bf16* __restrict__ X2g)
{
    __shared__ float sh[32];
    const long base = (long)blockIdx.x*DD;
    const float inv = 1.f/DD;
    float2 v[4]; float sr=0,sq=0,si=0,qi=0;
    #pragma unroll
    for (int i=0;i<2;i++){
        int d = 2*(threadIdx.x + i*256);
        float4 o = *(const float4*)(O + base + d);
        float4 q = *(const float4*)(query + base + d);
        v[2*i]   = make_float2(o.x+q.x, o.y+q.y);
        v[2*i+1] = make_float2(o.z+q.z, o.w+q.w);
        sr+=v[2*i].x+v[2*i+1].x; sq+=v[2*i].x*v[2*i].x+v[2*i+1].x*v[2*i+1].x;
        si+=v[2*i].y+v[2*i+1].y; qi+=v[2*i].y*v[2*i].y+v[2*i+1].y*v[2*i+1].y;
    }
    reduce4(sr,sq,si,qi,sh);
    float mr=sr*inv, mi=si*inv;
    float rr=rsqrtf(sq*inv-mr*mr+LN_EPS), ri=rsqrtf(qi*inv-mi*mi+LN_EPS);
    float2 u[4]; float s2=0,q2=0,s3=0,q3=0;
    #pragma unroll
    for (int i=0;i<2;i++){
        int d = 2*(threadIdx.x + i*256);
        float2 gr = *(const float2*)(g + d);
        float2 gi2 = *(const float2*)(g + DD + d);
        float2 br = *(const float2*)(bta + d);
        float2 bi2 = *(const float2*)(bta + DD + d);
        float4 xx = *(const float4*)(x + base + d);
        float tr0=(v[2*i].x-mr)*rr*gr.x+br.x,   ti0=(v[2*i].y-mi)*ri*gi2.x+bi2.x;
        float tr1=(v[2*i+1].x-mr)*rr*gr.y+br.y, ti1=(v[2*i+1].y-mi)*ri*gi2.y+bi2.y;
        u[2*i]   = make_float2(xx.x+tr0, xx.y+ti0);
        u[2*i+1] = make_float2(xx.z+tr1, xx.w+ti1);
        s2+=u[2*i].x+u[2*i+1].x; q2+=u[2*i].x*u[2*i].x+u[2*i+1].x*u[2*i+1].x;
        s3+=u[2*i].y+u[2*i+1].y; q3+=u[2*i].y*u[2*i].y+u[2*i+1].y*u[2*i+1].y;
    }
    reduce4(s2,q2,s3,q3,sh);
    float m2=s2*inv, m3=s3*inv;
    float r2=rsqrtf(q2*inv-m2*m2+LN_EPS), r3=rsqrtf(q3*inv-m3*m3+LN_EPS);
    const float *g1=g+2*DD, *b1=bta+2*DD;
    #pragma unroll
    for (int i=0;i<2;i++){
        int d = 2*(threadIdx.x + i*256);
        float2 gr = *(const float2*)(g1 + d);
        float2 gi2 = *(const float2*)(g1 + DD + d);
        float2 br = *(const float2*)(b1 + d);
        float2 bi2 = *(const float2*)(b1 + DD + d);
        float y0r=(u[2*i].x-m2)*r2*gr.x+br.x,   y0i=(u[2*i].y-m3)*r3*gi2.x+bi2.x;
        float y1r=(u[2*i+1].x-m2)*r2*gr.y+br.y, y1i=(u[2*i+1].y-m3)*r3*gi2.y+bi2.y;
        float4 o4; o4.x=y0r; o4.y=y0i; o4.z=y1r; o4.w=y1i;
        *(float4*)(X2 + base + d) = o4;
        float c0[3] = { y0r, y0i, y0r + y0i };
        float c1[3] = { y1r, y1i, y1r + y1i };
        bf16* eb = X2g + (long)blockIdx.x*6144 + d;
        #pragma unroll
        for (int c=0;c<3;c++){
            bf16* b = eb + c*2048;
            *(uint32_t*)(b)        = pk2(c0[c], c1[c]);
            *(uint32_t*)(b + 1024) = pk2(flo(c0[c]), flo(c1[c]));
        }
    }
}

__global__ __launch_bounds__(256)
void ln_final_kernel(const float2* __restrict__ X2, const float* __restrict__ Pp,
                     const float2* __restrict__ bpr,
                     const float* __restrict__ g, const float* __restrict__ bta,
                     float2* __restrict__ out)
{
    __shared__ float sh[32];
    const long base = (long)blockIdx.x*DD;
    const long S = (long)MR*1024;
    const float inv = 1.f/DD;
    float2 v[4]; float sr=0,sq=0,si=0,qi=0;
    #pragma unroll
    for (int i=0;i<4;i++){
        int d = threadIdx.x + i*256;
        long fi = base + d;
        float P1 = Pp[fi]     + Pp[S+fi]   + Pp[2*S+fi];
        float P2 = Pp[3*S+fi] + Pp[4*S+fi] + Pp[5*S+fi];
        float P3 = Pp[6*S+fi] + Pp[7*S+fi] + Pp[8*S+fi];
        float2 a = X2[fi]; float2 bb = bpr[d];
        v[i] = make_float2(a.x + (P1 - P2) + bb.x,
                           a.y + (P3 - P1 - P2) + bb.y);
        sr+=v[i].x; sq+=v[i].x*v[i].x; si+=v[i].y; qi+=v[i].y*v[i].y;
    }
    reduce4(sr,sq,si,qi,sh);
    float mr=sr*inv, mi=si*inv;
    float rr=rsqrtf(sq*inv-mr*mr+LN_EPS), ri=rsqrtf(qi*inv-mi*mi+LN_EPS);
    const float *g2=g+4*DD, *b2=bta+4*DD;
    #pragma unroll
    for (int i=0;i<4;i++){
        int d = threadIdx.x + i*256;
        out[base+d]=make_float2((v[i].x-mr)*rr*g2[d]+b2[d], (v[i].y-mi)*ri*g2[DD+d]+b2[DD+d]);
    }
}

// ---------------- host ----------------
static GP mkgp(const bf16* A, const bf16* A2, long lda, const bf16* B, long ldb, int kC,
               float2* C, long ldc, const float2* bias, float scale,
               int zdiv, long sA1, long sA2, long sB1, long sB2, long sC1, long sC2)
{
    GP p = {};
    p.A=A; p.A2=A2; p.B=B; p.lda=lda; p.ldb=ldb; p.kC=kC;
    p.C=C; p.ldc=ldc; p.bias=bias; p.scale=scale; p.zdiv=zdiv;
    p.sA1=sA1; p.sA2=sA2; p.sB1=sB1; p.sB2=sB2; p.sC1=sC1; p.sC2=sC2;
    return p;
}

extern "C" void kernel_launch(void* const* d_in, const int* in_sizes, int n_in,
                              void* d_out, int out_size)
{
    const float2* x     = (const float2*)d_in[0];
    const float2* query = (const float2*)d_in[1];
    const float2* wq    = (const float2*)d_in[2];
    const float2* bq    = (const float2*)d_in[3];
    const float2* wk    = (const float2*)d_in[4];
    const float2* bk    = (const float2*)d_in[5];
    const float2* wv    = (const float2*)d_in[6];
    const float2* bv    = (const float2*)d_in[7];
    const float2* wfc   = (const float2*)d_in[8];
    const float2* bfc   = (const float2*)d_in[9];
    const float2* wpr   = (const float2*)d_in[10];
    const float2* bpr   = (const float2*)d_in[11];
    const float*  lng   = (const float*)d_in[12];
    const float*  lnb   = (const float*)d_in[13];

    char* pool;
    cudaGetSymbolAddress((void**)&pool, g_pool);
    bf16 *Qg   = (bf16*)(pool + O_QG),   *Xg   = (bf16*)(pool + O_XG);
    bf16 *X2g  = (bf16*)(pool + O_X2G),  *Hmg  = (bf16*)(pool + O_HMG);
    bf16 *Wqkv = (bf16*)(pool + O_WQKV), *Wfcg = (bf16*)(pool + O_WFCG);
    bf16 *Wpg  = (bf16*)(pool + O_WPG);
    bf16 *Qa   = (bf16*)(pool + O_QA),   *Kb   = (bf16*)(pool + O_KB);
    bf16 *Vb   = (bf16*)(pool + O_VB),   *Pa   = (bf16*)(pool + O_PA);
    float *Pq  = (float*)(pool + O_PQ),  *Pfc  = (float*)(pool + O_PFC);
    float *Pp  = (float*)(pool + O_PP);
    float2 *O  = (float2*)(pool + O_OO), *X2   = (float2*)(pool + O_X2);
    float2 *Sc = (float2*)(pool + O_SC);

    cudaFuncSetAttribute(tgemm<16,16,0,3>,   cudaFuncAttributeMaxDynamicSharedMemorySize, SMB);
    cudaFuncSetAttribute(tgemm<2,2,0,100>,   cudaFuncAttributeMaxDynamicSharedMemorySize, SMB);
    cudaFuncSetAttribute(tgemm<16,16,0,100>, cudaFuncAttributeMaxDynamicSharedMemorySize, SMB);
    cudaFuncSetAttribute(tgemm<64,64,1,100>, cudaFuncAttributeMaxDynamicSharedMemorySize, SMB);

    // merged expansions (1 launch)
    expandALL<<<38912,256>>>(query, x, wq, wk, wv, wfc, wpr, Qg, Xg, Wqkv, Wfcg, Wpg);

    // QKV Gauss: grid (8,32,9); z = inp*3 + prod; z>=3 uses Xg. kC=48, cps=16.
    tgemm<16,16,0,3><<<dim3(8,32,9),256,SMB>>>(mkgp(Qg, Xg, 6144, Wqkv, 6144, 48,
        (float2*)Pq, 512, nullptr, 1.f,
        3, 0, 2048, 1024L*6144, 2048, 3L*MR*512, (long)MR*512));

    // merged combine (1 launch): [0,8192) Q/K quad, [8192,12288) V transpose
    cqkvall<<<12288,256>>>(Pq, bq, bk, bv, Qa, Kb, Vb);

    // scores: per z=(b,h); kC=6, cps=2.
    tgemm<2,2,0,100><<<dim3(8,4,128),256,SMB>>>(mkgp(Qa, Qa, 256, Kb, 256, 6,
        Sc, 512, nullptr, 0.125f,
        1, 512L*256, 0, 1024L*256, 0, 512L*512, 0));
    softmax_kernel<<<128*512/8,256>>>(Sc, Pa);

    // AV: per z; kC=48, cps=16.
    tgemm<16,16,0,100><<<dim3(1,4,128),256,SMB>>>(mkgp(Pa, Pa, 2048, Vb, 2048, 48,
        O, 1024, nullptr, 1.f,
        16, 16L*512*2048, 512L*2048, 16L*128*2048, 128L*2048, 512L*1024, 64));

    ln_attn_kernel<<<MR,256>>>(O, query, x, lng, lnb, X2, X2g);

    // fc Gauss: grid (32,32,3); z = product. kC=48, cps=16.
    tgemm<16,16,0,100><<<dim3(32,32,3),256,SMB>>>(mkgp(X2g, X2g, 6144, Wfcg, 6144, 48,
        (float2*)Pfc, 2048, nullptr, 1.f,
        3, 0, 2048, 0, 2048, 0, (long)MR*2048));
    cfc4<<<16384,256>>>(Pfc, bfc, Hmg);

    // proj Gauss + split-K x3: grid (8,32,9); kC=64, cps=64, cbase=(z%3)*64.
    tgemm<64,64,1,100><<<dim3(8,32,9),256,SMB>>>(mkgp(Hmg, Hmg, 24576, Wpg, 24576, 64,
        (float2*)Pp, 512, nullptr, 1.f,
        3, 8192, 0, 8192, 0, 3L*MR*512, (long)MR*512));

    ln_final_kernel<<<MR,256>>>(X2, Pp, bpr, lng, lnb, (float2*)d_out);
}

// round 17
// speedup vs baseline: 3.8068x; 1.0003x over previous
#include <cuda_runtime.h>
#include <cuda_bf16.h>
#include <cstdint>
#include <math.h>

typedef __nv_bfloat16 bf16;
typedef __nv_bfloat162 bf162;

#define DD 1024
#define MR 4096
#define LN_EPS 1e-5f

// ---------------- pooled scratch (deduped layouts: A=[h|l], B=[h|l]) ----------------
constexpr size_t O_QG   = 0;
constexpr size_t O_XG   = O_QG   + (size_t)MR*6144*2;
constexpr size_t O_X2G  = O_XG   + (size_t)MR*6144*2;
constexpr size_t O_WQKV = O_X2G  + (size_t)MR*6144*2;
constexpr size_t O_WFCG = O_WQKV + (size_t)3*1024*6144*2;
constexpr size_t O_WPG  = O_WFCG + (size_t)4096*6144*2;
constexpr size_t O_QA   = O_WPG  + (size_t)1024*24576*2;
constexpr size_t O_KB   = O_QA   + (size_t)128*512*256*2;
constexpr size_t O_VB   = O_KB   + (size_t)128*1024*256*2;
constexpr size_t O_PA   = O_VB   + (size_t)128*128*2048*2;
constexpr size_t O_OO   = O_PA   + (size_t)128*512*2048*2;
constexpr size_t O_X2   = O_OO   + (size_t)MR*DD*8;
constexpr size_t O_HMG  = O_X2   + (size_t)MR*DD*8;
constexpr size_t O_SC   = O_HMG  + (size_t)MR*24576*2;
constexpr size_t POOLSZ = O_SC   + (size_t)128*512*512*8;
// aliases (disjoint lifetimes in launch order):
constexpr size_t O_PQ  = O_HMG;  // Pq dead after cqkvall; Hmg written at cfc
constexpr size_t O_PFC = O_SC;   // Pfc written at fc; Sc/Op dead by then
constexpr size_t O_OP  = O_SC;   // Op (4x33.5MB) written at AV; Sc dead after softmax; dead after ln_attn
constexpr size_t O_PP  = O_PA;   // Pp written at proj; Pa dead after AV

__device__ __align__(256) char g_pool[POOLSZ];

// ---------------- helpers ----------------
__device__ __forceinline__ uint32_t s2u(const void* p){
    uint32_t a;
    asm("{ .reg .u64 t; cvta.to.shared.u64 t, %1; cvt.u32.u64 %0, t; }":"=r"(a):"l"(p));
    return a;
}
__device__ __forceinline__ void cpa16(uint32_t d, const void* g){
    asm volatile("cp.async.cg.shared.global [%0], [%1], 16;"::"r"(d),"l"(g));
}
__device__ __forceinline__ void split2(float vr, float vi, bf162& h, bf162& l){
    h.x=__float2bfloat16_rn(vr); h.y=__float2bfloat16_rn(vi);
    l.x=__float2bfloat16_rn(vr-__bfloat162float(h.x));
    l.y=__float2bfloat16_rn(vi-__bfloat162float(h.y));
}
__device__ __forceinline__ float flo(float v){
    return v - __bfloat162float(__float2bfloat16_rn(v));
}
__device__ __forceinline__ uint32_t pk2(float a, float b){
    bf162 t; t.x=__float2bfloat16_rn(a); t.y=__float2bfloat16_rn(b);
    return *(uint32_t*)&t;
}
__device__ __forceinline__ void ldm4(uint32_t* r, uint32_t a){
    asm volatile("ldmatrix.sync.aligned.m8n8.x4.shared.b16 {%0,%1,%2,%3}, [%4];"
        :"=r"(r[0]),"=r"(r[1]),"=r"(r[2]),"=r"(r[3]):"r"(a));
}
__device__ __forceinline__ void mma16816(float* d, const uint32_t* a, uint32_t b0, uint32_t b1){
    asm volatile("mma.sync.aligned.m16n8k16.row.col.f32.bf16.bf16.f32 "
        "{%0,%1,%2,%3}, {%4,%5,%6,%7}, {%8,%9}, {%0,%1,%2,%3};"
        :"+f"(d[0]),"+f"(d[1]),"+f"(d[2]),"+f"(d[3])
        :"r"(a[0]),"r"(a[1]),"r"(a[2]),"r"(a[3]),"r"(b0),"r"(b1));
}

// ---------------- GEMM via mma.sync, section-remapped operands ----------------
// CBZ: 0=no chunk bias; 1=cbase=(z%zdiv)*kC; 2=cbase=(z/zdiv)*kC (split-K outer in z).
struct GP {
    const bf16 *A, *A2, *B;
    long lda, ldb;
    long sA1, sA2, sB1, sB2;
    float2* C; long ldc, sC1, sC2;
    const float2* bias;
    int zdiv, kC;
    float scale;
};
#define ROWB 144
#define ASZ  (128*ROWB)
#define STB  (2*ASZ)
#define SMB  (3*STB)

template<int CPSA, int CPSB, int CBZ, int A2Z>
__global__ __launch_bounds__(256,2) void tgemm(GP p)
{
    extern __shared__ __align__(256) char sm[];
    uint32_t TILE = s2u(sm);
    const int tid = threadIdx.x, lane = tid & 31, wid = tid >> 5;
    const int warpM = wid & 3, warpN = wid >> 2;

    const int z = blockIdx.z;
    const bf16* Ap = (z >= A2Z) ? p.A2 : p.A;
    const long offA = (z/p.zdiv)*p.sA1 + (z%p.zdiv)*p.sA2;
    const long offB = (z/p.zdiv)*p.sB1 + (z%p.zdiv)*p.sB2;
    const bf16* Ag = Ap + offA + (long)blockIdx.y*128*p.lda;
    const bf16* Bg = p.B + offB + (long)blockIdx.x*128*p.ldb;
    const int cbase = (CBZ==1) ? (z % p.zdiv) * p.kC : ((CBZ==2) ? (z / p.zdiv) * p.kC : 0);

    auto loadStage = [&](int c){
        uint32_t st = TILE + (c%3)*STB;
        int ct = c + cbase;
        int sa = ct / CPSA, sb = ct / CPSB;
        long kofA = ((sa==1) ? (long)CPSA*64 : 0L) + (long)(ct % CPSA)*64;
        long kofB = ((sb==2) ? (long)CPSB*64 : 0L) + (long)(ct % CPSB)*64;
        #pragma unroll
        for (int i=0;i<4;i++){
            int idx = tid + i*256; int r = idx>>3, cc = idx&7;
            cpa16(st + r*ROWB + cc*16, Ag + (long)r*p.lda + kofA + cc*8);
        }
        #pragma unroll
        for (int i=0;i<4;i++){
            int idx = tid + i*256; int r = idx>>3, cc = idx&7;
            cpa16(st + ASZ + r*ROWB + cc*16, Bg + (long)r*p.ldb + kofB + cc*8);
        }
        asm volatile("cp.async.commit_group;":::"memory");
    };

    float acc[2][8][4];
    #pragma unroll
    for (int mf=0;mf<2;mf++)
        #pragma unroll
        for (int nf=0;nf<8;nf++)
            #pragma unroll
            for (int t=0;t<4;t++) acc[mf][nf][t] = 0.f;

    loadStage(0);
    if (p.kC > 1) loadStage(1);

    const uint32_t aRel = (uint32_t)((warpM*32 + (lane&15))*ROWB + (lane>>4)*16);
    const uint32_t bRel = (uint32_t)(ASZ + (warpN*64 + (lane&7))*ROWB + ((lane>>3)&3)*16);

    for (int c = 0; c < p.kC; c++) {
        if (c+1 < p.kC) asm volatile("cp.async.wait_group 1;":::"memory");
        else            asm volatile("cp.async.wait_group 0;":::"memory");
        __syncthreads();
        if (c+2 < p.kC) loadStage(c+2);

        uint32_t st = TILE + (c%3)*STB;
        uint32_t aB = st + aRel, bB = st + bRel;
        #pragma unroll
        for (int kh=0; kh<2; kh++){
            uint32_t bfr[8][4];
            #pragma unroll
            for (int nf=0; nf<8; nf++) ldm4(bfr[nf], bB + nf*(8*ROWB) + kh*64);
            #pragma unroll
            for (int s=0; s<2; s++){
                int ks = kh*2 + s;
                uint32_t af[2][4];
                #pragma unroll
                for (int mf=0; mf<2; mf++) ldm4(af[mf], aB + mf*(16*ROWB) + ks*32);
                #pragma unroll
                for (int mf=0; mf<2; mf++)
                    #pragma unroll
                    for (int nf=0; nf<8; nf++)
                        mma16816(acc[mf][nf], af[mf], bfr[nf][s*2], bfr[nf][s*2+1]);
            }
        }
    }

    const long coff = (z/p.zdiv)*p.sC1 + (z%p.zdiv)*p.sC2;
    const int ncBase = blockIdx.x*64 + warpN*32 + (lane&3);
    #pragma unroll
    for (int mf=0; mf<2; mf++){
        long r0 = (long)blockIdx.y*128 + warpM*32 + mf*16 + (lane>>2);
        #pragma unroll
        for (int nf=0; nf<8; nf++){
            int nc = ncBase + nf*4;
            float2 bb = p.bias ? p.bias[nc] : make_float2(0.f,0.f);
            #pragma unroll
            for (int h2=0; h2<2; h2++){
                long m = r0 + h2*8;
                float cr = acc[mf][nf][2*h2]   * p.scale + bb.x;
                float ci = acc[mf][nf][2*h2+1] * p.scale + bb.y;
                p.C[coff + m*p.ldc + nc] = make_float2(cr, ci);
            }
        }
    }
}

// ---------------- merged expansions ----------------
__global__ __launch_bounds__(256) void expandALL(
    const float2* __restrict__ q, const float2* __restrict__ x,
    const float2* __restrict__ wq, const float2* __restrict__ wk, const float2* __restrict__ wv,
    const float2* __restrict__ wfc, const float2* __restrict__ wpr,
    bf16* __restrict__ Qg, bf16* __restrict__ Xg,
    bf16* __restrict__ Wqkv, bf16* __restrict__ Wfcg, bf16* __restrict__ Wpg)
{
    long bid = blockIdx.x;
    if (bid < 16384) {
        const float2* src = q; bf16* dst = Qg;
        if (bid >= 8192) { bid -= 8192; src = x; dst = Xg; }
        long pidx = bid*256 + threadIdx.x;
        long m = pidx >> 9; int k = (int)(pidx & 511) * 2;
        float4 vv = *(const float4*)(src + m*1024 + k);
        float c0[3] = { vv.x, vv.y, vv.x + vv.y };
        float c1[3] = { vv.z, vv.w, vv.z + vv.w };
        bf16* base = dst + m*6144 + k;
        #pragma unroll
        for (int c=0;c<3;c++){
            bf16* b = base + c*2048;
            *(uint32_t*)(b)        = pk2(c0[c], c1[c]);
            *(uint32_t*)(b + 1024) = pk2(flo(c0[c]), flo(c1[c]));
        }
        return;
    }
    bid -= 16384;
    const float2* W; bf16* out; int K; long rstride;
    if      (bid < 2048)  { W=wq;  out=Wqkv;                    K=1024; rstride=6144; }
    else if (bid < 4096)  { W=wk;  out=Wqkv+(size_t)1024*6144;  K=1024; rstride=6144; bid-=2048; }
    else if (bid < 6144)  { W=wv;  out=Wqkv+(size_t)2048*6144;  K=1024; rstride=6144; bid-=4096; }
    else if (bid < 14336) { W=wfc; out=Wfcg;                    K=1024; rstride=6144; bid-=6144; }
    else                  { W=wpr; out=Wpg;                     K=4096; rstride=24576; bid-=14336; }
    long pidx = bid*256 + threadIdx.x;
    int Kp = K >> 1;
    long n = pidx / Kp; int k = (int)(pidx % Kp) * 2;
    float4 ww = *(const float4*)(W + n*K + k);
    float c0[3] = { ww.x, ww.y, ww.x + ww.y };
    float c1[3] = { ww.z, ww.w, ww.z + ww.w };
    bf16* base = out + n*rstride + k;
    #pragma unroll
    for (int c=0;c<3;c++){
        bf16* b = base + (long)c*2*K;
        *(uint32_t*)(b)     = pk2(c0[c], c1[c]);
        *(uint32_t*)(b + K) = pk2(flo(c0[c]), flo(c1[c]));
    }
}

// ---------------- merged QKV combine ----------------
__global__ __launch_bounds__(256) void cqkvall(const float* __restrict__ Pq,
                                               const float2* __restrict__ bq,
                                               const float2* __restrict__ bk,
                                               const float2* __restrict__ bv,
                                               bf16* __restrict__ Qa, bf16* __restrict__ Kb,
                                               bf16* __restrict__ Vb)
{
    __shared__ float syr[32][33], syi[32][33];
    long bid = blockIdx.x;
    const long MN = (long)MR*1024;
    if (bid < 8192) {
        int q3 = (int)(bid >> 12); bid &= 4095;
        long qidx = bid*256 + threadIdx.x;
        long m = qidx >> 8; int n = (int)(qidx & 255) * 4;
        const float* P = Pq + (long)q3*3*MN;
        long e = m*1024 + n;
        float4 p0 = *(const float4*)(P + e);
        float4 p1 = *(const float4*)(P + MN + e);
        float4 p2 = *(const float4*)(P + 2*MN + e);
        const float2* bi = (q3==0) ? bq : bk;
        float4 b01 = *(const float4*)(bi + n);
        float4 b23 = *(const float4*)(bi + n + 2);
        float yr[4], yi[4];
        yr[0]=p0.x-p1.x+b01.x; yi[0]=p2.x-p0.x-p1.x+b01.y;
        yr[1]=p0.y-p1.y+b01.z; yi[1]=p2.y-p0.y-p1.y+b01.w;
        yr[2]=p0.z-p1.z+b23.x; yi[2]=p2.z-p0.z-p1.z+b23.y;
        yr[3]=p0.w-p1.w+b23.z; yi[3]=p2.w-p0.w-p1.w+b23.w;

        int b=(int)(m>>9), s=(int)(m&511), hh=n>>6, d=n&63;
        long zz = b*16 + hh;
        if (q3 == 0) {
            uint4 H, L;
            H.x=pk2(yr[0],yi[0]); H.y=pk2(yr[1],yi[1]); H.z=pk2(yr[2],yi[2]); H.w=pk2(yr[3],yi[3]);
            L.x=pk2(flo(yr[0]),flo(yi[0])); L.y=pk2(flo(yr[1]),flo(yi[1]));
            L.z=pk2(flo(yr[2]),flo(yi[2])); L.w=pk2(flo(yr[3]),flo(yi[3]));
            bf16* base = Qa + (zz*512 + s)*256 + 2*d;
            *(uint4*)(base)       = H;
            *(uint4*)(base + 128) = L;
        } else {
            uint4 H0, L0, H1, L1;
            #pragma unroll
            for (int j=0;j<4;j++){
                ((uint32_t*)&H0)[j] = pk2(yr[j], -yi[j]);
                ((uint32_t*)&L0)[j] = pk2(flo(yr[j]), flo(-yi[j]));
                ((uint32_t*)&H1)[j] = pk2(yi[j], yr[j]);
                ((uint32_t*)&L1)[j] = pk2(flo(yi[j]), flo(yr[j]));
            }
            bf16* r0p = Kb + (zz*1024 + 2*s)*256 + 2*d;
            bf16* r1p = r0p + 256;
            *(uint4*)(r0p) = H0; *(uint4*)(r0p + 128) = L0;
            *(uint4*)(r1p) = H1; *(uint4*)(r1p + 128) = L1;
        }
        return;
    }
    long bid2 = bid - 8192;
    const int s0 = ((int)bid2 & 15) * 32;
    const int d0 = (((int)bid2 >> 4) & 1) * 32;
    const int zz = (int)(bid2 >> 5);
    const int b = zz >> 4, h = zz & 15;
    const float* P = Pq + 2L*3*MN;
    const int tl = threadIdx.x & 31, tw = threadIdx.x >> 5;

    #pragma unroll
    for (int r=0;r<4;r++){
        int sl = tw + 8*r;
        long e = ((long)(b*512 + s0 + sl))*1024 + h*64 + d0 + tl;
        float p0 = P[e], p1 = P[MN+e], p2 = P[2*MN+e];
        float2 bb = bv[h*64 + d0 + tl];
        syr[sl][tl] = p0 - p1 + bb.x;
        syi[sl][tl] = p2 - p0 - p1 + bb.y;
    }
    __syncthreads();

    #pragma unroll
    for (int r=0;r<4;r++){
        int dl = tw + 8*r;
        float yr = syr[tl][dl], yi = syi[tl][dl];
        bf16* r0p = Vb + ((long)zz*128 + 2*(d0+dl))*2048 + 2*(s0+tl);
        bf16* r1p = r0p + 2048;
        *(uint32_t*)(r0p)        = pk2(yr, -yi);
        *(uint32_t*)(r0p + 1024) = pk2(flo(yr), flo(-yi));
        *(uint32_t*)(r1p)        = pk2(yi, yr);
        *(uint32_t*)(r1p + 1024) = pk2(flo(yi), flo(yr));
    }
}

// ---------------- fc combine (quad) ----------------
__global__ __launch_bounds__(256) void cfc4(const float* __restrict__ Pfc,
                                            const float2* __restrict__ bfc,
                                            bf16* __restrict__ Hmg)
{
    long qidx = (long)blockIdx.x*256 + threadIdx.x;
    long m = qidx >> 10; int n = (int)(qidx & 1023) * 4;
    const long MN = (long)MR*4096;
    long e = m*4096 + n;
    float4 p0 = *(const float4*)(Pfc + e);
    float4 p1 = *(const float4*)(Pfc + MN + e);
    float4 p2 = *(const float4*)(Pfc + 2*MN + e);
    float4 b01 = *(const float4*)(bfc + n);
    float4 b23 = *(const float4*)(bfc + n + 2);
    float yr[4], yi[4];
    yr[0]=p0.x-p1.x+b01.x; yi[0]=p2.x-p0.x-p1.x+b01.y;
    yr[1]=p0.y-p1.y+b01.z; yi[1]=p2.y-p0.y-p1.y+b01.w;
    yr[2]=p0.z-p1.z+b23.x; yi[2]=p2.z-p0.z-p1.z+b23.y;
    yr[3]=p0.w-p1.w+b23.z; yi[3]=p2.w-p0.w-p1.w+b23.w;
    float cs[3][4];
    #pragma unroll
    for (int j=0;j<4;j++){
        float mg = sqrtf(yr[j]*yr[j] + yi[j]*yi[j]);
        float r = 0.5f*(yr[j] + mg), ii = 0.5f*yi[j];
        cs[0][j] = r; cs[1][j] = ii; cs[2][j] = r + ii;
    }
    bf16* base = Hmg + m*24576 + n;
    #pragma unroll
    for (int c=0;c<3;c++){
        uint2 H, L;
        H.x = pk2(cs[c][0], cs[c][1]); H.y = pk2(cs[c][2], cs[c][3]);
        L.x = pk2(flo(cs[c][0]), flo(cs[c][1])); L.y = pk2(flo(cs[c][2]), flo(cs[c][3]));
        bf16* b = base + c*8192;
        *(uint2*)(b)        = H;
        *(uint2*)(b + 4096) = L;
    }
}

// ---------------- softmax + probs ([h|l], width 2048) ----------------
__global__ __launch_bounds__(256) void softmax_kernel(const float2* __restrict__ Sc, bf16* __restrict__ Pa)
{
    long rid = (long)blockIdx.x*8 + (threadIdx.x>>5);
    int lane = threadIdx.x & 31;
    const float2* r = Sc + rid*512;
    float2 v[16]; float mx=-1e30f, my=-1e30f;
    #pragma unroll
    for (int i=0;i<16;i++){ v[i]=r[lane+32*i]; mx=fmaxf(mx,v[i].x); my=fmaxf(my,v[i].y); }
    #pragma unroll
    for (int o=16;o>0;o>>=1){ mx=fmaxf(mx,__shfl_xor_sync(~0u,mx,o)); my=fmaxf(my,__shfl_xor_sync(~0u,my,o)); }
    float sx=0.f, sy=0.f;
    #pragma unroll
    for (int i=0;i<16;i++){ v[i].x=__expf(v[i].x-mx); v[i].y=__expf(v[i].y-my); sx+=v[i].x; sy+=v[i].y; }
    #pragma unroll
    for (int o=16;o>0;o>>=1){ sx+=__shfl_xor_sync(~0u,sx,o); sy+=__shfl_xor_sync(~0u,sy,o); }
    float ix=1.f/sx, iy=1.f/sy;
    bf16* base = Pa + rid*2048;
    #pragma unroll
    for (int i=0;i<16;i++){
        int k = lane + 32*i;
        bf162 h,l; split2(v[i].x*ix, v[i].y*iy, h, l);
        *(bf162*)(base+2*k)=h; *(bf162*)(base+1024+2*k)=l;
    }
}

// ---------------- layernorms ----------------
__device__ __forceinline__ void reduce4(float& a, float& b, float& c, float& d, float* sh)
{
    #pragma unroll
    for (int o=16;o>0;o>>=1){
        a+=__shfl_xor_sync(~0u,a,o); b+=__shfl_xor_sync(~0u,b,o);
        c+=__shfl_xor_sync(~0u,c,o); d+=__shfl_xor_sync(~0u,d,o);
    }
    int w = threadIdx.x>>5;
    __syncthreads();
    if ((threadIdx.x&31)==0){ sh[w]=a; sh[8+w]=b; sh[16+w]=c; sh[24+w]=d; }
    __syncthreads();
    float ra=0,rb=0,rc=0,rd=0;
    #pragma unroll
    for (int i=0;i<8;i++){ ra+=sh[i]; rb+=sh[8+i]; rc+=sh[16+i]; rd+=sh[24+i]; }
    a=ra; b=rb; c=rc; d=rd;
}

// Op: 4 split-K partials, layout [ks][zz][512][64] complex (per-head contiguous)
__global__ __launch_bounds__(256)
void ln_attn_kernel(const float2* __restrict__ Op, const float2* __restrict__ query,
                    const float2* __restrict__ x,
                    const float* __restrict__ g, const float* __restrict__ bta,
                    float2* __restrict__ X2, bf16* __restrict__ X2g)
{
    __shared__ float sh[32];
    const long base = (long)blockIdx.x*DD;
    const long PS = 128L*512*64;            // plane stride in float2
    const int bidx = (int)(blockIdx.x >> 9), sidx = (int)(blockIdx.x & 511);
    const float inv = 1.f/DD;
    float2 v[4]; float sr=0,sq=0,si=0,qi=0;
    #pragma unroll
    for (int i=0;i<2;i++){
        int d = 2*(threadIdx.x + i*256);
        int hh = d >> 6, dd = d & 63;
        long oi = (((long)(bidx*16 + hh)*512 + sidx)*64 + dd);
        float4 o0 = *(const float4*)(Op + oi);
        float4 o1 = *(const float4*)(Op + PS + oi);
        float4 o2 = *(const float4*)(Op + 2*PS + oi);
        float4 o3 = *(const float4*)(Op + 3*PS + oi);
        float4 o; o.x=o0.x+o1.x+o2.x+o3.x; o.y=o0.y+o1.y+o2.y+o3.y;
        o.z=o0.z+o1.z+o2.z+o3.z; o.w=o0.w+o1.w+o2.w+o3.w;
        float4 q = *(const float4*)(query + base + d);
        v[2*i]   = make_float2(o.x+q.x, o.y+q.y);
        v[2*i+1] = make_float2(o.z+q.z, o.w+q.w);
        sr+=v[2*i].x+v[2*i+1].x; sq+=v[2*i].x*v[2*i].x+v[2*i+1].x*v[2*i+1].x;
        si+=v[2*i].y+v[2*i+1].y; qi+=v[2*i].y*v[2*i].y+v[2*i+1].y*v[2*i+1].y;
    }
    reduce4(sr,sq,si,qi,sh);
    float mr=sr*inv, mi=si*inv;
    float rr=rsqrtf(sq*inv-mr*mr+LN_EPS), ri=rsqrtf(qi*inv-mi*mi+LN_EPS);
    float2 u[4]; float s2=0,q2=0,s3=0,q3=0;
    #pragma unroll
    for (int i=0;i<2;i++){
        int d = 2*(threadIdx.x + i*256);
        float2 gr = *(const float2*)(g + d);
        float2 gi2 = *(const float2*)(g + DD + d);
        float2 br = *(const float2*)(bta + d);
        float2 bi2 = *(const float2*)(bta + DD + d);
        float4 xx = *(const float4*)(x + base + d);
        float tr0=(v[2*i].x-mr)*rr*gr.x+br.x,   ti0=(v[2*i].y-mi)*ri*gi2.x+bi2.x;
        float tr1=(v[2*i+1].x-mr)*rr*gr.y+br.y, ti1=(v[2*i+1].y-mi)*ri*gi2.y+bi2.y;
        u[2*i]   = make_float2(xx.x+tr0, xx.y+ti0);
        u[2*i+1] = make_float2(xx.z+tr1, xx.w+ti1);
        s2+=u[2*i].x+u[2*i+1].x; q2+=u[2*i].x*u[2*i].x+u[2*i+1].x*u[2*i+1].x;
        s3+=u[2*i].y+u[2*i+1].y; q3+=u[2*i].y*u[2*i].y+u[2*i+1].y*u[2*i+1].y;
    }
    reduce4(s2,q2,s3,q3,sh);
    float m2=s2*inv, m3=s3*inv;
    float r2=rsqrtf(q2*inv-m2*m2+LN_EPS), r3=rsqrtf(q3*inv-m3*m3+LN_EPS);
    const float *g1=g+2*DD, *b1=bta+2*DD;
    #pragma unroll
    for (int i=0;i<2;i++){
        int d = 2*(threadIdx.x + i*256);
        float2 gr = *(const float2*)(g1 + d);
        float2 gi2 = *(const float2*)(g1 + DD + d);
        float2 br = *(const float2*)(b1 + d);
        float2 bi2 = *(const float2*)(b1 + DD + d);
        float y0r=(u[2*i].x-m2)*r2*gr.x+br.x,   y0i=(u[2*i].y-m3)*r3*gi2.x+bi2.x;
        float y1r=(u[2*i+1].x-m2)*r2*gr.y+br.y, y1i=(u[2*i+1].y-m3)*r3*gi2.y+bi2.y;
        float4 o4; o4.x=y0r; o4.y=y0i; o4.z=y1r; o4.w=y1i;
        *(float4*)(X2 + base + d) = o4;
        float c0[3] = { y0r, y0i, y0r + y0i };
        float c1[3] = { y1r, y1i, y1r + y1i };
        bf16* eb = X2g + (long)blockIdx.x*6144 + d;
        #pragma unroll
        for (int c=0;c<3;c++){
            bf16* b = eb + c*2048;
            *(uint32_t*)(b)        = pk2(c0[c], c1[c]);
            *(uint32_t*)(b + 1024) = pk2(flo(c0[c]), flo(c1[c]));
        }
    }
}

__global__ __launch_bounds__(256)
void ln_final_kernel(const float2* __restrict__ X2, const float* __restrict__ Pp,
                     const float2* __restrict__ bpr,
                     const float* __restrict__ g, const float* __restrict__ bta,
                     float2* __restrict__ out)
{
    __shared__ float sh[32];
    const long base = (long)blockIdx.x*DD;
    const long S = (long)MR*1024;
    const float inv = 1.f/DD;
    float2 v[4]; float sr=0,sq=0,si=0,qi=0;
    #pragma unroll
    for (int i=0;i<4;i++){
        int d = threadIdx.x + i*256;
        long fi = base + d;
        float P1 = Pp[fi]     + Pp[S+fi]   + Pp[2*S+fi];
        float P2 = Pp[3*S+fi] + Pp[4*S+fi] + Pp[5*S+fi];
        float P3 = Pp[6*S+fi] + Pp[7*S+fi] + Pp[8*S+fi];
        float2 a = X2[fi]; float2 bb = bpr[d];
        v[i] = make_float2(a.x + (P1 - P2) + bb.x,
                           a.y + (P3 - P1 - P2) + bb.y);
        sr+=v[i].x; sq+=v[i].x*v[i].x; si+=v[i].y; qi+=v[i].y*v[i].y;
    }
    reduce4(sr,sq,si,qi,sh);
    float mr=sr*inv, mi=si*inv;
    float rr=rsqrtf(sq*inv-mr*mr+LN_EPS), ri=rsqrtf(qi*inv-mi*mi+LN_EPS);
    const float *g2=g+4*DD, *b2=bta+4*DD;
    #pragma unroll
    for (int i=0;i<4;i++){
        int d = threadIdx.x + i*256;
        out[base+d]=make_float2((v[i].x-mr)*rr*g2[d]+b2[d], (v[i].y-mi)*ri*g2[DD+d]+b2[DD+d]);
    }
}

// ---------------- host ----------------
static GP mkgp(const bf16* A, const bf16* A2, long lda, const bf16* B, long ldb, int kC,
               float2* C, long ldc, const float2* bias, float scale,
               int zdiv, long sA1, long sA2, long sB1, long sB2, long sC1, long sC2)
{
    GP p = {};
    p.A=A; p.A2=A2; p.B=B; p.lda=lda; p.ldb=ldb; p.kC=kC;
    p.C=C; p.ldc=ldc; p.bias=bias; p.scale=scale; p.zdiv=zdiv;
    p.sA1=sA1; p.sA2=sA2; p.sB1=sB1; p.sB2=sB2; p.sC1=sC1; p.sC2=sC2;
    return p;
}

extern "C" void kernel_launch(void* const* d_in, const int* in_sizes, int n_in,
                              void* d_out, int out_size)
{
    const float2* x     = (const float2*)d_in[0];
    const float2* query = (const float2*)d_in[1];
    const float2* wq    = (const float2*)d_in[2];
    const float2* bq    = (const float2*)d_in[3];
    const float2* wk    = (const float2*)d_in[4];
    const float2* bk    = (const float2*)d_in[5];
    const float2* wv    = (const float2*)d_in[6];
    const float2* bv    = (const float2*)d_in[7];
    const float2* wfc   = (const float2*)d_in[8];
    const float2* bfc   = (const float2*)d_in[9];
    const float2* wpr   = (const float2*)d_in[10];
    const float2* bpr   = (const float2*)d_in[11];
    const float*  lng   = (const float*)d_in[12];
    const float*  lnb   = (const float*)d_in[13];

    char* pool;
    cudaGetSymbolAddress((void**)&pool, g_pool);
    bf16 *Qg   = (bf16*)(pool + O_QG),   *Xg   = (bf16*)(pool + O_XG);
    bf16 *X2g  = (bf16*)(pool + O_X2G),  *Hmg  = (bf16*)(pool + O_HMG);
    bf16 *Wqkv = (bf16*)(pool + O_WQKV), *Wfcg = (bf16*)(pool + O_WFCG);
    bf16 *Wpg  = (bf16*)(pool + O_WPG);
    bf16 *Qa   = (bf16*)(pool + O_QA),   *Kb   = (bf16*)(pool + O_KB);
    bf16 *Vb   = (bf16*)(pool + O_VB),   *Pa   = (bf16*)(pool + O_PA);
    float *Pq  = (float*)(pool + O_PQ),  *Pfc  = (float*)(pool + O_PFC);
    float *Pp  = (float*)(pool + O_PP);
    float2 *Op = (float2*)(pool + O_OP), *X2   = (float2*)(pool + O_X2);
    float2 *Sc = (float2*)(pool + O_SC);

    cudaFuncSetAttribute(tgemm<16,16,0,3>,   cudaFuncAttributeMaxDynamicSharedMemorySize, SMB);
    cudaFuncSetAttribute(tgemm<2,2,0,100>,   cudaFuncAttributeMaxDynamicSharedMemorySize, SMB);
    cudaFuncSetAttribute(tgemm<16,16,2,1000>, cudaFuncAttributeMaxDynamicSharedMemorySize, SMB);
    cudaFuncSetAttribute(tgemm<16,16,0,100>, cudaFuncAttributeMaxDynamicSharedMemorySize, SMB);
    cudaFuncSetAttribute(tgemm<64,64,1,100>, cudaFuncAttributeMaxDynamicSharedMemorySize, SMB);

    // merged expansions (1 launch)
    expandALL<<<38912,256>>>(query, x, wq, wk, wv, wfc, wpr, Qg, Xg, Wqkv, Wfcg, Wpg);

    // QKV Gauss: grid (8,32,9); z = inp*3 + prod; z>=3 uses Xg. kC=48, cps=16.
    tgemm<16,16,0,3><<<dim3(8,32,9),256,SMB>>>(mkgp(Qg, Xg, 6144, Wqkv, 6144, 48,
        (float2*)Pq, 512, nullptr, 1.f,
        3, 0, 2048, 1024L*6144, 2048, 3L*MR*512, (long)MR*512));

    // merged combine (1 launch)
    cqkvall<<<12288,256>>>(Pq, bq, bk, bv, Qa, Kb, Vb);

    // scores: per z=(b,h); kC=6, cps=2.
    tgemm<2,2,0,100><<<dim3(8,4,128),256,SMB>>>(mkgp(Qa, Qa, 256, Kb, 256, 6,
        Sc, 512, nullptr, 0.125f,
        1, 512L*256, 0, 1024L*256, 0, 512L*512, 0));
    softmax_kernel<<<128*512/8,256>>>(Sc, Pa);

    // AV split-K x4: z = ks*128 + zz; zdiv=128: z/128=ks (CBZ=2 chunk base), z%128=zz.
    // Op layout [ks][zz][512][64] complex.
    tgemm<16,16,2,1000><<<dim3(1,4,512),256,SMB>>>(mkgp(Pa, Pa, 2048, Vb, 2048, 12,
        Op, 64, nullptr, 1.f,
        128, 0, 512L*2048, 0, 128L*2048, 128L*512*64, 512L*64));

    ln_attn_kernel<<<MR,256>>>(Op, query, x, lng, lnb, X2, X2g);

    // fc Gauss: grid (32,32,3); z = product. kC=48, cps=16.
    tgemm<16,16,0,100><<<dim3(32,32,3),256,SMB>>>(mkgp(X2g, X2g, 6144, Wfcg, 6144, 48,
        (float2*)Pfc, 2048, nullptr, 1.f,
        3, 0, 2048, 0, 2048, 0, (long)MR*2048));
    cfc4<<<16384,256>>>(Pfc, bfc, Hmg);

    // proj Gauss + split-K x3: grid (8,32,9); kC=64, cps=64, cbase=(z%3)*64.
    tgemm<64,64,1,100><<<dim3(8,32,9),256,SMB>>>(mkgp(Hmg, Hmg, 24576, Wpg, 24576, 64,
        (float2*)Pp, 512, nullptr, 1.f,
        3, 8192, 0, 8192, 0, 3L*MR*512, (long)MR*512));

    ln_final_kernel<<<MR,256>>>(X2, Pp, bpr, lng, lnb, (float2*)d_out);
}